// round 1
// baseline (speedup 1.0000x reference)
#include <cuda_runtime.h>
#include <math.h>

// ---------------- problem constants ----------------
#define BSZ    2
#define NN     8192
#define DIM    256
#define HEADS  8
#define DH     64
#define INNER  512     // HEADS*DH
#define NBF    256     // num random features
#define FFD    1024
#define EEDG   131072
#define ROWS   (BSZ*NN)     // 16384
#define BH     (BSZ*HEADS)  // 16
#define KEPS   1e-4f
#define LNEPS  1e-5f
#define DN     0.3535533905932738f   /* 64^-0.25 */
#define RATIO  0.0625f               /* 256^-0.5 */

// ---------------- scratch (device globals; no allocation allowed) -------
__device__ float g_z[ROWS*DIM];
__device__ float g_y[ROWS*DIM];
__device__ float g_q[ROWS*INNER];
__device__ float g_k[ROWS*INNER];
__device__ float g_v[ROWS*INNER];
__device__ float g_o[ROWS*INNER];
__device__ float g_ff[ROWS*FFD];
__device__ float g_qf[(size_t)BH*NN*NBF];
__device__ float g_kf[(size_t)BH*NN*NBF];
__device__ float g_agg[NN*DIM];
__device__ float g_go[NN*DIM];
__device__ float g_deg[NN];
__device__ float g_dinv[NN];
__device__ float g_rowmax[BH*NN];
__device__ float g_stab[BH];
__device__ float g_ksum[BH*NBF];
__device__ float g_ctx[BH*NBF*DH];

// ---------------- helpers ----------------
__device__ __forceinline__ float gelu_f(float v) {
    const float c = 0.7978845608028654f;
    float t = tanhf(c * (v + 0.044715f * v * v * v));
    return 0.5f * v * (1.0f + t);
}

// ---------------- generic tiled SGEMM ----------------
// C[M,N] = alpha * sum_k A[m*a_rs + k*a_cs] * B[k*b_ks + n*b_ns]  (+bias[n]) (+C if beta)
// epi: 0 none, 1 relu, 2 gelu.  nsplit>1 -> split-K atomicAdd (no bias/epi/beta).
__global__ void gemm_kernel(int M, int N, int K,
                            const float* __restrict__ A, int a_rs, int a_cs,
                            const float* __restrict__ B, int b_ks, int b_ns,
                            float* __restrict__ C, int ldc,
                            const float* __restrict__ bias,
                            float alpha, int beta, int epi, int nsplit)
{
    const int BK = 16;
    __shared__ float As[16][65];
    __shared__ float Bs[16][65];
    int tid = threadIdx.x;
    int tx = tid & 15;          // n-dir
    int ty = tid >> 4;          // m-dir
    int row0 = blockIdx.y * 64;
    int col0 = blockIdx.x * 64;
    int kchunk = (K + nsplit - 1) / nsplit;
    int kbeg = blockIdx.z * kchunk;
    int kend = kbeg + kchunk; if (kend > K) kend = K;

    float acc[4][4] = {};
    for (int kt = kbeg; kt < kend; kt += BK) {
        #pragma unroll
        for (int i = 0; i < 4; i++) {
            int idx = tid + i * 256;
            int m = idx & 63, kk = idx >> 6;
            int gm = row0 + m, gk = kt + kk;
            As[kk][m] = (gm < M && gk < kend)
                      ? A[(long)gm * a_rs + (long)gk * a_cs] : 0.0f;
        }
        #pragma unroll
        for (int i = 0; i < 4; i++) {
            int idx = tid + i * 256;
            int nn2 = idx & 63, kk = idx >> 6;
            int gn = col0 + nn2, gk = kt + kk;
            Bs[kk][nn2] = (gn < N && gk < kend)
                        ? B[(long)gk * b_ks + (long)gn * b_ns] : 0.0f;
        }
        __syncthreads();
        #pragma unroll
        for (int kk = 0; kk < BK; kk++) {
            float a[4], b[4];
            #pragma unroll
            for (int i = 0; i < 4; i++) a[i] = As[kk][ty * 4 + i];
            #pragma unroll
            for (int j = 0; j < 4; j++) b[j] = Bs[kk][tx * 4 + j];
            #pragma unroll
            for (int i = 0; i < 4; i++)
                #pragma unroll
                for (int j = 0; j < 4; j++)
                    acc[i][j] += a[i] * b[j];
        }
        __syncthreads();
    }
    #pragma unroll
    for (int i = 0; i < 4; i++) {
        int gm = row0 + ty * 4 + i;
        if (gm >= M) continue;
        #pragma unroll
        for (int j = 0; j < 4; j++) {
            int gn = col0 + tx * 4 + j;
            if (gn >= N) continue;
            float v = alpha * acc[i][j];
            if (nsplit > 1) {
                atomicAdd(&C[(long)gm * ldc + gn], v);
            } else {
                if (bias) v += bias[gn];
                if (epi == 1) v = fmaxf(v, 0.0f);
                else if (epi == 2) v = gelu_f(v);
                if (beta) v += C[(long)gm * ldc + gn];
                C[(long)gm * ldc + gn] = v;
            }
        }
    }
}

// ---------------- small kernels ----------------
__global__ void zero_kernel(float* p, long n) {
    long i = (long)blockIdx.x * blockDim.x + threadIdx.x;
    long stride = (long)gridDim.x * blockDim.x;
    for (; i < n; i += stride) p[i] = 0.0f;
}

__global__ void embed_kernel(const float* __restrict__ x,
                             const float* __restrict__ w1,
                             const float* __restrict__ b1,
                             float* __restrict__ h)
{
    long i = blockIdx.x;
    int j = threadIdx.x;
    float v = x[i] * w1[j] + b1[j];
    h[i * DIM + j] = fmaxf(v, 0.0f);
}

__global__ void deg_kernel(const int* __restrict__ ei,
                           const float* __restrict__ ew,
                           float* __restrict__ deg)
{
    int e = blockIdx.x * blockDim.x + threadIdx.x;
    if (e < EEDG) atomicAdd(&deg[ei[EEDG + e]], ew[e]);
}

__global__ void dinv_kernel(const float* __restrict__ deg, float* __restrict__ dinv)
{
    int i = blockIdx.x * blockDim.x + threadIdx.x;
    if (i < NN) {
        float d = deg[i];
        dinv[i] = (d > 0.0f) ? rsqrtf(fmaxf(d, 1e-12f)) : 0.0f;
    }
}

__global__ void agg_kernel(const int* __restrict__ ei,
                           const float* __restrict__ ew,
                           const float* __restrict__ dinv,
                           const float* __restrict__ emb,
                           float* __restrict__ agg)
{
    int e = blockIdx.x;
    int j = threadIdx.x;
    int r = ei[e];
    int c = ei[EEDG + e];
    float w = dinv[r] * ew[e] * dinv[c];
    atomicAdd(&agg[(long)c * DIM + j], emb[(long)r * DIM + j] * w);
}

__global__ void zadd_kernel(float* __restrict__ z,
                            const float* __restrict__ pos,
                            const float* __restrict__ go)
{
    long i = blockIdx.x;
    int j = threadIdx.x;
    int n = (int)(i & (NN - 1));
    z[i * DIM + j] += pos[(long)n * DIM + j] + go[(long)n * DIM + j];
}

__global__ void ln_kernel(const float* __restrict__ x,
                          const float* __restrict__ g,
                          const float* __restrict__ b,
                          float* __restrict__ y)
{
    long row = blockIdx.x;
    int tid = threadIdx.x;
    __shared__ float red[256];
    float v = x[row * DIM + tid];
    red[tid] = v; __syncthreads();
    for (int s = 128; s > 0; s >>= 1) {
        if (tid < s) red[tid] += red[tid + s];
        __syncthreads();
    }
    float mean = red[0] * (1.0f / DIM);
    __syncthreads();
    float d = v - mean;
    red[tid] = d * d; __syncthreads();
    for (int s = 128; s > 0; s >>= 1) {
        if (tid < s) red[tid] += red[tid + s];
        __syncthreads();
    }
    float var = red[0] * (1.0f / DIM);
    y[row * DIM + tid] = d * rsqrtf(var + LNEPS) * g[tid] + b[tid];
}

// mode 0: Q (per-row stab), write out.
// mode 1: K pass1 (write rowmax per (b,h,n) only).
// mode 2: K pass2 (global stab per (b,h)), write out.
__global__ void favor_kernel(const float* __restrict__ qkv,
                             const float* __restrict__ proj,
                             float* __restrict__ out,
                             float* __restrict__ rowmax,
                             const float* __restrict__ stab_in,
                             int mode)
{
    int r = blockIdx.x;          // 0..BH*NN-1, layout [b][h][n]
    int n = r & (NN - 1);
    int h = (r >> 13) & (HEADS - 1);
    int b = r >> 16;
    const float* qrow = qkv + ((long)(b * NN + n)) * INNER + h * DH;
    __shared__ float qs[DH];
    __shared__ float red[256];
    int tid = threadIdx.x;
    if (tid < DH) qs[tid] = qrow[tid] * DN;
    __syncthreads();
    float dd = 0.0f;
    const float* pr = proj + (long)tid * DH;
    #pragma unroll 16
    for (int d = 0; d < DH; d++) dd += qs[d] * pr[d];
    red[tid] = dd; __syncthreads();
    for (int s = 128; s > 0; s >>= 1) {
        if (tid < s) red[tid] = fmaxf(red[tid], red[tid + s]);
        __syncthreads();
    }
    float rmax = red[0];
    if (mode == 1) {
        if (tid == 0) rowmax[r] = rmax;
        return;
    }
    __syncthreads();
    red[tid] = (tid < DH) ? qs[tid] * qs[tid] : 0.0f;
    __syncthreads();
    for (int s = 128; s > 0; s >>= 1) {
        if (tid < s) red[tid] += red[tid + s];
        __syncthreads();
    }
    float diag = 0.5f * red[0];
    float stab = (mode == 0) ? rmax : stab_in[(b << 3) | h];
    out[(long)r * NBF + tid] = RATIO * (expf(dd - diag - stab) + KEPS);
}

__global__ void stab_reduce_kernel(const float* __restrict__ rowmax,
                                   float* __restrict__ stab)
{
    int bh = blockIdx.x;
    int tid = threadIdx.x;
    __shared__ float red[256];
    float m = -INFINITY;
    for (int i = tid; i < NN; i += 256)
        m = fmaxf(m, rowmax[(long)bh * NN + i]);
    red[tid] = m; __syncthreads();
    for (int s = 128; s > 0; s >>= 1) {
        if (tid < s) red[tid] = fmaxf(red[tid], red[tid + s]);
        __syncthreads();
    }
    if (tid == 0) stab[bh] = red[0];
}

__global__ void ksum_kernel(const float* __restrict__ kf, float* __restrict__ ksum)
{
    int bh = blockIdx.x;
    int chunk = blockIdx.y;        // 32 chunks of 256 n each
    int m = threadIdx.x;
    const float* base = kf + (size_t)bh * NN * NBF;
    float s = 0.0f;
    int n0 = chunk * 256;
    for (int nn2 = n0; nn2 < n0 + 256; nn2++)
        s += base[(long)nn2 * NBF + m];
    atomicAdd(&ksum[bh * NBF + m], s);
}

__global__ void attn_out_kernel(const float* __restrict__ qf,
                                const float* __restrict__ ctx,
                                const float* __restrict__ ksum,
                                float* __restrict__ o)
{
    int r = blockIdx.x;
    int n = r & (NN - 1);
    int h = (r >> 13) & (HEADS - 1);
    int b = r >> 16;
    int bh = (b << 3) | h;
    __shared__ float qfs[NBF];
    __shared__ float red[64];
    int tid = threadIdx.x;   // 64
    const float* qrow = qf + (size_t)r * NBF;
    const float* ks = ksum + bh * NBF;
    float dpart = 0.0f;
    #pragma unroll
    for (int i = 0; i < 4; i++) {
        int m = tid * 4 + i;
        float v = qrow[m];
        qfs[m] = v;
        dpart += v * ks[m];
    }
    red[tid] = dpart; __syncthreads();
    for (int s = 32; s > 0; s >>= 1) {
        if (tid < s) red[tid] += red[tid + s];
        __syncthreads();
    }
    float denom = red[0];
    const float* cbase = ctx + (long)bh * NBF * DH + tid;
    float acc = 0.0f;
    #pragma unroll 8
    for (int m = 0; m < NBF; m++) acc += qfs[m] * cbase[(long)m * DH];
    o[((long)(b * NN + n)) * INNER + h * DH + tid] = acc / denom;
}

__global__ void head_kernel(const float* __restrict__ y,
                            const float* __restrict__ w,
                            const float* __restrict__ bb,
                            float* __restrict__ out)
{
    long row = blockIdx.x;
    int tid = threadIdx.x;
    __shared__ float red[256];
    red[tid] = y[row * DIM + tid] * w[tid];
    __syncthreads();
    for (int s = 128; s > 0; s >>= 1) {
        if (tid < s) red[tid] += red[tid + s];
        __syncthreads();
    }
    if (tid == 0) out[row] = red[0] + bb[0];
}

// ---------------- host side ----------------
static inline void gemm(int M, int N, int K,
                        const float* A, int a_rs, int a_cs,
                        const float* B, int b_ks, int b_ns,
                        float* C, int ldc, const float* bias,
                        float alpha, int beta, int epi, int nsplit)
{
    dim3 grid((N + 63) / 64, (M + 63) / 64, nsplit);
    gemm_kernel<<<grid, 256>>>(M, N, K, A, a_rs, a_cs, B, b_ks, b_ns,
                               C, ldc, bias, alpha, beta, epi, nsplit);
}

extern "C" void kernel_launch(void* const* d_in, const int* in_sizes, int n_in,
                              void* d_out, int out_size)
{
    const float* x        = (const float*)d_in[0];
    const float* mlp_w1   = (const float*)d_in[1];
    const float* mlp_b1   = (const float*)d_in[2];
    const float* mlp_w2   = (const float*)d_in[3];
    const float* mlp_b2   = (const float*)d_in[4];
    const float* pos      = (const float*)d_in[5];
    const float* gnn_emb  = (const float*)d_in[6];
    const float* gnn_w    = (const float*)d_in[7];
    const float* gnn_b    = (const float*)d_in[8];
    const float* ew       = (const float*)d_in[9];
    const float* proj     = (const float*)d_in[10];
    const float* ln1_g    = (const float*)d_in[11];
    const float* ln1_b    = (const float*)d_in[12];
    const float* wq       = (const float*)d_in[13];
    const float* wk       = (const float*)d_in[14];
    const float* wv       = (const float*)d_in[15];
    const float* wo       = (const float*)d_in[16];
    const float* bo       = (const float*)d_in[17];
    const float* ln2_g    = (const float*)d_in[18];
    const float* ln2_b    = (const float*)d_in[19];
    const float* ffw1     = (const float*)d_in[20];
    const float* ffb1     = (const float*)d_in[21];
    const float* ffw2     = (const float*)d_in[22];
    const float* ffb2     = (const float*)d_in[23];
    const float* normf_g  = (const float*)d_in[24];
    const float* normf_b  = (const float*)d_in[25];
    const float* out_w    = (const float*)d_in[26];
    const float* out_b    = (const float*)d_in[27];
    const int*   ei       = (const int*)d_in[28];
    float* out            = (float*)d_out;

    float *z, *y, *q, *k, *v, *o, *ff, *qf, *kf, *agg, *go, *deg, *dinv;
    float *rowmax, *stab, *ksum, *ctx;
    cudaGetSymbolAddress((void**)&z, g_z);
    cudaGetSymbolAddress((void**)&y, g_y);
    cudaGetSymbolAddress((void**)&q, g_q);
    cudaGetSymbolAddress((void**)&k, g_k);
    cudaGetSymbolAddress((void**)&v, g_v);
    cudaGetSymbolAddress((void**)&o, g_o);
    cudaGetSymbolAddress((void**)&ff, g_ff);
    cudaGetSymbolAddress((void**)&qf, g_qf);
    cudaGetSymbolAddress((void**)&kf, g_kf);
    cudaGetSymbolAddress((void**)&agg, g_agg);
    cudaGetSymbolAddress((void**)&go, g_go);
    cudaGetSymbolAddress((void**)&deg, g_deg);
    cudaGetSymbolAddress((void**)&dinv, g_dinv);
    cudaGetSymbolAddress((void**)&rowmax, g_rowmax);
    cudaGetSymbolAddress((void**)&stab, g_stab);
    cudaGetSymbolAddress((void**)&ksum, g_ksum);
    cudaGetSymbolAddress((void**)&ctx, g_ctx);

    // ---- embedding: h = relu(x*w1+b1); emb = h@w2 + b2 -> z ----
    embed_kernel<<<ROWS, DIM>>>(x, mlp_w1, mlp_b1, y);
    gemm(ROWS, DIM, DIM, y, DIM, 1, mlp_w2, DIM, 1, z, DIM, mlp_b2, 1.0f, 0, 0, 1);

    // ---- GNN ----
    zero_kernel<<<64, 256>>>(deg, NN);
    zero_kernel<<<1024, 256>>>(agg, (long)NN * DIM);
    deg_kernel<<<EEDG / 256, 256>>>(ei, ew, deg);
    dinv_kernel<<<NN / 256, 256>>>(deg, dinv);
    agg_kernel<<<EEDG, DIM>>>(ei, ew, dinv, gnn_emb, agg);
    gemm(NN, DIM, DIM, agg, DIM, 1, gnn_w, DIM, 1, go, DIM, gnn_b, 1.0f, 0, 0, 1);
    zadd_kernel<<<ROWS, DIM>>>(z, pos, go);

    // ---- transformer layers ----
    for (int l = 0; l < 2; l++) {
        const float* wq_l  = wq  + (long)l * DIM * INNER;
        const float* wk_l  = wk  + (long)l * DIM * INNER;
        const float* wv_l  = wv  + (long)l * DIM * INNER;
        const float* wo_l  = wo  + (long)l * INNER * DIM;
        const float* bo_l  = bo  + (long)l * DIM;
        const float* ffw1_l = ffw1 + (long)l * DIM * FFD;
        const float* ffb1_l = ffb1 + (long)l * FFD;
        const float* ffw2_l = ffw2 + (long)l * FFD * DIM;
        const float* ffb2_l = ffb2 + (long)l * DIM;

        ln_kernel<<<ROWS, DIM>>>(z, ln1_g + l * DIM, ln1_b + l * DIM, y);
        gemm(ROWS, INNER, DIM, y, DIM, 1, wq_l, INNER, 1, q, INNER, nullptr, 1.0f, 0, 0, 1);
        gemm(ROWS, INNER, DIM, y, DIM, 1, wk_l, INNER, 1, k, INNER, nullptr, 1.0f, 0, 0, 1);
        gemm(ROWS, INNER, DIM, y, DIM, 1, wv_l, INNER, 1, v, INNER, nullptr, 1.0f, 0, 0, 1);

        favor_kernel<<<BH * NN, 256>>>(q, proj, qf, nullptr, nullptr, 0);
        favor_kernel<<<BH * NN, 256>>>(k, proj, nullptr, rowmax, nullptr, 1);
        stab_reduce_kernel<<<BH, 256>>>(rowmax, stab);
        favor_kernel<<<BH * NN, 256>>>(k, proj, kf, nullptr, stab, 2);

        zero_kernel<<<16, 256>>>(ksum, BH * NBF);
        zero_kernel<<<256, 256>>>(ctx, (long)BH * NBF * DH);
        ksum_kernel<<<dim3(BH, 32), 256>>>(kf, ksum);
        // ctx[bh][m][d] = sum_n kf[bh][n][m] * v[b][n][h*64+d]
        for (int bh = 0; bh < BH; bh++) {
            int b = bh >> 3, h = bh & 7;
            gemm(NBF, DH, NN,
                 kf + (size_t)bh * NN * NBF, 1, NBF,
                 v + (long)b * NN * INNER + h * DH, INNER, 1,
                 ctx + (long)bh * NBF * DH, DH, nullptr, 1.0f, 0, 0, 32);
        }
        attn_out_kernel<<<BH * NN, 64>>>(qf, ctx, ksum, o);

        gemm(ROWS, DIM, INNER, o, INNER, 1, wo_l, DIM, 1, z, DIM, bo_l, 1.0f, 1, 0, 1);

        ln_kernel<<<ROWS, DIM>>>(z, ln2_g + l * DIM, ln2_b + l * DIM, y);
        gemm(ROWS, FFD, DIM, y, DIM, 1, ffw1_l, FFD, 1, ff, FFD, ffb1_l, 1.0f, 0, 2, 1);
        gemm(ROWS, DIM, FFD, ff, FFD, 1, ffw2_l, DIM, 1, z, DIM, ffb2_l, 1.0f, 1, 0, 1);
    }

    // ---- final LN + head ----
    ln_kernel<<<ROWS, DIM>>>(z, normf_g, normf_b, y);
    head_kernel<<<ROWS, DIM>>>(y, out_w, out_b, out);
}

// round 2
// speedup vs baseline: 10.9117x; 10.9117x over previous
#include <cuda_runtime.h>
#include <math.h>

// ---------------- problem constants ----------------
#define BSZ    2
#define NN     8192
#define DIM    256
#define HEADS  8
#define DH     64
#define INNER  512
#define NBF    256
#define FFD    1024
#define EEDG   131072
#define ROWS   (BSZ*NN)
#define BH     (BSZ*HEADS)
#define KEPS   1e-4f
#define LNEPS  1e-5f
#define DN     0.3535533905932738f   /* 64^-0.25 */
#define RATIO  0.0625f               /* 256^-0.5 */

// ---------------- scratch ----------------
__device__ float g_z[ROWS*DIM];
__device__ float g_y[ROWS*DIM];
__device__ float g_q[ROWS*INNER];
__device__ float g_k[ROWS*INNER];
__device__ float g_v[ROWS*INNER];
__device__ float g_o[ROWS*INNER];
__device__ float g_ff[(size_t)ROWS*FFD];
__device__ float g_qf[(size_t)BH*NN*NBF];
__device__ float g_kf[(size_t)BH*NN*NBF];
__device__ float g_agg[NN*DIM];
__device__ float g_go[NN*DIM];
__device__ float g_deg[NN];
__device__ float g_dinv[NN];
__device__ float g_rowmax[BH*NN];
__device__ float g_stab[BH];
__device__ float g_ksum[BH*NBF];
__device__ float g_ctx[BH*NBF*DH];
__device__ float g_denom[BH*NN];
__device__ float g_projT[DH*NBF];

__device__ __forceinline__ float gelu_f(float v) {
    const float c = 0.7978845608028654f;
    float t = tanhf(c * (v + 0.044715f * v * v * v));
    return 0.5f * v * (1.0f + t);
}

// =====================================================================
// Fast batched SGEMM: 128x128 tile, BK=8, 256 threads, 8x8 microtile.
// Requirements (guaranteed by call sites): M % 128 == 0, K/nsplit % 8 == 0,
// N % 4 == 0, all strides multiples of 4.
// Batch offsets: off = (batch>>3)*so + (batch&7)*si   (batch = blockIdx.z/nsplit)
// epi: 0 none, 1 relu, 2 gelu, 3 divide-by-denom[row].
// nsplit>1: atomicAdd into C (no bias/epi/beta).
// =====================================================================
__global__ __launch_bounds__(256, 2)
void sgemm_kernel(int M, int N, int K,
                  const float* __restrict__ A, int a_rs, int a_cs, long a_so, long a_si,
                  const float* __restrict__ B, int b_ks, int b_ns, long b_so, long b_si,
                  float* __restrict__ C, int c_rs, long c_so, long c_si,
                  const float* __restrict__ bias,
                  const float* __restrict__ denom, long d_so, long d_si,
                  float alpha, int beta, int epi, int nsplit)
{
    __shared__ float As[8][132];
    __shared__ float Bs[8][132];

    int zz = blockIdx.z;
    int batch = zz / nsplit;
    int split = zz - batch * nsplit;
    long aoff = (long)(batch >> 3) * a_so + (long)(batch & 7) * a_si;
    long boff = (long)(batch >> 3) * b_so + (long)(batch & 7) * b_si;
    long coff = (long)(batch >> 3) * c_so + (long)(batch & 7) * c_si;

    int row0 = blockIdx.y * 128;
    int col0 = blockIdx.x * 128;
    int kchunk = K / nsplit;
    int kbeg = split * kchunk;

    int tid = threadIdx.x;
    int tx = tid & 15, ty = tid >> 4;

    float acc[8][8];
    #pragma unroll
    for (int i = 0; i < 8; i++)
        #pragma unroll
        for (int j = 0; j < 8; j++) acc[i][j] = 0.0f;

    for (int kt = kbeg; kt < kbeg + kchunk; kt += 8) {
        // ---- load A tile (transposed into smem) ----
        if (a_cs == 1) {
            int m = tid >> 1;
            int kq = (tid & 1) * 4;
            float4 v = *(const float4*)(A + aoff + (long)(row0 + m) * a_rs + (kt + kq));
            As[kq+0][m] = v.x; As[kq+1][m] = v.y; As[kq+2][m] = v.z; As[kq+3][m] = v.w;
        } else {
            #pragma unroll
            for (int j = 0; j < 4; j++) {
                int e = tid + j * 256;
                int m = e & 127;
                int kk = e >> 7;
                As[kk][m] = A[aoff + (long)(row0 + m) * a_rs + (long)(kt + kk) * a_cs];
            }
        }
        // ---- load B tile ----
        {
            int k = tid >> 5;
            int n4 = (tid & 31) * 4;
            float4 v = make_float4(0.f, 0.f, 0.f, 0.f);
            if (col0 + n4 < N) {
                if (b_ns == 1) {
                    v = *(const float4*)(B + boff + (long)(kt + k) * b_ks + (col0 + n4));
                } else {
                    const float* bp = B + boff + (long)(kt + k) * b_ks;
                    v.x = bp[(long)(col0 + n4 + 0) * b_ns];
                    v.y = bp[(long)(col0 + n4 + 1) * b_ns];
                    v.z = bp[(long)(col0 + n4 + 2) * b_ns];
                    v.w = bp[(long)(col0 + n4 + 3) * b_ns];
                }
            }
            *(float4*)&Bs[k][n4] = v;
        }
        __syncthreads();
        #pragma unroll
        for (int kk = 0; kk < 8; kk++) {
            float a[8], b[8];
            *(float4*)&a[0] = *(const float4*)&As[kk][ty * 4];
            *(float4*)&a[4] = *(const float4*)&As[kk][64 + ty * 4];
            *(float4*)&b[0] = *(const float4*)&Bs[kk][tx * 4];
            *(float4*)&b[4] = *(const float4*)&Bs[kk][64 + tx * 4];
            #pragma unroll
            for (int i = 0; i < 8; i++)
                #pragma unroll
                for (int j = 0; j < 8; j++)
                    acc[i][j] += a[i] * b[j];
        }
        __syncthreads();
    }

    // ---- epilogue ----
    #pragma unroll
    for (int qi = 0; qi < 2; qi++) {
        #pragma unroll
        for (int i = 0; i < 4; i++) {
            int gm = row0 + qi * 64 + ty * 4 + i;
            long crow = coff + (long)gm * c_rs;
            float rdv = 1.0f;
            if (epi == 3)
                rdv = 1.0f / denom[(long)(batch >> 3) * d_so + (long)(batch & 7) * d_si + gm];
            #pragma unroll
            for (int qj = 0; qj < 2; qj++) {
                int gn = col0 + qj * 64 + tx * 4;
                if (gn >= N) continue;
                float r0 = alpha * acc[qi*4+i][qj*4+0];
                float r1 = alpha * acc[qi*4+i][qj*4+1];
                float r2 = alpha * acc[qi*4+i][qj*4+2];
                float r3 = alpha * acc[qi*4+i][qj*4+3];
                if (nsplit > 1) {
                    atomicAdd(C + crow + gn + 0, r0);
                    atomicAdd(C + crow + gn + 1, r1);
                    atomicAdd(C + crow + gn + 2, r2);
                    atomicAdd(C + crow + gn + 3, r3);
                } else {
                    if (bias) {
                        float4 bb = *(const float4*)(bias + gn);
                        r0 += bb.x; r1 += bb.y; r2 += bb.z; r3 += bb.w;
                    }
                    if (epi == 1) {
                        r0 = fmaxf(r0, 0.f); r1 = fmaxf(r1, 0.f);
                        r2 = fmaxf(r2, 0.f); r3 = fmaxf(r3, 0.f);
                    } else if (epi == 2) {
                        r0 = gelu_f(r0); r1 = gelu_f(r1); r2 = gelu_f(r2); r3 = gelu_f(r3);
                    } else if (epi == 3) {
                        r0 *= rdv; r1 *= rdv; r2 *= rdv; r3 *= rdv;
                    }
                    if (beta) {
                        float4 c0 = *(const float4*)(C + crow + gn);
                        r0 += c0.x; r1 += c0.y; r2 += c0.z; r3 += c0.w;
                    }
                    float4 w = make_float4(r0, r1, r2, r3);
                    *(float4*)(C + crow + gn) = w;
                }
            }
        }
    }
}

// ---------------- elementwise / reduction kernels ----------------
__global__ void zero_kernel(float* p, long n) {
    long i = (long)blockIdx.x * blockDim.x + threadIdx.x;
    long stride = (long)gridDim.x * blockDim.x;
    for (; i < n; i += stride) p[i] = 0.0f;
}

__global__ void embed_kernel(const float* __restrict__ x,
                             const float* __restrict__ w1,
                             const float* __restrict__ b1,
                             float* __restrict__ h)
{
    long i = blockIdx.x;
    int j = threadIdx.x;
    float v = x[i] * w1[j] + b1[j];
    h[i * DIM + j] = fmaxf(v, 0.0f);
}

__global__ void deg_kernel(const int* __restrict__ ei,
                           const float* __restrict__ ew,
                           float* __restrict__ deg)
{
    int e = blockIdx.x * blockDim.x + threadIdx.x;
    if (e < EEDG) atomicAdd(&deg[ei[EEDG + e]], ew[e]);
}

__global__ void dinv_kernel(const float* __restrict__ deg, float* __restrict__ dinv)
{
    int i = blockIdx.x * blockDim.x + threadIdx.x;
    if (i < NN) {
        float d = deg[i];
        dinv[i] = (d > 0.0f) ? rsqrtf(fmaxf(d, 1e-12f)) : 0.0f;
    }
}

__global__ void agg_kernel(const int* __restrict__ ei,
                           const float* __restrict__ ew,
                           const float* __restrict__ dinv,
                           const float* __restrict__ emb,
                           float* __restrict__ agg)
{
    int e = blockIdx.x;
    int j = threadIdx.x;
    int r = ei[e];
    int c = ei[EEDG + e];
    float w = dinv[r] * ew[e] * dinv[c];
    atomicAdd(&agg[(long)c * DIM + j], emb[(long)r * DIM + j] * w);
}

__global__ void zadd_kernel(float* __restrict__ z,
                            const float* __restrict__ pos,
                            const float* __restrict__ go)
{
    long i = blockIdx.x;
    int j = threadIdx.x;
    int n = (int)(i & (NN - 1));
    z[i * DIM + j] += pos[(long)n * DIM + j] + go[(long)n * DIM + j];
}

// warp-per-row LayerNorm (DIM=256)
__global__ void ln_kernel(const float* __restrict__ x,
                          const float* __restrict__ g,
                          const float* __restrict__ b,
                          float* __restrict__ y)
{
    int warp = threadIdx.x >> 5, lane = threadIdx.x & 31;
    long row = (long)blockIdx.x * 8 + warp;
    const float4* xr = (const float4*)(x + row * DIM);
    float4 v0 = xr[lane];
    float4 v1 = xr[lane + 32];
    float s  = v0.x + v0.y + v0.z + v0.w + v1.x + v1.y + v1.z + v1.w;
    float s2 = v0.x*v0.x + v0.y*v0.y + v0.z*v0.z + v0.w*v0.w
             + v1.x*v1.x + v1.y*v1.y + v1.z*v1.z + v1.w*v1.w;
    #pragma unroll
    for (int o = 16; o; o >>= 1) {
        s  += __shfl_xor_sync(0xffffffffu, s,  o);
        s2 += __shfl_xor_sync(0xffffffffu, s2, o);
    }
    float mean = s * (1.0f / DIM);
    float var = s2 * (1.0f / DIM) - mean * mean;
    float rstd = rsqrtf(fmaxf(var, 0.0f) + LNEPS);
    const float4* g4 = (const float4*)g;
    const float4* b4 = (const float4*)b;
    float4* yr = (float4*)(y + row * DIM);
    float4 ga = g4[lane], bb = b4[lane];
    float4 o0;
    o0.x = (v0.x - mean) * rstd * ga.x + bb.x;
    o0.y = (v0.y - mean) * rstd * ga.y + bb.y;
    o0.z = (v0.z - mean) * rstd * ga.z + bb.z;
    o0.w = (v0.w - mean) * rstd * ga.w + bb.w;
    yr[lane] = o0;
    ga = g4[lane + 32]; bb = b4[lane + 32];
    float4 o1;
    o1.x = (v1.x - mean) * rstd * ga.x + bb.x;
    o1.y = (v1.y - mean) * rstd * ga.y + bb.y;
    o1.z = (v1.z - mean) * rstd * ga.z + bb.z;
    o1.w = (v1.w - mean) * rstd * ga.w + bb.w;
    yr[lane + 32] = o1;
}

__global__ void transpose_proj_kernel(const float* __restrict__ proj,
                                      float* __restrict__ projT)
{
    int m = blockIdx.x;
    int d = threadIdx.x;   // 64
    projT[(long)d * NBF + m] = proj[(long)m * DH + d];
}

// per-row FAVOR postprocess: dd -> ratio*(exp(dd - diag - stab)+keps)
__global__ void favor_post_kernel(const float* __restrict__ qkv,
                                  float* __restrict__ dd,
                                  const float* __restrict__ stab_in,
                                  int isQ)
{
    int r = blockIdx.x;
    int n = r & (NN - 1), h = (r >> 13) & 7, b = r >> 16;
    int tid = threadIdx.x;
    __shared__ float sm[8];
    __shared__ float sm2[2];
    float v = dd[(long)r * NBF + tid];
    float m = v;
    #pragma unroll
    for (int o = 16; o; o >>= 1) m = fmaxf(m, __shfl_xor_sync(0xffffffffu, m, o));
    if ((tid & 31) == 0) sm[tid >> 5] = m;
    float sq = 0.0f;
    const float* qrow = qkv + ((long)(b * NN + n)) * INNER + h * DH;
    if (tid < DH) { float qv = qrow[tid] * DN; sq = qv * qv; }
    #pragma unroll
    for (int o = 16; o; o >>= 1) sq += __shfl_xor_sync(0xffffffffu, sq, o);
    if (tid < 64 && (tid & 31) == 0) sm2[tid >> 5] = sq;
    __syncthreads();
    float rmax = fmaxf(fmaxf(fmaxf(sm[0], sm[1]), fmaxf(sm[2], sm[3])),
                       fmaxf(fmaxf(sm[4], sm[5]), fmaxf(sm[6], sm[7])));
    float diag = 0.5f * (sm2[0] + sm2[1]);
    float stab = isQ ? rmax : stab_in[(b << 3) | h];
    dd[(long)r * NBF + tid] = RATIO * (expf(v - diag - stab) + KEPS);
}

// per-row max of dd (for K global stabilizer); warp per row
__global__ void rowmax_kernel(const float* __restrict__ dd, float* __restrict__ rowmax)
{
    int warp = threadIdx.x >> 5, lane = threadIdx.x & 31;
    long row = (long)blockIdx.x * 8 + warp;
    const float* p = dd + row * NBF;
    float m = -INFINITY;
    #pragma unroll
    for (int i = 0; i < 8; i++) m = fmaxf(m, p[lane + i * 32]);
    #pragma unroll
    for (int o = 16; o; o >>= 1) m = fmaxf(m, __shfl_xor_sync(0xffffffffu, m, o));
    if (lane == 0) rowmax[row] = m;
}

__global__ void stab_reduce_kernel(const float* __restrict__ rowmax,
                                   float* __restrict__ stab)
{
    int bh = blockIdx.x;
    int tid = threadIdx.x;
    __shared__ float red[256];
    float m = -INFINITY;
    for (int i = tid; i < NN; i += 256)
        m = fmaxf(m, rowmax[(long)bh * NN + i]);
    red[tid] = m; __syncthreads();
    for (int s = 128; s > 0; s >>= 1) {
        if (tid < s) red[tid] = fmaxf(red[tid], red[tid + s]);
        __syncthreads();
    }
    if (tid == 0) stab[bh] = red[0];
}

__global__ void ksum_kernel(const float* __restrict__ kf, float* __restrict__ ksum)
{
    int bh = blockIdx.x;
    int chunk = blockIdx.y;
    int m = threadIdx.x;
    const float* base = kf + (size_t)bh * NN * NBF;
    float s = 0.0f;
    int n0 = chunk * 256;
    for (int nn2 = n0; nn2 < n0 + 256; nn2++)
        s += base[(long)nn2 * NBF + m];
    atomicAdd(&ksum[bh * NBF + m], s);
}

// denom[row] = qf[row,:] . ksum[bh,:]; warp per row
__global__ void denom_kernel(const float* __restrict__ qf,
                             const float* __restrict__ ksum,
                             float* __restrict__ denom)
{
    int warp = threadIdx.x >> 5, lane = threadIdx.x & 31;
    long row = (long)blockIdx.x * 8 + warp;
    int bh = (int)(row >> 13);
    const float* q = qf + row * NBF;
    const float* ks = ksum + (long)bh * NBF;
    float s = 0.0f;
    #pragma unroll
    for (int i = 0; i < 8; i++) s += q[lane + i * 32] * ks[lane + i * 32];
    #pragma unroll
    for (int o = 16; o; o >>= 1) s += __shfl_xor_sync(0xffffffffu, s, o);
    if (lane == 0) denom[row] = s;
}

__global__ void head_kernel(const float* __restrict__ y,
                            const float* __restrict__ w,
                            const float* __restrict__ bb,
                            float* __restrict__ out)
{
    int warp = threadIdx.x >> 5, lane = threadIdx.x & 31;
    long row = (long)blockIdx.x * 8 + warp;
    const float* yr = y + row * DIM;
    float s = 0.0f;
    #pragma unroll
    for (int i = 0; i < 8; i++) s += yr[lane + i * 32] * w[lane + i * 32];
    #pragma unroll
    for (int o = 16; o; o >>= 1) s += __shfl_xor_sync(0xffffffffu, s, o);
    if (lane == 0) out[row] = s + bb[0];
}

// ---------------- host ----------------
static inline void launch_gemm(int M, int N, int K,
    const float* A, int a_rs, int a_cs, long a_so, long a_si,
    const float* B, int b_ks, int b_ns, long b_so, long b_si,
    float* C, int c_rs, long c_so, long c_si,
    const float* bias, const float* denom, long d_so, long d_si,
    float alpha, int beta, int epi, int nbatch, int nsplit)
{
    dim3 grid((N + 127) / 128, (M + 127) / 128, nbatch * nsplit);
    sgemm_kernel<<<grid, 256>>>(M, N, K, A, a_rs, a_cs, a_so, a_si,
                                B, b_ks, b_ns, b_so, b_si,
                                C, c_rs, c_so, c_si,
                                bias, denom, d_so, d_si,
                                alpha, beta, epi, nsplit);
}

extern "C" void kernel_launch(void* const* d_in, const int* in_sizes, int n_in,
                              void* d_out, int out_size)
{
    const float* x        = (const float*)d_in[0];
    const float* mlp_w1   = (const float*)d_in[1];
    const float* mlp_b1   = (const float*)d_in[2];
    const float* mlp_w2   = (const float*)d_in[3];
    const float* mlp_b2   = (const float*)d_in[4];
    const float* pos      = (const float*)d_in[5];
    const float* gnn_emb  = (const float*)d_in[6];
    const float* gnn_w    = (const float*)d_in[7];
    const float* gnn_b    = (const float*)d_in[8];
    const float* ew       = (const float*)d_in[9];
    const float* proj     = (const float*)d_in[10];
    const float* ln1_g    = (const float*)d_in[11];
    const float* ln1_b    = (const float*)d_in[12];
    const float* wq       = (const float*)d_in[13];
    const float* wk       = (const float*)d_in[14];
    const float* wv       = (const float*)d_in[15];
    const float* wo       = (const float*)d_in[16];
    const float* bo       = (const float*)d_in[17];
    const float* ln2_g    = (const float*)d_in[18];
    const float* ln2_b    = (const float*)d_in[19];
    const float* ffw1     = (const float*)d_in[20];
    const float* ffb1     = (const float*)d_in[21];
    const float* ffw2     = (const float*)d_in[22];
    const float* ffb2     = (const float*)d_in[23];
    const float* normf_g  = (const float*)d_in[24];
    const float* normf_b  = (const float*)d_in[25];
    const float* out_w    = (const float*)d_in[26];
    const float* out_b    = (const float*)d_in[27];
    const int*   ei       = (const int*)d_in[28];
    float* out            = (float*)d_out;

    float *z, *y, *q, *k, *v, *o, *ff, *qf, *kf, *agg, *go, *deg, *dinv;
    float *rowmax, *stab, *ksum, *ctx, *denom, *projT;
    cudaGetSymbolAddress((void**)&z, g_z);
    cudaGetSymbolAddress((void**)&y, g_y);
    cudaGetSymbolAddress((void**)&q, g_q);
    cudaGetSymbolAddress((void**)&k, g_k);
    cudaGetSymbolAddress((void**)&v, g_v);
    cudaGetSymbolAddress((void**)&o, g_o);
    cudaGetSymbolAddress((void**)&ff, g_ff);
    cudaGetSymbolAddress((void**)&qf, g_qf);
    cudaGetSymbolAddress((void**)&kf, g_kf);
    cudaGetSymbolAddress((void**)&agg, g_agg);
    cudaGetSymbolAddress((void**)&go, g_go);
    cudaGetSymbolAddress((void**)&deg, g_deg);
    cudaGetSymbolAddress((void**)&dinv, g_dinv);
    cudaGetSymbolAddress((void**)&rowmax, g_rowmax);
    cudaGetSymbolAddress((void**)&stab, g_stab);
    cudaGetSymbolAddress((void**)&ksum, g_ksum);
    cudaGetSymbolAddress((void**)&ctx, g_ctx);
    cudaGetSymbolAddress((void**)&denom, g_denom);
    cudaGetSymbolAddress((void**)&projT, g_projT);

    // ---- embedding ----
    embed_kernel<<<ROWS, DIM>>>(x, mlp_w1, mlp_b1, y);
    launch_gemm(ROWS, DIM, DIM, y, DIM, 1, 0, 0, mlp_w2, DIM, 1, 0, 0,
                z, DIM, 0, 0, mlp_b2, nullptr, 0, 0, 1.0f, 0, 0, 1, 1);

    // ---- GNN ----
    zero_kernel<<<64, 256>>>(deg, NN);
    zero_kernel<<<1024, 256>>>(agg, (long)NN * DIM);
    deg_kernel<<<EEDG / 256, 256>>>(ei, ew, deg);
    dinv_kernel<<<NN / 256, 256>>>(deg, dinv);
    agg_kernel<<<EEDG, DIM>>>(ei, ew, dinv, gnn_emb, agg);
    launch_gemm(NN, DIM, DIM, agg, DIM, 1, 0, 0, gnn_w, DIM, 1, 0, 0,
                go, DIM, 0, 0, gnn_b, nullptr, 0, 0, 1.0f, 0, 0, 1, 1);
    zadd_kernel<<<ROWS, DIM>>>(z, pos, go);

    // ---- proj transpose (once) ----
    transpose_proj_kernel<<<NBF, DH>>>(proj, projT);

    // ---- transformer layers ----
    for (int l = 0; l < 2; l++) {
        const float* wq_l   = wq  + (long)l * DIM * INNER;
        const float* wk_l   = wk  + (long)l * DIM * INNER;
        const float* wv_l   = wv  + (long)l * DIM * INNER;
        const float* wo_l   = wo  + (long)l * INNER * DIM;
        const float* bo_l   = bo  + (long)l * DIM;
        const float* ffw1_l = ffw1 + (long)l * DIM * FFD;
        const float* ffb1_l = ffb1 + (long)l * FFD;
        const float* ffw2_l = ffw2 + (long)l * FFD * DIM;
        const float* ffb2_l = ffb2 + (long)l * DIM;

        ln_kernel<<<ROWS / 8, 256>>>(z, ln1_g + l * DIM, ln1_b + l * DIM, y);

        launch_gemm(ROWS, INNER, DIM, y, DIM, 1, 0, 0, wq_l, INNER, 1, 0, 0,
                    q, INNER, 0, 0, nullptr, nullptr, 0, 0, 1.0f, 0, 0, 1, 1);
        launch_gemm(ROWS, INNER, DIM, y, DIM, 1, 0, 0, wk_l, INNER, 1, 0, 0,
                    k, INNER, 0, 0, nullptr, nullptr, 0, 0, 1.0f, 0, 0, 1, 1);
        launch_gemm(ROWS, INNER, DIM, y, DIM, 1, 0, 0, wv_l, INNER, 1, 0, 0,
                    v, INNER, 0, 0, nullptr, nullptr, 0, 0, 1.0f, 0, 0, 1, 1);

        // dd_q = (q*DN) @ projT  (batched over bh)
        launch_gemm(NN, NBF, DH,
                    q, INNER, 1, (long)NN * INNER, DH,
                    projT, NBF, 1, 0, 0,
                    qf, NBF, 8LL * NN * NBF, (long)NN * NBF,
                    nullptr, nullptr, 0, 0, DN, 0, 0, BH, 1);
        favor_post_kernel<<<BH * NN, 256>>>(q, qf, nullptr, 1);

        // dd_k
        launch_gemm(NN, NBF, DH,
                    k, INNER, 1, (long)NN * INNER, DH,
                    projT, NBF, 1, 0, 0,
                    kf, NBF, 8LL * NN * NBF, (long)NN * NBF,
                    nullptr, nullptr, 0, 0, DN, 0, 0, BH, 1);
        rowmax_kernel<<<BH * NN / 8, 256>>>(kf, rowmax);
        stab_reduce_kernel<<<BH, 256>>>(rowmax, stab);
        favor_post_kernel<<<BH * NN, 256>>>(k, kf, stab, 0);

        // ksum + ctx
        zero_kernel<<<16, 256>>>(ksum, BH * NBF);
        zero_kernel<<<256, 256>>>(ctx, (long)BH * NBF * DH);
        ksum_kernel<<<dim3(BH, 32), 256>>>(kf, ksum);
        launch_gemm(NBF, DH, NN,
                    kf, 1, NBF, 8LL * NN * NBF, (long)NN * NBF,
                    v, INNER, 1, (long)NN * INNER, DH,
                    ctx, DH, 8LL * NBF * DH, (long)NBF * DH,
                    nullptr, nullptr, 0, 0, 1.0f, 0, 0, BH, 32);

        // denom + attention output (divide epilogue)
        denom_kernel<<<BH * NN / 8, 256>>>(qf, ksum, denom);
        launch_gemm(NN, DH, NBF,
                    qf, NBF, 1, 8LL * NN * NBF, (long)NN * NBF,
                    ctx, DH, 1, 8LL * NBF * DH, (long)NBF * DH,
                    o, INNER, (long)NN * INNER, DH,
                    nullptr, denom, 8LL * NN, NN, 1.0f, 0, 3, BH, 1);

        // z += o @ Wo + bo
        launch_gemm(ROWS, DIM, INNER, o, INNER, 1, 0, 0, wo_l, DIM, 1, 0, 0,
                    z, DIM, 0, 0, bo_l, nullptr, 0, 0, 1.0f, 1, 0, 1, 1);

        // FFN
        ln_kernel<<<ROWS / 8, 256>>>(z, ln2_g + l * DIM, ln2_b + l * DIM, y);
        launch_gemm(ROWS, FFD, DIM, y, DIM, 1, 0, 0, ffw1_l, FFD, 1, 0, 0,
                    ff, FFD, 0, 0, ffb1_l, nullptr, 0, 0, 1.0f, 0, 2, 1, 1);
        launch_gemm(ROWS, DIM, FFD, ff, FFD, 1, 0, 0, ffw2_l, DIM, 1, 0, 0,
                    z, DIM, 0, 0, ffb2_l, nullptr, 0, 0, 1.0f, 1, 0, 1, 1);
    }

    // ---- final LN + head ----
    ln_kernel<<<ROWS / 8, 256>>>(z, normf_g, normf_b, y);
    head_kernel<<<ROWS / 8, 256>>>(y, out_w, out_b, out);
}

// round 3
// speedup vs baseline: 20.8495x; 1.9107x over previous
#include <cuda_runtime.h>
#include <math.h>
#include <stdint.h>

// ---------------- problem constants ----------------
#define BSZ    2
#define NN     8192
#define DIM    256
#define HEADS  8
#define DH     64
#define INNER  512
#define NBF    256
#define FFD    1024
#define EEDG   131072
#define ROWS   (BSZ*NN)
#define BH     (BSZ*HEADS)
#define KEPS   1e-4f
#define LNEPS  1e-5f
#define DN     0.3535533905932738f   /* 64^-0.25 */
#define RATIO  0.0625f               /* 256^-0.5 */

// ---------------- scratch ----------------
__device__ float g_z[ROWS*DIM];
__device__ float g_y[ROWS*DIM];
__device__ float g_q[ROWS*INNER];
__device__ float g_k[ROWS*INNER];
__device__ float g_v[ROWS*INNER];
__device__ float g_o[ROWS*INNER];
__device__ float g_ff[(size_t)ROWS*FFD];
__device__ float g_qf[(size_t)BH*NN*NBF];
__device__ float g_kf[(size_t)BH*NN*NBF];
__device__ float g_agg[NN*DIM];
__device__ float g_go[NN*DIM];
__device__ float g_deg[NN];
__device__ float g_dinv[NN];
__device__ float g_rowmax[BH*NN];
__device__ float g_stab[BH];
__device__ float g_ksum[BH*NBF];
__device__ float g_ctx[BH*NBF*DH];
__device__ float g_denom[BH*NN];
__device__ float g_projT[DH*NBF];

__device__ __forceinline__ float gelu_f(float v) {
    const float c = 0.7978845608028654f;
    float t = tanhf(c * (v + 0.044715f * v * v * v));
    return 0.5f * v * (1.0f + t);
}

__device__ __forceinline__ float cvt_tf32(float x) {
    uint32_t u;
    asm("cvt.rna.tf32.f32 %0, %1;" : "=r"(u) : "f"(x));
    return __uint_as_float(u);
}

__device__ __forceinline__ void mma_tf32(float* c, const uint32_t* a,
                                         uint32_t b0, uint32_t b1) {
    asm volatile(
        "mma.sync.aligned.m16n8k8.row.col.f32.tf32.tf32.f32 "
        "{%0,%1,%2,%3}, {%4,%5,%6,%7}, {%8,%9}, {%0,%1,%2,%3};\n"
        : "+f"(c[0]), "+f"(c[1]), "+f"(c[2]), "+f"(c[3])
        : "r"(a[0]), "r"(a[1]), "r"(a[2]), "r"(a[3]), "r"(b0), "r"(b1));
}

// =====================================================================
// tf32 tensor-core GEMM. Block 128 x BN, 4 warps, warp tile 64 x WN.
// BK=16, double-buffered smem. Requirements: M%128==0, N%BN==0,
// (K/nsplit)%16==0, B row-major contiguous in n (b_ns==1),
// A either row-contiguous (a_cs==1) or col-contiguous (a_rs==1).
// Batch offset: (batch>>3)*so + (batch&7)*si.
// epi: 0 none, 1 relu, 2 gelu, 3 divide-by-denom[row].
// nsplit>1 -> atomicAdd into C (no bias/epi/beta).
// =====================================================================
template<int BN, int WN>
__global__ __launch_bounds__(128)
void tgemm_kernel(int M, int N, int K,
                  const float* __restrict__ A, int a_rs, int a_cs, long a_so, long a_si,
                  const float* __restrict__ B, int b_ks, long b_so, long b_si,
                  float* __restrict__ C, int c_rs, long c_so, long c_si,
                  const float* __restrict__ bias,
                  const float* __restrict__ denom, long d_so, long d_si,
                  float alpha, int beta, int epi, int nsplit)
{
    constexpr int BK = 16;
    constexpr int SA = 136;        // 136 % 32 == 8 -> conflict-free frag loads
    constexpr int SB = BN + 8;
    constexpr int NI = WN / 8;
    constexpr int NBL = BN / 32;   // B float4 loads per thread
    __shared__ float As[2][BK][SA];
    __shared__ float Bs[2][BK][SB];

    int zz = blockIdx.z;
    int batch = zz / nsplit;
    int split = zz - batch * nsplit;
    long aoff = (long)(batch >> 3) * a_so + (long)(batch & 7) * a_si;
    long boff = (long)(batch >> 3) * b_so + (long)(batch & 7) * b_si;
    long coff = (long)(batch >> 3) * c_so + (long)(batch & 7) * c_si;
    int row0 = blockIdx.y * 128;
    int col0 = blockIdx.x * BN;
    int kchunk = K / nsplit;
    int kbeg = split * kchunk;
    int kend = kbeg + kchunk;

    int tid = threadIdx.x;
    int lane = tid & 31;
    int warp = tid >> 5;
    int m_warp = (warp >> 1) * 64;
    int n_warp = (warp & 1) * WN;

    float c[4][NI][4];
    #pragma unroll
    for (int i = 0; i < 4; i++)
        #pragma unroll
        for (int j = 0; j < NI; j++)
            #pragma unroll
            for (int t = 0; t < 4; t++) c[i][j][t] = 0.0f;

    float4 ra[4];
    float4 rb[NBL];

    auto loadA = [&](int kt) {
        if (a_cs == 1) {
            #pragma unroll
            for (int i = 0; i < 4; i++) {
                int idx = tid + i * 128;
                int m = idx >> 2;
                int kc = (idx & 3) * 4;
                ra[i] = *(const float4*)(A + aoff + (long)(row0 + m) * a_rs + kt + kc);
            }
        } else {
            #pragma unroll
            for (int i = 0; i < 4; i++) {
                int idx = tid + i * 128;
                int m4 = (idx & 31) * 4;
                int kk = idx >> 5;
                ra[i] = *(const float4*)(A + aoff + (long)(kt + kk) * a_cs + row0 + m4);
            }
        }
    };
    auto storeA = [&](int bf) {
        if (a_cs == 1) {
            #pragma unroll
            for (int i = 0; i < 4; i++) {
                int idx = tid + i * 128;
                int m = idx >> 2;
                int kc = (idx & 3) * 4;
                float v[4] = {ra[i].x, ra[i].y, ra[i].z, ra[i].w};
                #pragma unroll
                for (int j0 = 0; j0 < 4; j0++) {
                    int j = (j0 + lane) & 3;     // rotate to kill store conflicts
                    As[bf][kc + j][m] = cvt_tf32(v[j]);
                }
            }
        } else {
            #pragma unroll
            for (int i = 0; i < 4; i++) {
                int idx = tid + i * 128;
                int m4 = (idx & 31) * 4;
                int kk = idx >> 5;
                float4 t;
                t.x = cvt_tf32(ra[i].x); t.y = cvt_tf32(ra[i].y);
                t.z = cvt_tf32(ra[i].z); t.w = cvt_tf32(ra[i].w);
                *(float4*)&As[bf][kk][m4] = t;
            }
        }
    };
    auto loadB = [&](int kt) {
        #pragma unroll
        for (int i = 0; i < NBL; i++) {
            int idx = tid + i * 128;
            int n4 = (idx & (BN / 4 - 1)) * 4;
            int kk = idx / (BN / 4);
            rb[i] = *(const float4*)(B + boff + (long)(kt + kk) * b_ks + col0 + n4);
        }
    };
    auto storeB = [&](int bf) {
        #pragma unroll
        for (int i = 0; i < NBL; i++) {
            int idx = tid + i * 128;
            int n4 = (idx & (BN / 4 - 1)) * 4;
            int kk = idx / (BN / 4);
            float4 t;
            t.x = cvt_tf32(rb[i].x); t.y = cvt_tf32(rb[i].y);
            t.z = cvt_tf32(rb[i].z); t.w = cvt_tf32(rb[i].w);
            *(float4*)&Bs[bf][kk][n4] = t;
        }
    };
    auto compute = [&](int bf) {
        #pragma unroll
        for (int s = 0; s < 2; s++) {
            int k8 = s * 8;
            uint32_t af[4][4];
            #pragma unroll
            for (int mi = 0; mi < 4; mi++) {
                int mr = m_warp + mi * 16 + (lane >> 2);
                af[mi][0] = __float_as_uint(As[bf][k8 + (lane & 3)][mr]);
                af[mi][1] = __float_as_uint(As[bf][k8 + (lane & 3)][mr + 8]);
                af[mi][2] = __float_as_uint(As[bf][k8 + 4 + (lane & 3)][mr]);
                af[mi][3] = __float_as_uint(As[bf][k8 + 4 + (lane & 3)][mr + 8]);
            }
            #pragma unroll
            for (int ni = 0; ni < NI; ni++) {
                int nc = n_warp + ni * 8 + (lane >> 2);
                uint32_t b0 = __float_as_uint(Bs[bf][k8 + (lane & 3)][nc]);
                uint32_t b1 = __float_as_uint(Bs[bf][k8 + 4 + (lane & 3)][nc]);
                #pragma unroll
                for (int mi = 0; mi < 4; mi++)
                    mma_tf32(c[mi][ni], af[mi], b0, b1);
            }
        }
    };

    // prologue
    loadA(kbeg); loadB(kbeg);
    storeA(0);   storeB(0);
    __syncthreads();
    int buf = 0;
    for (int kt = kbeg; kt < kend; kt += BK) {
        bool has_next = (kt + BK) < kend;
        if (has_next) { loadA(kt + BK); loadB(kt + BK); }
        compute(buf);
        if (has_next) {
            storeA(buf ^ 1); storeB(buf ^ 1);
            __syncthreads();
            buf ^= 1;
        }
    }

    // epilogue
    #pragma unroll
    for (int mi = 0; mi < 4; mi++) {
        int r = row0 + m_warp + mi * 16 + (lane >> 2);
        long crow0 = coff + (long)r * c_rs;
        long crow1 = coff + (long)(r + 8) * c_rs;
        float rdv0 = 1.0f, rdv1 = 1.0f;
        if (epi == 3) {
            long dof = (long)(batch >> 3) * d_so + (long)(batch & 7) * d_si;
            rdv0 = 1.0f / denom[dof + r];
            rdv1 = 1.0f / denom[dof + r + 8];
        }
        #pragma unroll
        for (int ni = 0; ni < NI; ni++) {
            int cc = col0 + n_warp + ni * 8 + 2 * (lane & 3);
            float v0 = alpha * c[mi][ni][0];
            float v1 = alpha * c[mi][ni][1];
            float v2 = alpha * c[mi][ni][2];
            float v3 = alpha * c[mi][ni][3];
            if (nsplit > 1) {
                atomicAdd(C + crow0 + cc,     v0);
                atomicAdd(C + crow0 + cc + 1, v1);
                atomicAdd(C + crow1 + cc,     v2);
                atomicAdd(C + crow1 + cc + 1, v3);
            } else {
                if (bias) {
                    float2 bb = *(const float2*)(bias + cc);
                    v0 += bb.x; v1 += bb.y; v2 += bb.x; v3 += bb.y;
                }
                if (epi == 1) {
                    v0 = fmaxf(v0, 0.f); v1 = fmaxf(v1, 0.f);
                    v2 = fmaxf(v2, 0.f); v3 = fmaxf(v3, 0.f);
                } else if (epi == 2) {
                    v0 = gelu_f(v0); v1 = gelu_f(v1);
                    v2 = gelu_f(v2); v3 = gelu_f(v3);
                } else if (epi == 3) {
                    v0 *= rdv0; v1 *= rdv0; v2 *= rdv1; v3 *= rdv1;
                }
                if (beta) {
                    float2 c0 = *(const float2*)(C + crow0 + cc);
                    float2 c1 = *(const float2*)(C + crow1 + cc);
                    v0 += c0.x; v1 += c0.y; v2 += c1.x; v3 += c1.y;
                }
                *(float2*)(C + crow0 + cc) = make_float2(v0, v1);
                *(float2*)(C + crow1 + cc) = make_float2(v2, v3);
            }
        }
    }
}

// =====================================================================
// fp32 SGEMM (kept for the FAVOR dd projections, K=64 — exp() feeds on
// these, keep full precision)
// =====================================================================
__global__ __launch_bounds__(256, 2)
void sgemm_kernel(int M, int N, int K,
                  const float* __restrict__ A, int a_rs, int a_cs, long a_so, long a_si,
                  const float* __restrict__ B, int b_ks, int b_ns, long b_so, long b_si,
                  float* __restrict__ C, int c_rs, long c_so, long c_si,
                  const float* __restrict__ bias,
                  float alpha, int nsplit)
{
    __shared__ float As[8][132];
    __shared__ float Bs[8][132];

    int zz = blockIdx.z;
    int batch = zz / nsplit;
    int split = zz - batch * nsplit;
    long aoff = (long)(batch >> 3) * a_so + (long)(batch & 7) * a_si;
    long boff = (long)(batch >> 3) * b_so + (long)(batch & 7) * b_si;
    long coff = (long)(batch >> 3) * c_so + (long)(batch & 7) * c_si;

    int row0 = blockIdx.y * 128;
    int col0 = blockIdx.x * 128;
    int kchunk = K / nsplit;
    int kbeg = split * kchunk;

    int tid = threadIdx.x;
    int tx = tid & 15, ty = tid >> 4;

    float acc[8][8];
    #pragma unroll
    for (int i = 0; i < 8; i++)
        #pragma unroll
        for (int j = 0; j < 8; j++) acc[i][j] = 0.0f;

    for (int kt = kbeg; kt < kbeg + kchunk; kt += 8) {
        if (a_cs == 1) {
            int m = tid >> 1;
            int kq = (tid & 1) * 4;
            float4 v = *(const float4*)(A + aoff + (long)(row0 + m) * a_rs + (kt + kq));
            As[kq+0][m] = v.x; As[kq+1][m] = v.y; As[kq+2][m] = v.z; As[kq+3][m] = v.w;
        } else {
            #pragma unroll
            for (int j = 0; j < 4; j++) {
                int e = tid + j * 256;
                int m = e & 127;
                int kk = e >> 7;
                As[kk][m] = A[aoff + (long)(row0 + m) * a_rs + (long)(kt + kk) * a_cs];
            }
        }
        {
            int k = tid >> 5;
            int n4 = (tid & 31) * 4;
            float4 v = make_float4(0.f, 0.f, 0.f, 0.f);
            if (col0 + n4 < N)
                v = *(const float4*)(B + boff + (long)(kt + k) * b_ks + (col0 + n4));
            *(float4*)&Bs[k][n4] = v;
        }
        __syncthreads();
        #pragma unroll
        for (int kk = 0; kk < 8; kk++) {
            float a[8], b[8];
            *(float4*)&a[0] = *(const float4*)&As[kk][ty * 4];
            *(float4*)&a[4] = *(const float4*)&As[kk][64 + ty * 4];
            *(float4*)&b[0] = *(const float4*)&Bs[kk][tx * 4];
            *(float4*)&b[4] = *(const float4*)&Bs[kk][64 + tx * 4];
            #pragma unroll
            for (int i = 0; i < 8; i++)
                #pragma unroll
                for (int j = 0; j < 8; j++)
                    acc[i][j] += a[i] * b[j];
        }
        __syncthreads();
    }

    #pragma unroll
    for (int qi = 0; qi < 2; qi++) {
        #pragma unroll
        for (int i = 0; i < 4; i++) {
            int gm = row0 + qi * 64 + ty * 4 + i;
            long crow = coff + (long)gm * c_rs;
            #pragma unroll
            for (int qj = 0; qj < 2; qj++) {
                int gn = col0 + qj * 64 + tx * 4;
                if (gn >= N) continue;
                float r0 = alpha * acc[qi*4+i][qj*4+0];
                float r1 = alpha * acc[qi*4+i][qj*4+1];
                float r2 = alpha * acc[qi*4+i][qj*4+2];
                float r3 = alpha * acc[qi*4+i][qj*4+3];
                if (bias) {
                    float4 bb = *(const float4*)(bias + gn);
                    r0 += bb.x; r1 += bb.y; r2 += bb.z; r3 += bb.w;
                }
                *(float4*)(C + crow + gn) = make_float4(r0, r1, r2, r3);
            }
        }
    }
}

// ---------------- elementwise / reduction kernels ----------------
__global__ void zero_kernel(float* p, long n) {
    long i = (long)blockIdx.x * blockDim.x + threadIdx.x;
    long stride = (long)gridDim.x * blockDim.x;
    for (; i < n; i += stride) p[i] = 0.0f;
}

__global__ void embed_kernel(const float* __restrict__ x,
                             const float* __restrict__ w1,
                             const float* __restrict__ b1,
                             float* __restrict__ h)
{
    long i = blockIdx.x;
    int j = threadIdx.x;
    float v = x[i] * w1[j] + b1[j];
    h[i * DIM + j] = fmaxf(v, 0.0f);
}

__global__ void deg_kernel(const int* __restrict__ ei,
                           const float* __restrict__ ew,
                           float* __restrict__ deg)
{
    int e = blockIdx.x * blockDim.x + threadIdx.x;
    if (e < EEDG) atomicAdd(&deg[ei[EEDG + e]], ew[e]);
}

__global__ void dinv_kernel(const float* __restrict__ deg, float* __restrict__ dinv)
{
    int i = blockIdx.x * blockDim.x + threadIdx.x;
    if (i < NN) {
        float d = deg[i];
        dinv[i] = (d > 0.0f) ? rsqrtf(fmaxf(d, 1e-12f)) : 0.0f;
    }
}

__global__ void agg_kernel(const int* __restrict__ ei,
                           const float* __restrict__ ew,
                           const float* __restrict__ dinv,
                           const float* __restrict__ emb,
                           float* __restrict__ agg)
{
    int e = blockIdx.x;
    int j = threadIdx.x;
    int r = ei[e];
    int c = ei[EEDG + e];
    float w = dinv[r] * ew[e] * dinv[c];
    atomicAdd(&agg[(long)c * DIM + j], emb[(long)r * DIM + j] * w);
}

__global__ void zadd_kernel(float* __restrict__ z,
                            const float* __restrict__ pos,
                            const float* __restrict__ go)
{
    long i = blockIdx.x;
    int j = threadIdx.x;
    int n = (int)(i & (NN - 1));
    z[i * DIM + j] += pos[(long)n * DIM + j] + go[(long)n * DIM + j];
}

__global__ void ln_kernel(const float* __restrict__ x,
                          const float* __restrict__ g,
                          const float* __restrict__ b,
                          float* __restrict__ y)
{
    int warp = threadIdx.x >> 5, lane = threadIdx.x & 31;
    long row = (long)blockIdx.x * 8 + warp;
    const float4* xr = (const float4*)(x + row * DIM);
    float4 v0 = xr[lane];
    float4 v1 = xr[lane + 32];
    float s  = v0.x + v0.y + v0.z + v0.w + v1.x + v1.y + v1.z + v1.w;
    float s2 = v0.x*v0.x + v0.y*v0.y + v0.z*v0.z + v0.w*v0.w
             + v1.x*v1.x + v1.y*v1.y + v1.z*v1.z + v1.w*v1.w;
    #pragma unroll
    for (int o = 16; o; o >>= 1) {
        s  += __shfl_xor_sync(0xffffffffu, s,  o);
        s2 += __shfl_xor_sync(0xffffffffu, s2, o);
    }
    float mean = s * (1.0f / DIM);
    float var = s2 * (1.0f / DIM) - mean * mean;
    float rstd = rsqrtf(fmaxf(var, 0.0f) + LNEPS);
    const float4* g4 = (const float4*)g;
    const float4* b4 = (const float4*)b;
    float4* yr = (float4*)(y + row * DIM);
    float4 ga = g4[lane], bb = b4[lane];
    float4 o0;
    o0.x = (v0.x - mean) * rstd * ga.x + bb.x;
    o0.y = (v0.y - mean) * rstd * ga.y + bb.y;
    o0.z = (v0.z - mean) * rstd * ga.z + bb.z;
    o0.w = (v0.w - mean) * rstd * ga.w + bb.w;
    yr[lane] = o0;
    ga = g4[lane + 32]; bb = b4[lane + 32];
    float4 o1;
    o1.x = (v1.x - mean) * rstd * ga.x + bb.x;
    o1.y = (v1.y - mean) * rstd * ga.y + bb.y;
    o1.z = (v1.z - mean) * rstd * ga.z + bb.z;
    o1.w = (v1.w - mean) * rstd * ga.w + bb.w;
    yr[lane + 32] = o1;
}

__global__ void transpose_proj_kernel(const float* __restrict__ proj,
                                      float* __restrict__ projT)
{
    int m = blockIdx.x;
    int d = threadIdx.x;
    projT[(long)d * NBF + m] = proj[(long)m * DH + d];
}

__global__ void favor_post_kernel(const float* __restrict__ qkv,
                                  float* __restrict__ dd,
                                  const float* __restrict__ stab_in,
                                  int isQ)
{
    int r = blockIdx.x;
    int n = r & (NN - 1), h = (r >> 13) & 7, b = r >> 16;
    int tid = threadIdx.x;
    __shared__ float sm[8];
    __shared__ float sm2[2];
    float v = dd[(long)r * NBF + tid];
    float m = v;
    #pragma unroll
    for (int o = 16; o; o >>= 1) m = fmaxf(m, __shfl_xor_sync(0xffffffffu, m, o));
    if ((tid & 31) == 0) sm[tid >> 5] = m;
    float sq = 0.0f;
    const float* qrow = qkv + ((long)(b * NN + n)) * INNER + h * DH;
    if (tid < DH) { float qv = qrow[tid] * DN; sq = qv * qv; }
    #pragma unroll
    for (int o = 16; o; o >>= 1) sq += __shfl_xor_sync(0xffffffffu, sq, o);
    if (tid < 64 && (tid & 31) == 0) sm2[tid >> 5] = sq;
    __syncthreads();
    float rmax = fmaxf(fmaxf(fmaxf(sm[0], sm[1]), fmaxf(sm[2], sm[3])),
                       fmaxf(fmaxf(sm[4], sm[5]), fmaxf(sm[6], sm[7])));
    float diag = 0.5f * (sm2[0] + sm2[1]);
    float stab = isQ ? rmax : stab_in[(b << 3) | h];
    dd[(long)r * NBF + tid] = RATIO * (expf(v - diag - stab) + KEPS);
}

__global__ void rowmax_kernel(const float* __restrict__ dd, float* __restrict__ rowmax)
{
    int warp = threadIdx.x >> 5, lane = threadIdx.x & 31;
    long row = (long)blockIdx.x * 8 + warp;
    const float* p = dd + row * NBF;
    float m = -INFINITY;
    #pragma unroll
    for (int i = 0; i < 8; i++) m = fmaxf(m, p[lane + i * 32]);
    #pragma unroll
    for (int o = 16; o; o >>= 1) m = fmaxf(m, __shfl_xor_sync(0xffffffffu, m, o));
    if (lane == 0) rowmax[row] = m;
}

__global__ void stab_reduce_kernel(const float* __restrict__ rowmax,
                                   float* __restrict__ stab)
{
    int bh = blockIdx.x;
    int tid = threadIdx.x;
    __shared__ float red[256];
    float m = -INFINITY;
    for (int i = tid; i < NN; i += 256)
        m = fmaxf(m, rowmax[(long)bh * NN + i]);
    red[tid] = m; __syncthreads();
    for (int s = 128; s > 0; s >>= 1) {
        if (tid < s) red[tid] = fmaxf(red[tid], red[tid + s]);
        __syncthreads();
    }
    if (tid == 0) stab[bh] = red[0];
}

__global__ void ksum_kernel(const float* __restrict__ kf, float* __restrict__ ksum)
{
    int bh = blockIdx.x;
    int chunk = blockIdx.y;
    int m = threadIdx.x;
    const float* base = kf + (size_t)bh * NN * NBF;
    float s = 0.0f;
    int n0 = chunk * 256;
    for (int nn2 = n0; nn2 < n0 + 256; nn2++)
        s += base[(long)nn2 * NBF + m];
    atomicAdd(&ksum[bh * NBF + m], s);
}

__global__ void denom_kernel(const float* __restrict__ qf,
                             const float* __restrict__ ksum,
                             float* __restrict__ denom)
{
    int warp = threadIdx.x >> 5, lane = threadIdx.x & 31;
    long row = (long)blockIdx.x * 8 + warp;
    int bh = (int)(row >> 13);
    const float* q = qf + row * NBF;
    const float* ks = ksum + (long)bh * NBF;
    float s = 0.0f;
    #pragma unroll
    for (int i = 0; i < 8; i++) s += q[lane + i * 32] * ks[lane + i * 32];
    #pragma unroll
    for (int o = 16; o; o >>= 1) s += __shfl_xor_sync(0xffffffffu, s, o);
    if (lane == 0) denom[row] = s;
}

__global__ void head_kernel(const float* __restrict__ y,
                            const float* __restrict__ w,
                            const float* __restrict__ bb,
                            float* __restrict__ out)
{
    int warp = threadIdx.x >> 5, lane = threadIdx.x & 31;
    long row = (long)blockIdx.x * 8 + warp;
    const float* yr = y + row * DIM;
    float s = 0.0f;
    #pragma unroll
    for (int i = 0; i < 8; i++) s += yr[lane + i * 32] * w[lane + i * 32];
    #pragma unroll
    for (int o = 16; o; o >>= 1) s += __shfl_xor_sync(0xffffffffu, s, o);
    if (lane == 0) out[row] = s + bb[0];
}

// ---------------- host ----------------
template<int BN, int WN>
static inline void launch_tgemm(int M, int N, int K,
    const float* A, int a_rs, int a_cs, long a_so, long a_si,
    const float* B, int b_ks, long b_so, long b_si,
    float* C, int c_rs, long c_so, long c_si,
    const float* bias, const float* denom, long d_so, long d_si,
    float alpha, int beta, int epi, int nbatch, int nsplit)
{
    dim3 grid(N / BN, M / 128, nbatch * nsplit);
    tgemm_kernel<BN, WN><<<grid, 128>>>(M, N, K, A, a_rs, a_cs, a_so, a_si,
                                        B, b_ks, b_so, b_si, C, c_rs, c_so, c_si,
                                        bias, denom, d_so, d_si, alpha, beta, epi, nsplit);
}

static inline void launch_sgemm(int M, int N, int K,
    const float* A, int a_rs, int a_cs, long a_so, long a_si,
    const float* B, int b_ks, long b_so, long b_si,
    float* C, int c_rs, long c_so, long c_si,
    const float* bias, float alpha, int nbatch, int nsplit)
{
    dim3 grid((N + 127) / 128, (M + 127) / 128, nbatch * nsplit);
    sgemm_kernel<<<grid, 256>>>(M, N, K, A, a_rs, a_cs, a_so, a_si,
                                B, b_ks, 1, b_so, b_si, C, c_rs, c_so, c_si,
                                bias, alpha, nsplit);
}

extern "C" void kernel_launch(void* const* d_in, const int* in_sizes, int n_in,
                              void* d_out, int out_size)
{
    const float* x        = (const float*)d_in[0];
    const float* mlp_w1   = (const float*)d_in[1];
    const float* mlp_b1   = (const float*)d_in[2];
    const float* mlp_w2   = (const float*)d_in[3];
    const float* mlp_b2   = (const float*)d_in[4];
    const float* pos      = (const float*)d_in[5];
    const float* gnn_emb  = (const float*)d_in[6];
    const float* gnn_w    = (const float*)d_in[7];
    const float* gnn_b    = (const float*)d_in[8];
    const float* ew       = (const float*)d_in[9];
    const float* proj     = (const float*)d_in[10];
    const float* ln1_g    = (const float*)d_in[11];
    const float* ln1_b    = (const float*)d_in[12];
    const float* wq       = (const float*)d_in[13];
    const float* wk       = (const float*)d_in[14];
    const float* wv       = (const float*)d_in[15];
    const float* wo       = (const float*)d_in[16];
    const float* bo       = (const float*)d_in[17];
    const float* ln2_g    = (const float*)d_in[18];
    const float* ln2_b    = (const float*)d_in[19];
    const float* ffw1     = (const float*)d_in[20];
    const float* ffb1     = (const float*)d_in[21];
    const float* ffw2     = (const float*)d_in[22];
    const float* ffb2     = (const float*)d_in[23];
    const float* normf_g  = (const float*)d_in[24];
    const float* normf_b  = (const float*)d_in[25];
    const float* out_w    = (const float*)d_in[26];
    const float* out_b    = (const float*)d_in[27];
    const int*   ei       = (const int*)d_in[28];
    float* out            = (float*)d_out;

    float *z, *y, *q, *k, *v, *o, *ff, *qf, *kf, *agg, *go, *deg, *dinv;
    float *rowmax, *stab, *ksum, *ctx, *denom, *projT;
    cudaGetSymbolAddress((void**)&z, g_z);
    cudaGetSymbolAddress((void**)&y, g_y);
    cudaGetSymbolAddress((void**)&q, g_q);
    cudaGetSymbolAddress((void**)&k, g_k);
    cudaGetSymbolAddress((void**)&v, g_v);
    cudaGetSymbolAddress((void**)&o, g_o);
    cudaGetSymbolAddress((void**)&ff, g_ff);
    cudaGetSymbolAddress((void**)&qf, g_qf);
    cudaGetSymbolAddress((void**)&kf, g_kf);
    cudaGetSymbolAddress((void**)&agg, g_agg);
    cudaGetSymbolAddress((void**)&go, g_go);
    cudaGetSymbolAddress((void**)&deg, g_deg);
    cudaGetSymbolAddress((void**)&dinv, g_dinv);
    cudaGetSymbolAddress((void**)&rowmax, g_rowmax);
    cudaGetSymbolAddress((void**)&stab, g_stab);
    cudaGetSymbolAddress((void**)&ksum, g_ksum);
    cudaGetSymbolAddress((void**)&ctx, g_ctx);
    cudaGetSymbolAddress((void**)&denom, g_denom);
    cudaGetSymbolAddress((void**)&projT, g_projT);

    // ---- GNN prep first (so the 6th launch ncu profiles is a tgemm) ----
    zero_kernel<<<64, 256>>>(deg, NN);
    zero_kernel<<<1024, 256>>>(agg, (long)NN * DIM);
    deg_kernel<<<EEDG / 256, 256>>>(ei, ew, deg);
    dinv_kernel<<<NN / 256, 256>>>(deg, dinv);

    // ---- embedding ----
    embed_kernel<<<ROWS, DIM>>>(x, mlp_w1, mlp_b1, y);
    launch_tgemm<128, 64>(ROWS, DIM, DIM, y, DIM, 1, 0, 0, mlp_w2, DIM, 0, 0,
                          z, DIM, 0, 0, mlp_b2, nullptr, 0, 0, 1.0f, 0, 0, 1, 1);

    // ---- GNN aggregate ----
    agg_kernel<<<EEDG, DIM>>>(ei, ew, dinv, gnn_emb, agg);
    launch_tgemm<128, 64>(NN, DIM, DIM, agg, DIM, 1, 0, 0, gnn_w, DIM, 0, 0,
                          go, DIM, 0, 0, gnn_b, nullptr, 0, 0, 1.0f, 0, 0, 1, 1);
    zadd_kernel<<<ROWS, DIM>>>(z, pos, go);

    transpose_proj_kernel<<<NBF, DH>>>(proj, projT);

    // ---- transformer layers ----
    for (int l = 0; l < 2; l++) {
        const float* wq_l   = wq  + (long)l * DIM * INNER;
        const float* wk_l   = wk  + (long)l * DIM * INNER;
        const float* wv_l   = wv  + (long)l * DIM * INNER;
        const float* wo_l   = wo  + (long)l * INNER * DIM;
        const float* bo_l   = bo  + (long)l * DIM;
        const float* ffw1_l = ffw1 + (long)l * DIM * FFD;
        const float* ffb1_l = ffb1 + (long)l * FFD;
        const float* ffw2_l = ffw2 + (long)l * FFD * DIM;
        const float* ffb2_l = ffb2 + (long)l * DIM;

        ln_kernel<<<ROWS / 8, 256>>>(z, ln1_g + l * DIM, ln1_b + l * DIM, y);

        launch_tgemm<128, 64>(ROWS, INNER, DIM, y, DIM, 1, 0, 0, wq_l, INNER, 0, 0,
                              q, INNER, 0, 0, nullptr, nullptr, 0, 0, 1.0f, 0, 0, 1, 1);
        launch_tgemm<128, 64>(ROWS, INNER, DIM, y, DIM, 1, 0, 0, wk_l, INNER, 0, 0,
                              k, INNER, 0, 0, nullptr, nullptr, 0, 0, 1.0f, 0, 0, 1, 1);
        launch_tgemm<128, 64>(ROWS, INNER, DIM, y, DIM, 1, 0, 0, wv_l, INNER, 0, 0,
                              v, INNER, 0, 0, nullptr, nullptr, 0, 0, 1.0f, 0, 0, 1, 1);

        // dd_q = (q*DN) @ projT  (fp32 — feeds exp)
        launch_sgemm(NN, NBF, DH,
                     q, INNER, 1, (long)NN * INNER, DH,
                     projT, NBF, 0, 0,
                     qf, NBF, 8LL * NN * NBF, (long)NN * NBF,
                     nullptr, DN, BH, 1);
        favor_post_kernel<<<BH * NN, 256>>>(q, qf, nullptr, 1);

        // dd_k
        launch_sgemm(NN, NBF, DH,
                     k, INNER, 1, (long)NN * INNER, DH,
                     projT, NBF, 0, 0,
                     kf, NBF, 8LL * NN * NBF, (long)NN * NBF,
                     nullptr, DN, BH, 1);
        rowmax_kernel<<<BH * NN / 8, 256>>>(kf, rowmax);
        stab_reduce_kernel<<<BH, 256>>>(rowmax, stab);
        favor_post_kernel<<<BH * NN, 256>>>(k, kf, stab, 0);

        // ksum + ctx
        zero_kernel<<<16, 256>>>(ksum, BH * NBF);
        zero_kernel<<<256, 256>>>(ctx, (long)BH * NBF * DH);
        ksum_kernel<<<dim3(BH, 32), 256>>>(kf, ksum);
        launch_tgemm<64, 32>(NBF, DH, NN,
                             kf, 1, NBF, 8LL * NN * NBF, (long)NN * NBF,
                             v, INNER, (long)NN * INNER, DH,
                             ctx, DH, 8LL * NBF * DH, (long)NBF * DH,
                             nullptr, nullptr, 0, 0, 1.0f, 0, 0, BH, 16);

        // denom + attention output (divide epilogue)
        denom_kernel<<<BH * NN / 8, 256>>>(qf, ksum, denom);
        launch_tgemm<64, 32>(NN, DH, NBF,
                             qf, NBF, 1, 8LL * NN * NBF, (long)NN * NBF,
                             ctx, DH, 8LL * NBF * DH, (long)NBF * DH,
                             o, INNER, (long)NN * INNER, DH,
                             nullptr, denom, 8LL * NN, NN, 1.0f, 0, 3, BH, 1);

        // z += o @ Wo + bo
        launch_tgemm<128, 64>(ROWS, DIM, INNER, o, INNER, 1, 0, 0, wo_l, DIM, 0, 0,
                              z, DIM, 0, 0, bo_l, nullptr, 0, 0, 1.0f, 1, 0, 1, 1);

        // FFN
        ln_kernel<<<ROWS / 8, 256>>>(z, ln2_g + l * DIM, ln2_b + l * DIM, y);
        launch_tgemm<128, 64>(ROWS, FFD, DIM, y, DIM, 1, 0, 0, ffw1_l, FFD, 0, 0,
                              ff, FFD, 0, 0, ffb1_l, nullptr, 0, 0, 1.0f, 0, 2, 1, 1);
        launch_tgemm<128, 64>(ROWS, DIM, FFD, ff, FFD, 1, 0, 0, ffw2_l, DIM, 0, 0,
                              z, DIM, 0, 0, ffb2_l, nullptr, 0, 0, 1.0f, 1, 0, 1, 1);
    }

    // ---- final LN + head ----
    ln_kernel<<<ROWS / 8, 256>>>(z, normf_g, normf_b, y);
    head_kernel<<<ROWS / 8, 256>>>(y, out_w, out_b, out);
}

// round 4
// speedup vs baseline: 27.5668x; 1.3222x over previous
#include <cuda_runtime.h>
#include <math.h>
#include <stdint.h>

// ---------------- problem constants ----------------
#define BSZ    2
#define NN     8192
#define DIM    256
#define HEADS  8
#define DH     64
#define INNER  512
#define NBF    256
#define FFD    1024
#define EEDG   131072
#define ROWS   (BSZ*NN)
#define BH     (BSZ*HEADS)
#define KEPS   1e-4f
#define LNEPS  1e-5f
#define DN     0.3535533905932738f   /* 64^-0.25 */
#define RATIO  0.0625f               /* 256^-0.5 */

// ---------------- scratch ----------------
__device__ float g_z[ROWS*DIM];
__device__ float g_y[ROWS*DIM];
__device__ float g_q[ROWS*INNER];
__device__ float g_k[ROWS*INNER];
__device__ float g_v[ROWS*INNER];
__device__ float g_o[ROWS*INNER];
__device__ float g_ff[(size_t)ROWS*FFD];
__device__ float g_qf[(size_t)BH*NN*NBF];
__device__ float g_kf[(size_t)BH*NN*NBF];
__device__ float g_agg[NN*DIM];
__device__ float g_go[NN*DIM];
__device__ float g_deg[NN];
__device__ float g_dinv[NN];
__device__ float g_rowmax[BH*NN];
__device__ float g_stab[BH];
__device__ float g_ksum[BH*NBF];
__device__ float g_ctx[BH*NBF*DH];
__device__ float g_denom[BH*NN];
__device__ float g_kdiag[BH*NN];
__device__ float g_pT_hi[DH*NBF];
__device__ float g_pT_lo[DH*NBF];

__device__ __forceinline__ float gelu_f(float v) {
    const float c = 0.7978845608028654f;
    float t = tanhf(c * (v + 0.044715f * v * v * v));
    return 0.5f * v * (1.0f + t);
}

__device__ __forceinline__ float cvt_tf32(float x) {
    uint32_t u;
    asm("cvt.rna.tf32.f32 %0, %1;" : "=r"(u) : "f"(x));
    return __uint_as_float(u);
}

__device__ __forceinline__ void mma_tf32(float* c, const uint32_t* a,
                                         uint32_t b0, uint32_t b1) {
    asm volatile(
        "mma.sync.aligned.m16n8k8.row.col.f32.tf32.tf32.f32 "
        "{%0,%1,%2,%3}, {%4,%5,%6,%7}, {%8,%9}, {%0,%1,%2,%3};\n"
        : "+f"(c[0]), "+f"(c[1]), "+f"(c[2]), "+f"(c[3])
        : "r"(a[0]), "r"(a[1]), "r"(a[2]), "r"(a[3]), "r"(b0), "r"(b1));
}

// =====================================================================
// tf32 tensor-core GEMM (residual-stream GEMMs). Block 128 x BN, 4 warps.
// =====================================================================
template<int BN, int WN>
__global__ __launch_bounds__(128)
void tgemm_kernel(int M, int N, int K,
                  const float* __restrict__ A, int a_rs, int a_cs, long a_so, long a_si,
                  const float* __restrict__ B, int b_ks, long b_so, long b_si,
                  float* __restrict__ C, int c_rs, long c_so, long c_si,
                  const float* __restrict__ bias,
                  const float* __restrict__ denom, long d_so, long d_si,
                  float alpha, int beta, int epi, int nsplit)
{
    constexpr int BK = 16;
    constexpr int SA = 136;
    constexpr int SB = BN + 8;
    constexpr int NI = WN / 8;
    constexpr int NBL = BN / 32;
    __shared__ float As[2][BK][SA];
    __shared__ float Bs[2][BK][SB];

    int zz = blockIdx.z;
    int batch = zz / nsplit;
    int split = zz - batch * nsplit;
    long aoff = (long)(batch >> 3) * a_so + (long)(batch & 7) * a_si;
    long boff = (long)(batch >> 3) * b_so + (long)(batch & 7) * b_si;
    long coff = (long)(batch >> 3) * c_so + (long)(batch & 7) * c_si;
    int row0 = blockIdx.y * 128;
    int col0 = blockIdx.x * BN;
    int kchunk = K / nsplit;
    int kbeg = split * kchunk;
    int kend = kbeg + kchunk;

    int tid = threadIdx.x;
    int lane = tid & 31;
    int warp = tid >> 5;
    int m_warp = (warp >> 1) * 64;
    int n_warp = (warp & 1) * WN;

    float c[4][NI][4];
    #pragma unroll
    for (int i = 0; i < 4; i++)
        #pragma unroll
        for (int j = 0; j < NI; j++)
            #pragma unroll
            for (int t = 0; t < 4; t++) c[i][j][t] = 0.0f;

    float4 ra[4];
    float4 rb[NBL];

    auto loadA = [&](int kt) {
        if (a_cs == 1) {
            #pragma unroll
            for (int i = 0; i < 4; i++) {
                int idx = tid + i * 128;
                int m = idx >> 2;
                int kc = (idx & 3) * 4;
                ra[i] = *(const float4*)(A + aoff + (long)(row0 + m) * a_rs + kt + kc);
            }
        } else {
            #pragma unroll
            for (int i = 0; i < 4; i++) {
                int idx = tid + i * 128;
                int m4 = (idx & 31) * 4;
                int kk = idx >> 5;
                ra[i] = *(const float4*)(A + aoff + (long)(kt + kk) * a_cs + row0 + m4);
            }
        }
    };
    auto storeA = [&](int bf) {
        if (a_cs == 1) {
            #pragma unroll
            for (int i = 0; i < 4; i++) {
                int idx = tid + i * 128;
                int m = idx >> 2;
                int kc = (idx & 3) * 4;
                float v[4] = {ra[i].x, ra[i].y, ra[i].z, ra[i].w};
                #pragma unroll
                for (int j0 = 0; j0 < 4; j0++) {
                    int j = (j0 + lane) & 3;
                    As[bf][kc + j][m] = cvt_tf32(v[j]);
                }
            }
        } else {
            #pragma unroll
            for (int i = 0; i < 4; i++) {
                int idx = tid + i * 128;
                int m4 = (idx & 31) * 4;
                int kk = idx >> 5;
                float4 t;
                t.x = cvt_tf32(ra[i].x); t.y = cvt_tf32(ra[i].y);
                t.z = cvt_tf32(ra[i].z); t.w = cvt_tf32(ra[i].w);
                *(float4*)&As[bf][kk][m4] = t;
            }
        }
    };
    auto loadB = [&](int kt) {
        #pragma unroll
        for (int i = 0; i < NBL; i++) {
            int idx = tid + i * 128;
            int n4 = (idx & (BN / 4 - 1)) * 4;
            int kk = idx / (BN / 4);
            rb[i] = *(const float4*)(B + boff + (long)(kt + kk) * b_ks + col0 + n4);
        }
    };
    auto storeB = [&](int bf) {
        #pragma unroll
        for (int i = 0; i < NBL; i++) {
            int idx = tid + i * 128;
            int n4 = (idx & (BN / 4 - 1)) * 4;
            int kk = idx / (BN / 4);
            float4 t;
            t.x = cvt_tf32(rb[i].x); t.y = cvt_tf32(rb[i].y);
            t.z = cvt_tf32(rb[i].z); t.w = cvt_tf32(rb[i].w);
            *(float4*)&Bs[bf][kk][n4] = t;
        }
    };
    auto compute = [&](int bf) {
        #pragma unroll
        for (int s = 0; s < 2; s++) {
            int k8 = s * 8;
            uint32_t af[4][4];
            #pragma unroll
            for (int mi = 0; mi < 4; mi++) {
                int mr = m_warp + mi * 16 + (lane >> 2);
                af[mi][0] = __float_as_uint(As[bf][k8 + (lane & 3)][mr]);
                af[mi][1] = __float_as_uint(As[bf][k8 + (lane & 3)][mr + 8]);
                af[mi][2] = __float_as_uint(As[bf][k8 + 4 + (lane & 3)][mr]);
                af[mi][3] = __float_as_uint(As[bf][k8 + 4 + (lane & 3)][mr + 8]);
            }
            #pragma unroll
            for (int ni = 0; ni < NI; ni++) {
                int nc = n_warp + ni * 8 + (lane >> 2);
                uint32_t b0 = __float_as_uint(Bs[bf][k8 + (lane & 3)][nc]);
                uint32_t b1 = __float_as_uint(Bs[bf][k8 + 4 + (lane & 3)][nc]);
                #pragma unroll
                for (int mi = 0; mi < 4; mi++)
                    mma_tf32(c[mi][ni], af[mi], b0, b1);
            }
        }
    };

    loadA(kbeg); loadB(kbeg);
    storeA(0);   storeB(0);
    __syncthreads();
    int buf = 0;
    for (int kt = kbeg; kt < kend; kt += BK) {
        bool has_next = (kt + BK) < kend;
        if (has_next) { loadA(kt + BK); loadB(kt + BK); }
        compute(buf);
        if (has_next) {
            storeA(buf ^ 1); storeB(buf ^ 1);
            __syncthreads();
            buf ^= 1;
        }
    }

    #pragma unroll
    for (int mi = 0; mi < 4; mi++) {
        int r = row0 + m_warp + mi * 16 + (lane >> 2);
        long crow0 = coff + (long)r * c_rs;
        long crow1 = coff + (long)(r + 8) * c_rs;
        float rdv0 = 1.0f, rdv1 = 1.0f;
        if (epi == 3) {
            long dof = (long)(batch >> 3) * d_so + (long)(batch & 7) * d_si;
            rdv0 = 1.0f / denom[dof + r];
            rdv1 = 1.0f / denom[dof + r + 8];
        }
        #pragma unroll
        for (int ni = 0; ni < NI; ni++) {
            int cc = col0 + n_warp + ni * 8 + 2 * (lane & 3);
            float v0 = alpha * c[mi][ni][0];
            float v1 = alpha * c[mi][ni][1];
            float v2 = alpha * c[mi][ni][2];
            float v3 = alpha * c[mi][ni][3];
            if (nsplit > 1) {
                atomicAdd(C + crow0 + cc,     v0);
                atomicAdd(C + crow0 + cc + 1, v1);
                atomicAdd(C + crow1 + cc,     v2);
                atomicAdd(C + crow1 + cc + 1, v3);
            } else {
                if (bias) {
                    float2 bb = *(const float2*)(bias + cc);
                    v0 += bb.x; v1 += bb.y; v2 += bb.x; v3 += bb.y;
                }
                if (epi == 1) {
                    v0 = fmaxf(v0, 0.f); v1 = fmaxf(v1, 0.f);
                    v2 = fmaxf(v2, 0.f); v3 = fmaxf(v3, 0.f);
                } else if (epi == 2) {
                    v0 = gelu_f(v0); v1 = gelu_f(v1);
                    v2 = gelu_f(v2); v3 = gelu_f(v3);
                } else if (epi == 3) {
                    v0 *= rdv0; v1 *= rdv0; v2 *= rdv1; v3 *= rdv1;
                }
                if (beta) {
                    float2 c0 = *(const float2*)(C + crow0 + cc);
                    float2 c1 = *(const float2*)(C + crow1 + cc);
                    v0 += c0.x; v1 += c0.y; v2 += c1.x; v3 += c1.y;
                }
                *(float2*)(C + crow0 + cc) = make_float2(v0, v1);
                *(float2*)(C + crow1 + cc) = make_float2(v2, v3);
            }
        }
    }
}

// =====================================================================
// Fused FAVOR feature kernel (tf32x3: fp32-accurate dd via tensor cores).
// Block: 256 threads (8 warps as 2m x 4n), tile 64 rows x 256 features, K=64.
// MODE 0 (Q): writes qf = ratio*(exp(dd - diag - rowmax)+keps) and
//             denom[row] = qf . ksum.
// MODE 1 (K): writes raw dd to out, rowmax[row], kdiag[row].
// =====================================================================
template<int MODE>
__global__ __launch_bounds__(256, 2)
void favor_gemm_kernel(const float* __restrict__ qk,
                       const float* __restrict__ pT_hi,
                       const float* __restrict__ pT_lo,
                       float* __restrict__ outf,
                       const float* __restrict__ ksum,
                       float* __restrict__ denom,
                       float* __restrict__ rowmax,
                       float* __restrict__ kdiag)
{
    constexpr int BK = 16;
    __shared__ float As_hi[BK][72], As_lo[BK][72];
    __shared__ float Bs_hi[BK][NBF + 8], Bs_lo[BK][NBF + 8];
    __shared__ float diag_s[64];
    __shared__ float red[4][64];
    __shared__ float rmax_s[64];
    __shared__ float ksum_s[NBF];

    int bh = blockIdx.y;
    int b = bh >> 3, h = bh & 7;
    int row0 = blockIdx.x * 64;
    const float* aptr = qk + ((long)(b * NN) + row0) * INNER + h * DH;

    int tid = threadIdx.x;
    int lane = tid & 31, w = tid >> 5;
    int m_warp = (w >> 2) * 32;
    int n_warp = (w & 3) * 64;

    if (MODE == 0) ksum_s[tid] = ksum[bh * NBF + tid];

    float c[2][8][4];
    #pragma unroll
    for (int mi = 0; mi < 2; mi++)
        #pragma unroll
        for (int ni = 0; ni < 8; ni++)
            #pragma unroll
            for (int t = 0; t < 4; t++) c[mi][ni][t] = 0.0f;

    int am = tid >> 2;
    int akc = (tid & 3) * 4;
    float sq = 0.0f;

    for (int kt = 0; kt < DH; kt += BK) {
        float4 av = *(const float4*)(aptr + (long)am * INNER + kt + akc);
        av.x *= DN; av.y *= DN; av.z *= DN; av.w *= DN;
        sq += av.x * av.x + av.y * av.y + av.z * av.z + av.w * av.w;
        float vv[4] = {av.x, av.y, av.z, av.w};
        #pragma unroll
        for (int j0 = 0; j0 < 4; j0++) {
            int j = (j0 + lane) & 3;
            float hi = cvt_tf32(vv[j]);
            As_hi[akc + j][am] = hi;
            As_lo[akc + j][am] = cvt_tf32(vv[j] - hi);
        }
        #pragma unroll
        for (int t = 0; t < 4; t++) {
            int idx = tid + t * 256;
            int n4 = (idx & 63) * 4;
            int kk = idx >> 6;
            *(float4*)&Bs_hi[kk][n4] = *(const float4*)(pT_hi + (long)(kt + kk) * NBF + n4);
            *(float4*)&Bs_lo[kk][n4] = *(const float4*)(pT_lo + (long)(kt + kk) * NBF + n4);
        }
        __syncthreads();
        #pragma unroll
        for (int s = 0; s < 2; s++) {
            int k8 = s * 8;
            uint32_t ah[2][4], al[2][4];
            #pragma unroll
            for (int mi = 0; mi < 2; mi++) {
                int mr = m_warp + mi * 16 + (lane >> 2);
                ah[mi][0] = __float_as_uint(As_hi[k8 + (lane & 3)][mr]);
                ah[mi][1] = __float_as_uint(As_hi[k8 + (lane & 3)][mr + 8]);
                ah[mi][2] = __float_as_uint(As_hi[k8 + 4 + (lane & 3)][mr]);
                ah[mi][3] = __float_as_uint(As_hi[k8 + 4 + (lane & 3)][mr + 8]);
                al[mi][0] = __float_as_uint(As_lo[k8 + (lane & 3)][mr]);
                al[mi][1] = __float_as_uint(As_lo[k8 + (lane & 3)][mr + 8]);
                al[mi][2] = __float_as_uint(As_lo[k8 + 4 + (lane & 3)][mr]);
                al[mi][3] = __float_as_uint(As_lo[k8 + 4 + (lane & 3)][mr + 8]);
            }
            #pragma unroll
            for (int ni = 0; ni < 8; ni++) {
                int nc = n_warp + ni * 8 + (lane >> 2);
                uint32_t bh0 = __float_as_uint(Bs_hi[k8 + (lane & 3)][nc]);
                uint32_t bh1 = __float_as_uint(Bs_hi[k8 + 4 + (lane & 3)][nc]);
                uint32_t bl0 = __float_as_uint(Bs_lo[k8 + (lane & 3)][nc]);
                uint32_t bl1 = __float_as_uint(Bs_lo[k8 + 4 + (lane & 3)][nc]);
                #pragma unroll
                for (int mi = 0; mi < 2; mi++) {
                    mma_tf32(c[mi][ni], ah[mi], bh0, bh1);
                    mma_tf32(c[mi][ni], ah[mi], bl0, bl1);
                    mma_tf32(c[mi][ni], al[mi], bh0, bh1);
                }
            }
        }
        __syncthreads();
    }

    // diag: reduce sq across the 4 threads sharing row am
    sq += __shfl_xor_sync(0xffffffffu, sq, 1);
    sq += __shfl_xor_sync(0xffffffffu, sq, 2);
    if ((tid & 3) == 0) diag_s[am] = 0.5f * sq;

    // per-row max over this warp's 64 cols
    float mx[2][2];
    #pragma unroll
    for (int mi = 0; mi < 2; mi++) {
        float mlo = -INFINITY, mhi = -INFINITY;
        #pragma unroll
        for (int ni = 0; ni < 8; ni++) {
            mlo = fmaxf(mlo, fmaxf(c[mi][ni][0], c[mi][ni][1]));
            mhi = fmaxf(mhi, fmaxf(c[mi][ni][2], c[mi][ni][3]));
        }
        #pragma unroll
        for (int o = 1; o <= 2; o <<= 1) {
            mlo = fmaxf(mlo, __shfl_xor_sync(0xffffffffu, mlo, o));
            mhi = fmaxf(mhi, __shfl_xor_sync(0xffffffffu, mhi, o));
        }
        mx[mi][0] = mlo; mx[mi][1] = mhi;
    }
    if ((lane & 3) == 0) {
        #pragma unroll
        for (int mi = 0; mi < 2; mi++) {
            int lr = m_warp + mi * 16 + (lane >> 2);
            red[w & 3][lr]     = mx[mi][0];
            red[w & 3][lr + 8] = mx[mi][1];
        }
    }
    __syncthreads();
    if (tid < 64)
        rmax_s[tid] = fmaxf(fmaxf(red[0][tid], red[1][tid]),
                            fmaxf(red[2][tid], red[3][tid]));
    __syncthreads();

    if (MODE == 1) {
        // K pass1: write raw dd + rowmax + diag
        if (tid < 64) {
            rowmax[(long)bh * NN + row0 + tid] = rmax_s[tid];
            kdiag[(long)bh * NN + row0 + tid]  = diag_s[tid];
        }
        #pragma unroll
        for (int mi = 0; mi < 2; mi++) {
            int rl = m_warp + mi * 16 + (lane >> 2);
            long o0 = ((long)bh * NN + row0 + rl) * NBF;
            long o1 = ((long)bh * NN + row0 + rl + 8) * NBF;
            #pragma unroll
            for (int ni = 0; ni < 8; ni++) {
                int nc = n_warp + ni * 8 + 2 * (lane & 3);
                *(float2*)(outf + o0 + nc) = make_float2(c[mi][ni][0], c[mi][ni][1]);
                *(float2*)(outf + o1 + nc) = make_float2(c[mi][ni][2], c[mi][ni][3]);
            }
        }
        return;
    }

    // Q mode: exp + write qf + fused denom
    float ds[2][2] = {{0.f, 0.f}, {0.f, 0.f}};
    #pragma unroll
    for (int mi = 0; mi < 2; mi++) {
        int rl = m_warp + mi * 16 + (lane >> 2);
        float sub0 = diag_s[rl]     + rmax_s[rl];
        float sub1 = diag_s[rl + 8] + rmax_s[rl + 8];
        long o0 = ((long)bh * NN + row0 + rl) * NBF;
        long o1 = ((long)bh * NN + row0 + rl + 8) * NBF;
        #pragma unroll
        for (int ni = 0; ni < 8; ni++) {
            int nc = n_warp + ni * 8 + 2 * (lane & 3);
            float v0 = RATIO * (expf(c[mi][ni][0] - sub0) + KEPS);
            float v1 = RATIO * (expf(c[mi][ni][1] - sub0) + KEPS);
            float v2 = RATIO * (expf(c[mi][ni][2] - sub1) + KEPS);
            float v3 = RATIO * (expf(c[mi][ni][3] - sub1) + KEPS);
            *(float2*)(outf + o0 + nc) = make_float2(v0, v1);
            *(float2*)(outf + o1 + nc) = make_float2(v2, v3);
            ds[mi][0] += v0 * ksum_s[nc] + v1 * ksum_s[nc + 1];
            ds[mi][1] += v2 * ksum_s[nc] + v3 * ksum_s[nc + 1];
        }
    }
    #pragma unroll
    for (int mi = 0; mi < 2; mi++) {
        #pragma unroll
        for (int o = 1; o <= 2; o <<= 1) {
            ds[mi][0] += __shfl_xor_sync(0xffffffffu, ds[mi][0], o);
            ds[mi][1] += __shfl_xor_sync(0xffffffffu, ds[mi][1], o);
        }
    }
    __syncthreads();   // red[] reuse
    if ((lane & 3) == 0) {
        #pragma unroll
        for (int mi = 0; mi < 2; mi++) {
            int lr = m_warp + mi * 16 + (lane >> 2);
            red[w & 3][lr]     = ds[mi][0];
            red[w & 3][lr + 8] = ds[mi][1];
        }
    }
    __syncthreads();
    if (tid < 64)
        denom[(long)bh * NN + row0 + tid] =
            red[0][tid] + red[1][tid] + red[2][tid] + red[3][tid];
}

// exp pass for K + fused ksum accumulation. Block: 256 threads, 64 rows.
__global__ void kexp_kernel(float* __restrict__ kf,
                            const float* __restrict__ kdiag,
                            const float* __restrict__ stab,
                            float* __restrict__ ksum)
{
    long rbase = (long)blockIdx.x * 64;
    int bh = (int)(rbase >> 13);
    float st = stab[bh];
    int col = threadIdx.x;
    float s = 0.0f;
    #pragma unroll 4
    for (int i = 0; i < 64; i++) {
        long r = rbase + i;
        float dd = kf[r * NBF + col];
        float v = RATIO * (expf(dd - kdiag[r] - st) + KEPS);
        kf[r * NBF + col] = v;
        s += v;
    }
    atomicAdd(&ksum[bh * NBF + col], s);
}

// ---------------- elementwise / misc kernels ----------------
__global__ void zero_kernel(float* p, long n) {
    long i = (long)blockIdx.x * blockDim.x + threadIdx.x;
    long stride = (long)gridDim.x * blockDim.x;
    for (; i < n; i += stride) p[i] = 0.0f;
}

__global__ void embed_kernel(const float* __restrict__ x,
                             const float* __restrict__ w1,
                             const float* __restrict__ b1,
                             float* __restrict__ h)
{
    long i = blockIdx.x;
    int j = threadIdx.x;
    float v = x[i] * w1[j] + b1[j];
    h[i * DIM + j] = fmaxf(v, 0.0f);
}

__global__ void deg_kernel(const int* __restrict__ ei,
                           const float* __restrict__ ew,
                           float* __restrict__ deg)
{
    int e = blockIdx.x * blockDim.x + threadIdx.x;
    if (e < EEDG) atomicAdd(&deg[ei[EEDG + e]], ew[e]);
}

__global__ void dinv_kernel(const float* __restrict__ deg, float* __restrict__ dinv)
{
    int i = blockIdx.x * blockDim.x + threadIdx.x;
    if (i < NN) {
        float d = deg[i];
        dinv[i] = (d > 0.0f) ? rsqrtf(fmaxf(d, 1e-12f)) : 0.0f;
    }
}

__global__ void agg_kernel(const int* __restrict__ ei,
                           const float* __restrict__ ew,
                           const float* __restrict__ dinv,
                           const float* __restrict__ emb,
                           float* __restrict__ agg)
{
    int e = blockIdx.x;
    int j = threadIdx.x;
    int r = ei[e];
    int c = ei[EEDG + e];
    float w = dinv[r] * ew[e] * dinv[c];
    atomicAdd(&agg[(long)c * DIM + j], emb[(long)r * DIM + j] * w);
}

__global__ void zadd_kernel(float* __restrict__ z,
                            const float* __restrict__ pos,
                            const float* __restrict__ go)
{
    long i = blockIdx.x;
    int j = threadIdx.x;
    int n = (int)(i & (NN - 1));
    z[i * DIM + j] += pos[(long)n * DIM + j] + go[(long)n * DIM + j];
}

__global__ void ln_kernel(const float* __restrict__ x,
                          const float* __restrict__ g,
                          const float* __restrict__ b,
                          float* __restrict__ y)
{
    int warp = threadIdx.x >> 5, lane = threadIdx.x & 31;
    long row = (long)blockIdx.x * 8 + warp;
    const float4* xr = (const float4*)(x + row * DIM);
    float4 v0 = xr[lane];
    float4 v1 = xr[lane + 32];
    float s  = v0.x + v0.y + v0.z + v0.w + v1.x + v1.y + v1.z + v1.w;
    float s2 = v0.x*v0.x + v0.y*v0.y + v0.z*v0.z + v0.w*v0.w
             + v1.x*v1.x + v1.y*v1.y + v1.z*v1.z + v1.w*v1.w;
    #pragma unroll
    for (int o = 16; o; o >>= 1) {
        s  += __shfl_xor_sync(0xffffffffu, s,  o);
        s2 += __shfl_xor_sync(0xffffffffu, s2, o);
    }
    float mean = s * (1.0f / DIM);
    float var = s2 * (1.0f / DIM) - mean * mean;
    float rstd = rsqrtf(fmaxf(var, 0.0f) + LNEPS);
    const float4* g4 = (const float4*)g;
    const float4* b4 = (const float4*)b;
    float4* yr = (float4*)(y + row * DIM);
    float4 ga = g4[lane], bb = b4[lane];
    float4 o0;
    o0.x = (v0.x - mean) * rstd * ga.x + bb.x;
    o0.y = (v0.y - mean) * rstd * ga.y + bb.y;
    o0.z = (v0.z - mean) * rstd * ga.z + bb.z;
    o0.w = (v0.w - mean) * rstd * ga.w + bb.w;
    yr[lane] = o0;
    ga = g4[lane + 32]; bb = b4[lane + 32];
    float4 o1;
    o1.x = (v1.x - mean) * rstd * ga.x + bb.x;
    o1.y = (v1.y - mean) * rstd * ga.y + bb.y;
    o1.z = (v1.z - mean) * rstd * ga.z + bb.z;
    o1.w = (v1.w - mean) * rstd * ga.w + bb.w;
    yr[lane + 32] = o1;
}

// proj [NBF][DH] -> projT hi/lo [DH][NBF] (tf32 split)
__global__ void transpose_proj_kernel(const float* __restrict__ proj,
                                      float* __restrict__ pT_hi,
                                      float* __restrict__ pT_lo)
{
    int m = blockIdx.x;
    int d = threadIdx.x;
    float v = proj[(long)m * DH + d];
    float hi = cvt_tf32(v);
    pT_hi[(long)d * NBF + m] = hi;
    pT_lo[(long)d * NBF + m] = cvt_tf32(v - hi);
}

__global__ void stab_reduce_kernel(const float* __restrict__ rowmax,
                                   float* __restrict__ stab)
{
    int bh = blockIdx.x;
    int tid = threadIdx.x;
    __shared__ float red[256];
    float m = -INFINITY;
    for (int i = tid; i < NN; i += 256)
        m = fmaxf(m, rowmax[(long)bh * NN + i]);
    red[tid] = m; __syncthreads();
    for (int s = 128; s > 0; s >>= 1) {
        if (tid < s) red[tid] = fmaxf(red[tid], red[tid + s]);
        __syncthreads();
    }
    if (tid == 0) stab[bh] = red[0];
}

__global__ void head_kernel(const float* __restrict__ y,
                            const float* __restrict__ w,
                            const float* __restrict__ bb,
                            float* __restrict__ out)
{
    int warp = threadIdx.x >> 5, lane = threadIdx.x & 31;
    long row = (long)blockIdx.x * 8 + warp;
    const float* yr = y + row * DIM;
    float s = 0.0f;
    #pragma unroll
    for (int i = 0; i < 8; i++) s += yr[lane + i * 32] * w[lane + i * 32];
    #pragma unroll
    for (int o = 16; o; o >>= 1) s += __shfl_xor_sync(0xffffffffu, s, o);
    if (lane == 0) out[row] = s + bb[0];
}

// ---------------- host ----------------
template<int BN, int WN>
static inline void launch_tgemm(int M, int N, int K,
    const float* A, int a_rs, int a_cs, long a_so, long a_si,
    const float* B, int b_ks, long b_so, long b_si,
    float* C, int c_rs, long c_so, long c_si,
    const float* bias, const float* denom, long d_so, long d_si,
    float alpha, int beta, int epi, int nbatch, int nsplit)
{
    dim3 grid(N / BN, M / 128, nbatch * nsplit);
    tgemm_kernel<BN, WN><<<grid, 128>>>(M, N, K, A, a_rs, a_cs, a_so, a_si,
                                        B, b_ks, b_so, b_si, C, c_rs, c_so, c_si,
                                        bias, denom, d_so, d_si, alpha, beta, epi, nsplit);
}

extern "C" void kernel_launch(void* const* d_in, const int* in_sizes, int n_in,
                              void* d_out, int out_size)
{
    const float* x        = (const float*)d_in[0];
    const float* mlp_w1   = (const float*)d_in[1];
    const float* mlp_b1   = (const float*)d_in[2];
    const float* mlp_w2   = (const float*)d_in[3];
    const float* mlp_b2   = (const float*)d_in[4];
    const float* pos      = (const float*)d_in[5];
    const float* gnn_emb  = (const float*)d_in[6];
    const float* gnn_w    = (const float*)d_in[7];
    const float* gnn_b    = (const float*)d_in[8];
    const float* ew       = (const float*)d_in[9];
    const float* proj     = (const float*)d_in[10];
    const float* ln1_g    = (const float*)d_in[11];
    const float* ln1_b    = (const float*)d_in[12];
    const float* wq       = (const float*)d_in[13];
    const float* wk       = (const float*)d_in[14];
    const float* wv       = (const float*)d_in[15];
    const float* wo       = (const float*)d_in[16];
    const float* bo       = (const float*)d_in[17];
    const float* ln2_g    = (const float*)d_in[18];
    const float* ln2_b    = (const float*)d_in[19];
    const float* ffw1     = (const float*)d_in[20];
    const float* ffb1     = (const float*)d_in[21];
    const float* ffw2     = (const float*)d_in[22];
    const float* ffb2     = (const float*)d_in[23];
    const float* normf_g  = (const float*)d_in[24];
    const float* normf_b  = (const float*)d_in[25];
    const float* out_w    = (const float*)d_in[26];
    const float* out_b    = (const float*)d_in[27];
    const int*   ei       = (const int*)d_in[28];
    float* out            = (float*)d_out;

    float *z, *y, *q, *k, *v, *o, *ff, *qf, *kf, *agg, *go, *deg, *dinv;
    float *rowmax, *stab, *ksum, *ctx, *denom, *kdiag, *pT_hi, *pT_lo;
    cudaGetSymbolAddress((void**)&z, g_z);
    cudaGetSymbolAddress((void**)&y, g_y);
    cudaGetSymbolAddress((void**)&q, g_q);
    cudaGetSymbolAddress((void**)&k, g_k);
    cudaGetSymbolAddress((void**)&v, g_v);
    cudaGetSymbolAddress((void**)&o, g_o);
    cudaGetSymbolAddress((void**)&ff, g_ff);
    cudaGetSymbolAddress((void**)&qf, g_qf);
    cudaGetSymbolAddress((void**)&kf, g_kf);
    cudaGetSymbolAddress((void**)&agg, g_agg);
    cudaGetSymbolAddress((void**)&go, g_go);
    cudaGetSymbolAddress((void**)&deg, g_deg);
    cudaGetSymbolAddress((void**)&dinv, g_dinv);
    cudaGetSymbolAddress((void**)&rowmax, g_rowmax);
    cudaGetSymbolAddress((void**)&stab, g_stab);
    cudaGetSymbolAddress((void**)&ksum, g_ksum);
    cudaGetSymbolAddress((void**)&ctx, g_ctx);
    cudaGetSymbolAddress((void**)&denom, g_denom);
    cudaGetSymbolAddress((void**)&kdiag, g_kdiag);
    cudaGetSymbolAddress((void**)&pT_hi, g_pT_hi);
    cudaGetSymbolAddress((void**)&pT_lo, g_pT_lo);

    // ---- GNN prep ----
    zero_kernel<<<64, 256>>>(deg, NN);
    zero_kernel<<<1024, 256>>>(agg, (long)NN * DIM);
    deg_kernel<<<EEDG / 256, 256>>>(ei, ew, deg);
    dinv_kernel<<<NN / 256, 256>>>(deg, dinv);

    // ---- embedding ----
    embed_kernel<<<ROWS, DIM>>>(x, mlp_w1, mlp_b1, y);
    launch_tgemm<128, 64>(ROWS, DIM, DIM, y, DIM, 1, 0, 0, mlp_w2, DIM, 0, 0,
                          z, DIM, 0, 0, mlp_b2, nullptr, 0, 0, 1.0f, 0, 0, 1, 1);

    // ---- GNN aggregate ----
    agg_kernel<<<EEDG, DIM>>>(ei, ew, dinv, gnn_emb, agg);
    launch_tgemm<128, 64>(NN, DIM, DIM, agg, DIM, 1, 0, 0, gnn_w, DIM, 0, 0,
                          go, DIM, 0, 0, gnn_b, nullptr, 0, 0, 1.0f, 0, 0, 1, 1);
    zadd_kernel<<<ROWS, DIM>>>(z, pos, go);

    transpose_proj_kernel<<<NBF, DH>>>(proj, pT_hi, pT_lo);

    // ---- transformer layers ----
    for (int l = 0; l < 2; l++) {
        const float* wq_l   = wq  + (long)l * DIM * INNER;
        const float* wk_l   = wk  + (long)l * DIM * INNER;
        const float* wv_l   = wv  + (long)l * DIM * INNER;
        const float* wo_l   = wo  + (long)l * INNER * DIM;
        const float* bo_l   = bo  + (long)l * DIM;
        const float* ffw1_l = ffw1 + (long)l * DIM * FFD;
        const float* ffb1_l = ffb1 + (long)l * FFD;
        const float* ffw2_l = ffw2 + (long)l * FFD * DIM;
        const float* ffb2_l = ffb2 + (long)l * DIM;

        ln_kernel<<<ROWS / 8, 256>>>(z, ln1_g + l * DIM, ln1_b + l * DIM, y);

        launch_tgemm<128, 64>(ROWS, INNER, DIM, y, DIM, 1, 0, 0, wq_l, INNER, 0, 0,
                              q, INNER, 0, 0, nullptr, nullptr, 0, 0, 1.0f, 0, 0, 1, 1);
        launch_tgemm<128, 64>(ROWS, INNER, DIM, y, DIM, 1, 0, 0, wk_l, INNER, 0, 0,
                              k, INNER, 0, 0, nullptr, nullptr, 0, 0, 1.0f, 0, 0, 1, 1);
        launch_tgemm<128, 64>(ROWS, INNER, DIM, y, DIM, 1, 0, 0, wv_l, INNER, 0, 0,
                              v, INNER, 0, 0, nullptr, nullptr, 0, 0, 1.0f, 0, 0, 1, 1);

        // K path: dd (+rowmax +diag) -> stab -> exp+ksum
        zero_kernel<<<16, 256>>>(ksum, BH * NBF);
        favor_gemm_kernel<1><<<dim3(NN / 64, BH), 256>>>(
            k, pT_hi, pT_lo, kf, nullptr, nullptr, rowmax, kdiag);
        stab_reduce_kernel<<<BH, 256>>>(rowmax, stab);
        kexp_kernel<<<BH * NN / 64, 256>>>(kf, kdiag, stab, ksum);

        // ctx = kf^T @ v (batched, split-K)
        zero_kernel<<<256, 256>>>(ctx, (long)BH * NBF * DH);
        launch_tgemm<64, 32>(NBF, DH, NN,
                             kf, 1, NBF, 8LL * NN * NBF, (long)NN * NBF,
                             v, INNER, (long)NN * INNER, DH,
                             ctx, DH, 8LL * NBF * DH, (long)NBF * DH,
                             nullptr, nullptr, 0, 0, 1.0f, 0, 0, BH, 16);

        // Q path: qf + fused denom (uses finalized ksum)
        favor_gemm_kernel<0><<<dim3(NN / 64, BH), 256>>>(
            q, pT_hi, pT_lo, qf, ksum, denom, nullptr, nullptr);

        // o = (qf @ ctx) / denom
        launch_tgemm<64, 32>(NN, DH, NBF,
                             qf, NBF, 1, 8LL * NN * NBF, (long)NN * NBF,
                             ctx, DH, 8LL * NBF * DH, (long)NBF * DH,
                             o, INNER, (long)NN * INNER, DH,
                             nullptr, denom, 8LL * NN, NN, 1.0f, 0, 3, BH, 1);

        // z += o @ Wo + bo
        launch_tgemm<128, 64>(ROWS, DIM, INNER, o, INNER, 1, 0, 0, wo_l, DIM, 0, 0,
                              z, DIM, 0, 0, bo_l, nullptr, 0, 0, 1.0f, 1, 0, 1, 1);

        // FFN
        ln_kernel<<<ROWS / 8, 256>>>(z, ln2_g + l * DIM, ln2_b + l * DIM, y);
        launch_tgemm<128, 64>(ROWS, FFD, DIM, y, DIM, 1, 0, 0, ffw1_l, FFD, 0, 0,
                              ff, FFD, 0, 0, ffb1_l, nullptr, 0, 0, 1.0f, 0, 2, 1, 1);
        launch_tgemm<128, 64>(ROWS, DIM, FFD, ff, FFD, 1, 0, 0, ffw2_l, DIM, 0, 0,
                              z, DIM, 0, 0, ffb2_l, nullptr, 0, 0, 1.0f, 1, 0, 1, 1);
    }

    // ---- final LN + head ----
    ln_kernel<<<ROWS / 8, 256>>>(z, normf_g, normf_b, y);
    head_kernel<<<ROWS / 8, 256>>>(y, out_w, out_b, out);
}

// round 6
// speedup vs baseline: 28.7354x; 1.0424x over previous
#include <cuda_runtime.h>
#include <math.h>
#include <stdint.h>

// ---------------- problem constants ----------------
#define BSZ    2
#define NN     8192
#define DIM    256
#define HEADS  8
#define DH     64
#define INNER  512
#define NBF    256
#define FFD    1024
#define EEDG   131072
#define ROWS   (BSZ*NN)
#define BH     (BSZ*HEADS)
#define KEPS   1e-4f
#define LNEPS  1e-5f
#define DN     0.3535533905932738f   /* 64^-0.25 */
#define RATIO  0.0625f               /* 256^-0.5 */

// ---------------- scratch ----------------
__device__ float g_z[ROWS*DIM];
__device__ float g_y[ROWS*DIM];
__device__ float g_q[ROWS*INNER];
__device__ float g_k[ROWS*INNER];
__device__ float g_v[ROWS*INNER];
__device__ float g_o[ROWS*INNER];
__device__ float g_ff[(size_t)ROWS*FFD];
__device__ float g_qf[(size_t)BH*NN*NBF];
__device__ float g_kf[(size_t)BH*NN*NBF];
__device__ float g_agg[NN*DIM];
__device__ float g_go[NN*DIM];
__device__ float g_deg[NN];
__device__ float g_dinv[NN];
__device__ float g_rowmax[BH*NN];
__device__ float g_stab[BH];
__device__ float g_ksum[BH*NBF];
__device__ float g_ctx[BH*NBF*DH];
__device__ float g_denom[BH*NN];
__device__ float g_kdiag[BH*NN];
__device__ float g_pT_hi[DH*NBF];
__device__ float g_pT_lo[DH*NBF];

__device__ __forceinline__ float gelu_f(float v) {
    const float c = 0.7978845608028654f;
    float t = tanhf(c * (v + 0.044715f * v * v * v));
    return 0.5f * v * (1.0f + t);
}

__device__ __forceinline__ float cvt_tf32(float x) {
    uint32_t u;
    asm("cvt.rna.tf32.f32 %0, %1;" : "=r"(u) : "f"(x));
    return __uint_as_float(u);
}

__device__ __forceinline__ void mma_tf32(float* c, const uint32_t* a,
                                         uint32_t b0, uint32_t b1) {
    asm volatile(
        "mma.sync.aligned.m16n8k8.row.col.f32.tf32.tf32.f32 "
        "{%0,%1,%2,%3}, {%4,%5,%6,%7}, {%8,%9}, {%0,%1,%2,%3};\n"
        : "+f"(c[0]), "+f"(c[1]), "+f"(c[2]), "+f"(c[3])
        : "r"(a[0]), "r"(a[1]), "r"(a[2]), "r"(a[3]), "r"(b0), "r"(b1));
}

// =====================================================================
// tf32 tensor-core GEMM (residual-stream GEMMs). Block 128 x BN, 4 warps.
// =====================================================================
template<int BN, int WN>
__global__ __launch_bounds__(128)
void tgemm_kernel(int M, int N, int K,
                  const float* __restrict__ A, int a_rs, int a_cs, long a_so, long a_si,
                  const float* __restrict__ B, int b_ks, long b_so, long b_si,
                  float* __restrict__ C, int c_rs, long c_so, long c_si,
                  const float* __restrict__ bias,
                  const float* __restrict__ denom, long d_so, long d_si,
                  float alpha, int beta, int epi, int nsplit)
{
    constexpr int BK = 16;
    constexpr int SA = 136;
    constexpr int SB = BN + 8;
    constexpr int NI = WN / 8;
    constexpr int NBL = BN / 32;
    __shared__ float As[2][BK][SA];
    __shared__ float Bs[2][BK][SB];

    int zz = blockIdx.z;
    int batch = zz / nsplit;
    int split = zz - batch * nsplit;
    long aoff = (long)(batch >> 3) * a_so + (long)(batch & 7) * a_si;
    long boff = (long)(batch >> 3) * b_so + (long)(batch & 7) * b_si;
    long coff = (long)(batch >> 3) * c_so + (long)(batch & 7) * c_si;
    int row0 = blockIdx.y * 128;
    int col0 = blockIdx.x * BN;
    int kchunk = K / nsplit;
    int kbeg = split * kchunk;
    int kend = kbeg + kchunk;

    int tid = threadIdx.x;
    int lane = tid & 31;
    int warp = tid >> 5;
    int m_warp = (warp >> 1) * 64;
    int n_warp = (warp & 1) * WN;

    float c[4][NI][4];
    #pragma unroll
    for (int i = 0; i < 4; i++)
        #pragma unroll
        for (int j = 0; j < NI; j++)
            #pragma unroll
            for (int t = 0; t < 4; t++) c[i][j][t] = 0.0f;

    float4 ra[4];
    float4 rb[NBL];

    auto loadA = [&](int kt) {
        if (a_cs == 1) {
            #pragma unroll
            for (int i = 0; i < 4; i++) {
                int idx = tid + i * 128;
                int m = idx >> 2;
                int kc = (idx & 3) * 4;
                ra[i] = *(const float4*)(A + aoff + (long)(row0 + m) * a_rs + kt + kc);
            }
        } else {
            #pragma unroll
            for (int i = 0; i < 4; i++) {
                int idx = tid + i * 128;
                int m4 = (idx & 31) * 4;
                int kk = idx >> 5;
                ra[i] = *(const float4*)(A + aoff + (long)(kt + kk) * a_cs + row0 + m4);
            }
        }
    };
    auto storeA = [&](int bf) {
        if (a_cs == 1) {
            #pragma unroll
            for (int i = 0; i < 4; i++) {
                int idx = tid + i * 128;
                int m = idx >> 2;
                int kc = (idx & 3) * 4;
                float v[4] = {ra[i].x, ra[i].y, ra[i].z, ra[i].w};
                #pragma unroll
                for (int j0 = 0; j0 < 4; j0++) {
                    int j = (j0 + lane) & 3;
                    As[bf][kc + j][m] = cvt_tf32(v[j]);
                }
            }
        } else {
            #pragma unroll
            for (int i = 0; i < 4; i++) {
                int idx = tid + i * 128;
                int m4 = (idx & 31) * 4;
                int kk = idx >> 5;
                float4 t;
                t.x = cvt_tf32(ra[i].x); t.y = cvt_tf32(ra[i].y);
                t.z = cvt_tf32(ra[i].z); t.w = cvt_tf32(ra[i].w);
                *(float4*)&As[bf][kk][m4] = t;
            }
        }
    };
    auto loadB = [&](int kt) {
        #pragma unroll
        for (int i = 0; i < NBL; i++) {
            int idx = tid + i * 128;
            int n4 = (idx & (BN / 4 - 1)) * 4;
            int kk = idx / (BN / 4);
            rb[i] = *(const float4*)(B + boff + (long)(kt + kk) * b_ks + col0 + n4);
        }
    };
    auto storeB = [&](int bf) {
        #pragma unroll
        for (int i = 0; i < NBL; i++) {
            int idx = tid + i * 128;
            int n4 = (idx & (BN / 4 - 1)) * 4;
            int kk = idx / (BN / 4);
            float4 t;
            t.x = cvt_tf32(rb[i].x); t.y = cvt_tf32(rb[i].y);
            t.z = cvt_tf32(rb[i].z); t.w = cvt_tf32(rb[i].w);
            *(float4*)&Bs[bf][kk][n4] = t;
        }
    };
    auto compute = [&](int bf) {
        #pragma unroll
        for (int s = 0; s < 2; s++) {
            int k8 = s * 8;
            uint32_t af[4][4];
            #pragma unroll
            for (int mi = 0; mi < 4; mi++) {
                int mr = m_warp + mi * 16 + (lane >> 2);
                af[mi][0] = __float_as_uint(As[bf][k8 + (lane & 3)][mr]);
                af[mi][1] = __float_as_uint(As[bf][k8 + (lane & 3)][mr + 8]);
                af[mi][2] = __float_as_uint(As[bf][k8 + 4 + (lane & 3)][mr]);
                af[mi][3] = __float_as_uint(As[bf][k8 + 4 + (lane & 3)][mr + 8]);
            }
            #pragma unroll
            for (int ni = 0; ni < NI; ni++) {
                int nc = n_warp + ni * 8 + (lane >> 2);
                uint32_t b0 = __float_as_uint(Bs[bf][k8 + (lane & 3)][nc]);
                uint32_t b1 = __float_as_uint(Bs[bf][k8 + 4 + (lane & 3)][nc]);
                #pragma unroll
                for (int mi = 0; mi < 4; mi++)
                    mma_tf32(c[mi][ni], af[mi], b0, b1);
            }
        }
    };

    loadA(kbeg); loadB(kbeg);
    storeA(0);   storeB(0);
    __syncthreads();
    int buf = 0;
    for (int kt = kbeg; kt < kend; kt += BK) {
        bool has_next = (kt + BK) < kend;
        if (has_next) { loadA(kt + BK); loadB(kt + BK); }
        compute(buf);
        if (has_next) {
            storeA(buf ^ 1); storeB(buf ^ 1);
            __syncthreads();
            buf ^= 1;
        }
    }

    #pragma unroll
    for (int mi = 0; mi < 4; mi++) {
        int r = row0 + m_warp + mi * 16 + (lane >> 2);
        long crow0 = coff + (long)r * c_rs;
        long crow1 = coff + (long)(r + 8) * c_rs;
        float rdv0 = 1.0f, rdv1 = 1.0f;
        if (epi == 3) {
            long dof = (long)(batch >> 3) * d_so + (long)(batch & 7) * d_si;
            rdv0 = 1.0f / denom[dof + r];
            rdv1 = 1.0f / denom[dof + r + 8];
        }
        #pragma unroll
        for (int ni = 0; ni < NI; ni++) {
            int cc = col0 + n_warp + ni * 8 + 2 * (lane & 3);
            float v0 = alpha * c[mi][ni][0];
            float v1 = alpha * c[mi][ni][1];
            float v2 = alpha * c[mi][ni][2];
            float v3 = alpha * c[mi][ni][3];
            if (nsplit > 1) {
                atomicAdd(C + crow0 + cc,     v0);
                atomicAdd(C + crow0 + cc + 1, v1);
                atomicAdd(C + crow1 + cc,     v2);
                atomicAdd(C + crow1 + cc + 1, v3);
            } else {
                if (bias) {
                    float2 bb = *(const float2*)(bias + cc);
                    v0 += bb.x; v1 += bb.y; v2 += bb.x; v3 += bb.y;
                }
                if (epi == 1) {
                    v0 = fmaxf(v0, 0.f); v1 = fmaxf(v1, 0.f);
                    v2 = fmaxf(v2, 0.f); v3 = fmaxf(v3, 0.f);
                } else if (epi == 2) {
                    v0 = gelu_f(v0); v1 = gelu_f(v1);
                    v2 = gelu_f(v2); v3 = gelu_f(v3);
                } else if (epi == 3) {
                    v0 *= rdv0; v1 *= rdv0; v2 *= rdv1; v3 *= rdv1;
                }
                if (beta) {
                    float2 c0 = *(const float2*)(C + crow0 + cc);
                    float2 c1 = *(const float2*)(C + crow1 + cc);
                    v0 += c0.x; v1 += c0.y; v2 += c1.x; v3 += c1.y;
                }
                *(float2*)(C + crow0 + cc) = make_float2(v0, v1);
                *(float2*)(C + crow1 + cc) = make_float2(v2, v3);
            }
        }
    }
}

// =====================================================================
// Fused FAVOR feature kernel (tf32x3). See R4 notes.
// =====================================================================
template<int MODE>
__global__ __launch_bounds__(256, 2)
void favor_gemm_kernel(const float* __restrict__ qk,
                       const float* __restrict__ pT_hi,
                       const float* __restrict__ pT_lo,
                       float* __restrict__ outf,
                       const float* __restrict__ ksum,
                       float* __restrict__ denom,
                       float* __restrict__ rowmax,
                       float* __restrict__ kdiag)
{
    constexpr int BK = 16;
    __shared__ float As_hi[BK][72], As_lo[BK][72];
    __shared__ float Bs_hi[BK][NBF + 8], Bs_lo[BK][NBF + 8];
    __shared__ float diag_s[64];
    __shared__ float red[4][64];
    __shared__ float rmax_s[64];
    __shared__ float ksum_s[NBF];

    int bh = blockIdx.y;
    int b = bh >> 3, h = bh & 7;
    int row0 = blockIdx.x * 64;
    const float* aptr = qk + ((long)(b * NN) + row0) * INNER + h * DH;

    int tid = threadIdx.x;
    int lane = tid & 31, w = tid >> 5;
    int m_warp = (w >> 2) * 32;
    int n_warp = (w & 3) * 64;

    if (MODE == 0) ksum_s[tid] = ksum[bh * NBF + tid];

    float c[2][8][4];
    #pragma unroll
    for (int mi = 0; mi < 2; mi++)
        #pragma unroll
        for (int ni = 0; ni < 8; ni++)
            #pragma unroll
            for (int t = 0; t < 4; t++) c[mi][ni][t] = 0.0f;

    int am = tid >> 2;
    int akc = (tid & 3) * 4;
    float sq = 0.0f;

    for (int kt = 0; kt < DH; kt += BK) {
        float4 av = *(const float4*)(aptr + (long)am * INNER + kt + akc);
        av.x *= DN; av.y *= DN; av.z *= DN; av.w *= DN;
        sq += av.x * av.x + av.y * av.y + av.z * av.z + av.w * av.w;
        float vv[4] = {av.x, av.y, av.z, av.w};
        #pragma unroll
        for (int j0 = 0; j0 < 4; j0++) {
            int j = (j0 + lane) & 3;
            float hi = cvt_tf32(vv[j]);
            As_hi[akc + j][am] = hi;
            As_lo[akc + j][am] = cvt_tf32(vv[j] - hi);
        }
        #pragma unroll
        for (int t = 0; t < 4; t++) {
            int idx = tid + t * 256;
            int n4 = (idx & 63) * 4;
            int kk = idx >> 6;
            *(float4*)&Bs_hi[kk][n4] = *(const float4*)(pT_hi + (long)(kt + kk) * NBF + n4);
            *(float4*)&Bs_lo[kk][n4] = *(const float4*)(pT_lo + (long)(kt + kk) * NBF + n4);
        }
        __syncthreads();
        #pragma unroll
        for (int s = 0; s < 2; s++) {
            int k8 = s * 8;
            uint32_t ah[2][4], al[2][4];
            #pragma unroll
            for (int mi = 0; mi < 2; mi++) {
                int mr = m_warp + mi * 16 + (lane >> 2);
                ah[mi][0] = __float_as_uint(As_hi[k8 + (lane & 3)][mr]);
                ah[mi][1] = __float_as_uint(As_hi[k8 + (lane & 3)][mr + 8]);
                ah[mi][2] = __float_as_uint(As_hi[k8 + 4 + (lane & 3)][mr]);
                ah[mi][3] = __float_as_uint(As_hi[k8 + 4 + (lane & 3)][mr + 8]);
                al[mi][0] = __float_as_uint(As_lo[k8 + (lane & 3)][mr]);
                al[mi][1] = __float_as_uint(As_lo[k8 + (lane & 3)][mr + 8]);
                al[mi][2] = __float_as_uint(As_lo[k8 + 4 + (lane & 3)][mr]);
                al[mi][3] = __float_as_uint(As_lo[k8 + 4 + (lane & 3)][mr + 8]);
            }
            #pragma unroll
            for (int ni = 0; ni < 8; ni++) {
                int nc = n_warp + ni * 8 + (lane >> 2);
                uint32_t bh0 = __float_as_uint(Bs_hi[k8 + (lane & 3)][nc]);
                uint32_t bh1 = __float_as_uint(Bs_hi[k8 + 4 + (lane & 3)][nc]);
                uint32_t bl0 = __float_as_uint(Bs_lo[k8 + (lane & 3)][nc]);
                uint32_t bl1 = __float_as_uint(Bs_lo[k8 + 4 + (lane & 3)][nc]);
                #pragma unroll
                for (int mi = 0; mi < 2; mi++) {
                    mma_tf32(c[mi][ni], ah[mi], bh0, bh1);
                    mma_tf32(c[mi][ni], ah[mi], bl0, bl1);
                    mma_tf32(c[mi][ni], al[mi], bh0, bh1);
                }
            }
        }
        __syncthreads();
    }

    sq += __shfl_xor_sync(0xffffffffu, sq, 1);
    sq += __shfl_xor_sync(0xffffffffu, sq, 2);
    if ((tid & 3) == 0) diag_s[am] = 0.5f * sq;

    float mx[2][2];
    #pragma unroll
    for (int mi = 0; mi < 2; mi++) {
        float mlo = -INFINITY, mhi = -INFINITY;
        #pragma unroll
        for (int ni = 0; ni < 8; ni++) {
            mlo = fmaxf(mlo, fmaxf(c[mi][ni][0], c[mi][ni][1]));
            mhi = fmaxf(mhi, fmaxf(c[mi][ni][2], c[mi][ni][3]));
        }
        #pragma unroll
        for (int o = 1; o <= 2; o <<= 1) {
            mlo = fmaxf(mlo, __shfl_xor_sync(0xffffffffu, mlo, o));
            mhi = fmaxf(mhi, __shfl_xor_sync(0xffffffffu, mhi, o));
        }
        mx[mi][0] = mlo; mx[mi][1] = mhi;
    }
    if ((lane & 3) == 0) {
        #pragma unroll
        for (int mi = 0; mi < 2; mi++) {
            int lr = m_warp + mi * 16 + (lane >> 2);
            red[w & 3][lr]     = mx[mi][0];
            red[w & 3][lr + 8] = mx[mi][1];
        }
    }
    __syncthreads();
    if (tid < 64)
        rmax_s[tid] = fmaxf(fmaxf(red[0][tid], red[1][tid]),
                            fmaxf(red[2][tid], red[3][tid]));
    __syncthreads();

    if (MODE == 1) {
        if (tid < 64) {
            rowmax[(long)bh * NN + row0 + tid] = rmax_s[tid];
            kdiag[(long)bh * NN + row0 + tid]  = diag_s[tid];
        }
        #pragma unroll
        for (int mi = 0; mi < 2; mi++) {
            int rl = m_warp + mi * 16 + (lane >> 2);
            long o0 = ((long)bh * NN + row0 + rl) * NBF;
            long o1 = ((long)bh * NN + row0 + rl + 8) * NBF;
            #pragma unroll
            for (int ni = 0; ni < 8; ni++) {
                int nc = n_warp + ni * 8 + 2 * (lane & 3);
                *(float2*)(outf + o0 + nc) = make_float2(c[mi][ni][0], c[mi][ni][1]);
                *(float2*)(outf + o1 + nc) = make_float2(c[mi][ni][2], c[mi][ni][3]);
            }
        }
        return;
    }

    float ds[2][2] = {{0.f, 0.f}, {0.f, 0.f}};
    #pragma unroll
    for (int mi = 0; mi < 2; mi++) {
        int rl = m_warp + mi * 16 + (lane >> 2);
        float sub0 = diag_s[rl]     + rmax_s[rl];
        float sub1 = diag_s[rl + 8] + rmax_s[rl + 8];
        long o0 = ((long)bh * NN + row0 + rl) * NBF;
        long o1 = ((long)bh * NN + row0 + rl + 8) * NBF;
        #pragma unroll
        for (int ni = 0; ni < 8; ni++) {
            int nc = n_warp + ni * 8 + 2 * (lane & 3);
            float v0 = RATIO * (expf(c[mi][ni][0] - sub0) + KEPS);
            float v1 = RATIO * (expf(c[mi][ni][1] - sub0) + KEPS);
            float v2 = RATIO * (expf(c[mi][ni][2] - sub1) + KEPS);
            float v3 = RATIO * (expf(c[mi][ni][3] - sub1) + KEPS);
            *(float2*)(outf + o0 + nc) = make_float2(v0, v1);
            *(float2*)(outf + o1 + nc) = make_float2(v2, v3);
            ds[mi][0] += v0 * ksum_s[nc] + v1 * ksum_s[nc + 1];
            ds[mi][1] += v2 * ksum_s[nc] + v3 * ksum_s[nc + 1];
        }
    }
    #pragma unroll
    for (int mi = 0; mi < 2; mi++) {
        #pragma unroll
        for (int o = 1; o <= 2; o <<= 1) {
            ds[mi][0] += __shfl_xor_sync(0xffffffffu, ds[mi][0], o);
            ds[mi][1] += __shfl_xor_sync(0xffffffffu, ds[mi][1], o);
        }
    }
    __syncthreads();
    if ((lane & 3) == 0) {
        #pragma unroll
        for (int mi = 0; mi < 2; mi++) {
            int lr = m_warp + mi * 16 + (lane >> 2);
            red[w & 3][lr]     = ds[mi][0];
            red[w & 3][lr + 8] = ds[mi][1];
        }
    }
    __syncthreads();
    if (tid < 64)
        denom[(long)bh * NN + row0 + tid] =
            red[0][tid] + red[1][tid] + red[2][tid] + red[3][tid];
}

__global__ void kexp_kernel(float* __restrict__ kf,
                            const float* __restrict__ kdiag,
                            const float* __restrict__ stab,
                            float* __restrict__ ksum)
{
    long rbase = (long)blockIdx.x * 64;
    int bh = (int)(rbase >> 13);
    float st = stab[bh];
    int col = threadIdx.x;
    float s = 0.0f;
    #pragma unroll 4
    for (int i = 0; i < 64; i++) {
        long r = rbase + i;
        float dd = kf[r * NBF + col];
        float v = RATIO * (expf(dd - kdiag[r] - st) + KEPS);
        kf[r * NBF + col] = v;
        s += v;
    }
    atomicAdd(&ksum[bh * NBF + col], s);
}

// ---------------- elementwise / misc kernels ----------------
__global__ void zero_kernel(float* p, long n) {
    long i = (long)blockIdx.x * blockDim.x + threadIdx.x;
    long stride = (long)gridDim.x * blockDim.x;
    for (; i < n; i += stride) p[i] = 0.0f;
}

__global__ void embed_kernel(const float* __restrict__ x,
                             const float* __restrict__ w1,
                             const float* __restrict__ b1,
                             float* __restrict__ h)
{
    long i = blockIdx.x;
    int j = threadIdx.x;
    float v = x[i] * w1[j] + b1[j];
    h[i * DIM + j] = fmaxf(v, 0.0f);
}

__global__ void deg_kernel(const int* __restrict__ ei,
                           const float* __restrict__ ew,
                           float* __restrict__ deg)
{
    int e = blockIdx.x * blockDim.x + threadIdx.x;
    if (e < EEDG) atomicAdd(&deg[ei[EEDG + e]], ew[e]);
}

__global__ void dinv_kernel(const float* __restrict__ deg, float* __restrict__ dinv)
{
    int i = blockIdx.x * blockDim.x + threadIdx.x;
    if (i < NN) {
        float d = deg[i];
        dinv[i] = (d > 0.0f) ? rsqrtf(fmaxf(d, 1e-12f)) : 0.0f;
    }
}

__global__ void agg_kernel(const int* __restrict__ ei,
                           const float* __restrict__ ew,
                           const float* __restrict__ dinv,
                           const float* __restrict__ emb,
                           float* __restrict__ agg)
{
    int e = blockIdx.x;
    int j = threadIdx.x;
    int r = ei[e];
    int c = ei[EEDG + e];
    float w = dinv[r] * ew[e] * dinv[c];
    atomicAdd(&agg[(long)c * DIM + j], emb[(long)r * DIM + j] * w);
}

__global__ void zadd_kernel(float* __restrict__ z,
                            const float* __restrict__ pos,
                            const float* __restrict__ go)
{
    long i = blockIdx.x;
    int j = threadIdx.x;
    int n = (int)(i & (NN - 1));
    z[i * DIM + j] += pos[(long)n * DIM + j] + go[(long)n * DIM + j];
}

__global__ void ln_kernel(const float* __restrict__ x,
                          const float* __restrict__ g,
                          const float* __restrict__ b,
                          float* __restrict__ y)
{
    int warp = threadIdx.x >> 5, lane = threadIdx.x & 31;
    long row = (long)blockIdx.x * 8 + warp;
    const float4* xr = (const float4*)(x + row * DIM);
    float4 v0 = xr[lane];
    float4 v1 = xr[lane + 32];
    float s  = v0.x + v0.y + v0.z + v0.w + v1.x + v1.y + v1.z + v1.w;
    float s2 = v0.x*v0.x + v0.y*v0.y + v0.z*v0.z + v0.w*v0.w
             + v1.x*v1.x + v1.y*v1.y + v1.z*v1.z + v1.w*v1.w;
    #pragma unroll
    for (int o = 16; o; o >>= 1) {
        s  += __shfl_xor_sync(0xffffffffu, s,  o);
        s2 += __shfl_xor_sync(0xffffffffu, s2, o);
    }
    float mean = s * (1.0f / DIM);
    float var = s2 * (1.0f / DIM) - mean * mean;
    float rstd = rsqrtf(fmaxf(var, 0.0f) + LNEPS);
    const float4* g4 = (const float4*)g;
    const float4* b4 = (const float4*)b;
    float4* yr = (float4*)(y + row * DIM);
    float4 ga = g4[lane], bb = b4[lane];
    float4 o0;
    o0.x = (v0.x - mean) * rstd * ga.x + bb.x;
    o0.y = (v0.y - mean) * rstd * ga.y + bb.y;
    o0.z = (v0.z - mean) * rstd * ga.z + bb.z;
    o0.w = (v0.w - mean) * rstd * ga.w + bb.w;
    yr[lane] = o0;
    ga = g4[lane + 32]; bb = b4[lane + 32];
    float4 o1;
    o1.x = (v1.x - mean) * rstd * ga.x + bb.x;
    o1.y = (v1.y - mean) * rstd * ga.y + bb.y;
    o1.z = (v1.z - mean) * rstd * ga.z + bb.z;
    o1.w = (v1.w - mean) * rstd * ga.w + bb.w;
    yr[lane + 32] = o1;
}

__global__ void transpose_proj_kernel(const float* __restrict__ proj,
                                      float* __restrict__ pT_hi,
                                      float* __restrict__ pT_lo)
{
    int m = blockIdx.x;
    int d = threadIdx.x;
    float v = proj[(long)m * DH + d];
    float hi = cvt_tf32(v);
    pT_hi[(long)d * NBF + m] = hi;
    pT_lo[(long)d * NBF + m] = cvt_tf32(v - hi);
}

__global__ void stab_reduce_kernel(const float* __restrict__ rowmax,
                                   float* __restrict__ stab)
{
    int bh = blockIdx.x;
    int tid = threadIdx.x;
    __shared__ float red[256];
    float m = -INFINITY;
    for (int i = tid; i < NN; i += 256)
        m = fmaxf(m, rowmax[(long)bh * NN + i]);
    red[tid] = m; __syncthreads();
    for (int s = 128; s > 0; s >>= 1) {
        if (tid < s) red[tid] = fmaxf(red[tid], red[tid + s]);
        __syncthreads();
    }
    if (tid == 0) stab[bh] = red[0];
}

__global__ void head_kernel(const float* __restrict__ y,
                            const float* __restrict__ w,
                            const float* __restrict__ bb,
                            float* __restrict__ out)
{
    int warp = threadIdx.x >> 5, lane = threadIdx.x & 31;
    long row = (long)blockIdx.x * 8 + warp;
    const float* yr = y + row * DIM;
    float s = 0.0f;
    #pragma unroll
    for (int i = 0; i < 8; i++) s += yr[lane + i * 32] * w[lane + i * 32];
    #pragma unroll
    for (int o = 16; o; o >>= 1) s += __shfl_xor_sync(0xffffffffu, s, o);
    if (lane == 0) out[row] = s + bb[0];
}

// ---------------- host ----------------
template<int BN, int WN>
static inline void launch_tgemm(cudaStream_t st, int M, int N, int K,
    const float* A, int a_rs, int a_cs, long a_so, long a_si,
    const float* B, int b_ks, long b_so, long b_si,
    float* C, int c_rs, long c_so, long c_si,
    const float* bias, const float* denom, long d_so, long d_si,
    float alpha, int beta, int epi, int nbatch, int nsplit)
{
    dim3 grid(N / BN, M / 128, nbatch * nsplit);
    tgemm_kernel<BN, WN><<<grid, 128, 0, st>>>(M, N, K, A, a_rs, a_cs, a_so, a_si,
                                        B, b_ks, b_so, b_si, C, c_rs, c_so, c_si,
                                        bias, denom, d_so, d_si, alpha, beta, epi, nsplit);
}

extern "C" void kernel_launch(void* const* d_in, const int* in_sizes, int n_in,
                              void* d_out, int out_size)
{
    const float* x        = (const float*)d_in[0];
    const float* mlp_w1   = (const float*)d_in[1];
    const float* mlp_b1   = (const float*)d_in[2];
    const float* mlp_w2   = (const float*)d_in[3];
    const float* mlp_b2   = (const float*)d_in[4];
    const float* pos      = (const float*)d_in[5];
    const float* gnn_emb  = (const float*)d_in[6];
    const float* gnn_w    = (const float*)d_in[7];
    const float* gnn_b    = (const float*)d_in[8];
    const float* ew       = (const float*)d_in[9];
    const float* proj     = (const float*)d_in[10];
    const float* ln1_g    = (const float*)d_in[11];
    const float* ln1_b    = (const float*)d_in[12];
    const float* wq       = (const float*)d_in[13];
    const float* wk       = (const float*)d_in[14];
    const float* wv       = (const float*)d_in[15];
    const float* wo       = (const float*)d_in[16];
    const float* bo       = (const float*)d_in[17];
    const float* ln2_g    = (const float*)d_in[18];
    const float* ln2_b    = (const float*)d_in[19];
    const float* ffw1     = (const float*)d_in[20];
    const float* ffb1     = (const float*)d_in[21];
    const float* ffw2     = (const float*)d_in[22];
    const float* ffb2     = (const float*)d_in[23];
    const float* normf_g  = (const float*)d_in[24];
    const float* normf_b  = (const float*)d_in[25];
    const float* out_w    = (const float*)d_in[26];
    const float* out_b    = (const float*)d_in[27];
    const int*   ei       = (const int*)d_in[28];
    float* out            = (float*)d_out;

    float *z, *y, *q, *k, *v, *o, *ff, *qf, *kf, *agg, *go, *deg, *dinv;
    float *rowmax, *stab, *ksum, *ctx, *denom, *kdiag, *pT_hi, *pT_lo;
    cudaGetSymbolAddress((void**)&z, g_z);
    cudaGetSymbolAddress((void**)&y, g_y);
    cudaGetSymbolAddress((void**)&q, g_q);
    cudaGetSymbolAddress((void**)&k, g_k);
    cudaGetSymbolAddress((void**)&v, g_v);
    cudaGetSymbolAddress((void**)&o, g_o);
    cudaGetSymbolAddress((void**)&ff, g_ff);
    cudaGetSymbolAddress((void**)&qf, g_qf);
    cudaGetSymbolAddress((void**)&kf, g_kf);
    cudaGetSymbolAddress((void**)&agg, g_agg);
    cudaGetSymbolAddress((void**)&go, g_go);
    cudaGetSymbolAddress((void**)&deg, g_deg);
    cudaGetSymbolAddress((void**)&dinv, g_dinv);
    cudaGetSymbolAddress((void**)&rowmax, g_rowmax);
    cudaGetSymbolAddress((void**)&stab, g_stab);
    cudaGetSymbolAddress((void**)&ksum, g_ksum);
    cudaGetSymbolAddress((void**)&ctx, g_ctx);
    cudaGetSymbolAddress((void**)&denom, g_denom);
    cudaGetSymbolAddress((void**)&kdiag, g_kdiag);
    cudaGetSymbolAddress((void**)&pT_hi, g_pT_hi);
    cudaGetSymbolAddress((void**)&pT_lo, g_pT_lo);

    // ---- streams & events: created ONCE (first call = correctness run,
    // before the harness's pre-capture memory baseline) and reused on every
    // subsequent call, so no allocation happens during/after capture. ----
    static cudaStream_t sA = nullptr, sB = nullptr;
    static cudaEvent_t evs[32];
    if (sA == nullptr) {
        cudaStreamCreateWithFlags(&sA, cudaStreamNonBlocking);
        cudaStreamCreateWithFlags(&sB, cudaStreamNonBlocking);
        for (int i = 0; i < 32; i++)
            cudaEventCreateWithFlags(&evs[i], cudaEventDisableTiming);
    }
    cudaStream_t s0 = cudaStreamPerThread;
    int ne = 0;
    auto fork_to = [&](cudaStream_t dst) {           // s0 -> dst
        cudaEventRecord(evs[ne], s0);
        cudaStreamWaitEvent(dst, evs[ne], 0);
        ne++;
    };
    auto join_from = [&](cudaStream_t src) {         // src -> s0
        cudaEventRecord(evs[ne], src);
        cudaStreamWaitEvent(s0, evs[ne], 0);
        ne++;
    };

    // ---- prologue: GNN chain on s0 ; embed chain on sB ; proj on sA ----
    fork_to(sA);
    fork_to(sB);
    transpose_proj_kernel<<<NBF, DH, 0, sA>>>(proj, pT_hi, pT_lo);

    embed_kernel<<<ROWS, DIM, 0, sB>>>(x, mlp_w1, mlp_b1, y);
    launch_tgemm<128, 64>(sB, ROWS, DIM, DIM, y, DIM, 1, 0, 0, mlp_w2, DIM, 0, 0,
                          z, DIM, 0, 0, mlp_b2, nullptr, 0, 0, 1.0f, 0, 0, 1, 1);

    zero_kernel<<<64, 256, 0, s0>>>(deg, NN);
    zero_kernel<<<1024, 256, 0, s0>>>(agg, (long)NN * DIM);
    deg_kernel<<<EEDG / 256, 256, 0, s0>>>(ei, ew, deg);
    dinv_kernel<<<NN / 256, 256, 0, s0>>>(deg, dinv);
    agg_kernel<<<EEDG, DIM, 0, s0>>>(ei, ew, dinv, gnn_emb, agg);
    launch_tgemm<128, 64>(s0, NN, DIM, DIM, agg, DIM, 1, 0, 0, gnn_w, DIM, 0, 0,
                          go, DIM, 0, 0, gnn_b, nullptr, 0, 0, 1.0f, 0, 0, 1, 1);
    join_from(sB);   // z ready
    join_from(sA);   // pT ready
    zadd_kernel<<<ROWS, DIM, 0, s0>>>(z, pos, go);

    // ---- transformer layers ----
    for (int l = 0; l < 2; l++) {
        const float* wq_l   = wq  + (long)l * DIM * INNER;
        const float* wk_l   = wk  + (long)l * DIM * INNER;
        const float* wv_l   = wv  + (long)l * DIM * INNER;
        const float* wo_l   = wo  + (long)l * INNER * DIM;
        const float* bo_l   = bo  + (long)l * DIM;
        const float* ffw1_l = ffw1 + (long)l * DIM * FFD;
        const float* ffb1_l = ffb1 + (long)l * FFD;
        const float* ffw2_l = ffw2 + (long)l * FFD * DIM;
        const float* ffb2_l = ffb2 + (long)l * DIM;

        ln_kernel<<<ROWS / 8, 256, 0, s0>>>(z, ln1_g + l * DIM, ln1_b + l * DIM, y);

        // fork: q on sA, v on sB, k stays on s0 (critical path)
        fork_to(sA);
        fork_to(sB);
        launch_tgemm<128, 64>(sA, ROWS, INNER, DIM, y, DIM, 1, 0, 0, wq_l, INNER, 0, 0,
                              q, INNER, 0, 0, nullptr, nullptr, 0, 0, 1.0f, 0, 0, 1, 1);
        launch_tgemm<128, 64>(sB, ROWS, INNER, DIM, y, DIM, 1, 0, 0, wv_l, INNER, 0, 0,
                              v, INNER, 0, 0, nullptr, nullptr, 0, 0, 1.0f, 0, 0, 1, 1);
        zero_kernel<<<256, 256, 0, sB>>>(ctx, (long)BH * NBF * DH);

        launch_tgemm<128, 64>(s0, ROWS, INNER, DIM, y, DIM, 1, 0, 0, wk_l, INNER, 0, 0,
                              k, INNER, 0, 0, nullptr, nullptr, 0, 0, 1.0f, 0, 0, 1, 1);
        zero_kernel<<<16, 256, 0, s0>>>(ksum, BH * NBF);
        favor_gemm_kernel<1><<<dim3(NN / 64, BH), 256, 0, s0>>>(
            k, pT_hi, pT_lo, kf, nullptr, nullptr, rowmax, kdiag);
        stab_reduce_kernel<<<BH, 256, 0, s0>>>(rowmax, stab);
        kexp_kernel<<<BH * NN / 64, 256, 0, s0>>>(kf, kdiag, stab, ksum);

        // favor_q on sA needs q (sA) + ksum (s0)
        fork_to(sA);
        favor_gemm_kernel<0><<<dim3(NN / 64, BH), 256, 0, sA>>>(
            q, pT_hi, pT_lo, qf, ksum, denom, nullptr, nullptr);

        // ctx on s0 needs kf (s0) + v & zeroed ctx (sB)
        join_from(sB);
        launch_tgemm<64, 32>(s0, NBF, DH, NN,
                             kf, 1, NBF, 8LL * NN * NBF, (long)NN * NBF,
                             v, INNER, (long)NN * INNER, DH,
                             ctx, DH, 8LL * NBF * DH, (long)NBF * DH,
                             nullptr, nullptr, 0, 0, 1.0f, 0, 0, BH, 16);

        // attn-out needs qf/denom (sA) + ctx (s0)
        join_from(sA);
        launch_tgemm<64, 32>(s0, NN, DH, NBF,
                             qf, NBF, 1, 8LL * NN * NBF, (long)NN * NBF,
                             ctx, DH, 8LL * NBF * DH, (long)NBF * DH,
                             o, INNER, (long)NN * INNER, DH,
                             nullptr, denom, 8LL * NN, NN, 1.0f, 0, 3, BH, 1);

        launch_tgemm<128, 64>(s0, ROWS, DIM, INNER, o, INNER, 1, 0, 0, wo_l, DIM, 0, 0,
                              z, DIM, 0, 0, bo_l, nullptr, 0, 0, 1.0f, 1, 0, 1, 1);

        ln_kernel<<<ROWS / 8, 256, 0, s0>>>(z, ln2_g + l * DIM, ln2_b + l * DIM, y);
        launch_tgemm<128, 64>(s0, ROWS, FFD, DIM, y, DIM, 1, 0, 0, ffw1_l, FFD, 0, 0,
                              ff, FFD, 0, 0, ffb1_l, nullptr, 0, 0, 1.0f, 0, 2, 1, 1);
        launch_tgemm<128, 64>(s0, ROWS, DIM, FFD, ff, FFD, 1, 0, 0, ffw2_l, DIM, 0, 0,
                              z, DIM, 0, 0, ffb2_l, nullptr, 0, 0, 1.0f, 1, 0, 1, 1);
    }

    // ---- final LN + head ----
    ln_kernel<<<ROWS / 8, 256, 0, s0>>>(z, normf_g, normf_b, y);
    head_kernel<<<ROWS / 8, 256, 0, s0>>>(y, out_w, out_b, out);
}

// round 7
// speedup vs baseline: 28.7401x; 1.0002x over previous
#include <cuda_runtime.h>
#include <math.h>
#include <stdint.h>

// ---------------- problem constants ----------------
#define BSZ    2
#define NN     8192
#define DIM    256
#define HEADS  8
#define DH     64
#define INNER  512
#define QKVN   1536
#define NBF    256
#define FFD    1024
#define EEDG   131072
#define ROWS   (BSZ*NN)
#define BH     (BSZ*HEADS)
#define KEPS   1e-4f
#define LNEPS  1e-5f
#define DN     0.3535533905932738f   /* 64^-0.25 */
#define RATIO  0.0625f               /* 256^-0.5 */

// ---------------- scratch ----------------
__device__ float g_z[ROWS*DIM];
__device__ float g_y[ROWS*DIM];
__device__ float g_qkv[(size_t)ROWS*QKVN];
__device__ float g_wqkv[DIM*QKVN];
__device__ float g_o[ROWS*INNER];
__device__ float g_ff[(size_t)ROWS*FFD];
__device__ float g_qf[(size_t)BH*NN*NBF];
__device__ float g_kf[(size_t)BH*NN*NBF];
__device__ float g_agg[NN*DIM];
__device__ float g_go[NN*DIM];
__device__ float g_deg[NN];
__device__ float g_dinv[NN];
__device__ unsigned g_stab_u[BH];
__device__ float g_ksum[BH*NBF];
__device__ float g_ctx[BH*NBF*DH];
__device__ float g_denom[BH*NN];
__device__ float g_kdiag[BH*NN];
__device__ float g_pT_hi[DH*NBF];
__device__ float g_pT_lo[DH*NBF];

__device__ __forceinline__ float gelu_f(float v) {
    const float c = 0.7978845608028654f;
    float t = tanhf(c * (v + 0.044715f * v * v * v));
    return 0.5f * v * (1.0f + t);
}

__device__ __forceinline__ float cvt_tf32(float x) {
    uint32_t u;
    asm("cvt.rna.tf32.f32 %0, %1;" : "=r"(u) : "f"(x));
    return __uint_as_float(u);
}

// monotonic float->uint key (increasing), for atomicMax on floats of any sign
__device__ __forceinline__ unsigned fkey(float f) {
    unsigned b = __float_as_uint(f);
    return (b & 0x80000000u) ? ~b : (b | 0x80000000u);
}
__device__ __forceinline__ float fkey_inv(unsigned u) {
    unsigned b = (u & 0x80000000u) ? (u ^ 0x80000000u) : ~u;
    return __uint_as_float(b);
}

__device__ __forceinline__ void mma_tf32(float* c, const uint32_t* a,
                                         uint32_t b0, uint32_t b1) {
    asm volatile(
        "mma.sync.aligned.m16n8k8.row.col.f32.tf32.tf32.f32 "
        "{%0,%1,%2,%3}, {%4,%5,%6,%7}, {%8,%9}, {%0,%1,%2,%3};\n"
        : "+f"(c[0]), "+f"(c[1]), "+f"(c[2]), "+f"(c[3])
        : "r"(a[0]), "r"(a[1]), "r"(a[2]), "r"(a[3]), "r"(b0), "r"(b1));
}

// =====================================================================
// tf32 tensor-core GEMM (residual-stream GEMMs). Block 128 x BN, 4 warps.
// =====================================================================
template<int BN, int WN>
__global__ __launch_bounds__(128)
void tgemm_kernel(int M, int N, int K,
                  const float* __restrict__ A, int a_rs, int a_cs, long a_so, long a_si,
                  const float* __restrict__ B, int b_ks, long b_so, long b_si,
                  float* __restrict__ C, int c_rs, long c_so, long c_si,
                  const float* __restrict__ bias,
                  const float* __restrict__ denom, long d_so, long d_si,
                  float alpha, int beta, int epi, int nsplit)
{
    constexpr int BK = 16;
    constexpr int SA = 136;
    constexpr int SB = BN + 8;
    constexpr int NI = WN / 8;
    constexpr int NBL = BN / 32;
    __shared__ float As[2][BK][SA];
    __shared__ float Bs[2][BK][SB];

    int zz = blockIdx.z;
    int batch = zz / nsplit;
    int split = zz - batch * nsplit;
    long aoff = (long)(batch >> 3) * a_so + (long)(batch & 7) * a_si;
    long boff = (long)(batch >> 3) * b_so + (long)(batch & 7) * b_si;
    long coff = (long)(batch >> 3) * c_so + (long)(batch & 7) * c_si;
    int row0 = blockIdx.y * 128;
    int col0 = blockIdx.x * BN;
    int kchunk = K / nsplit;
    int kbeg = split * kchunk;
    int kend = kbeg + kchunk;

    int tid = threadIdx.x;
    int lane = tid & 31;
    int warp = tid >> 5;
    int m_warp = (warp >> 1) * 64;
    int n_warp = (warp & 1) * WN;

    float c[4][NI][4];
    #pragma unroll
    for (int i = 0; i < 4; i++)
        #pragma unroll
        for (int j = 0; j < NI; j++)
            #pragma unroll
            for (int t = 0; t < 4; t++) c[i][j][t] = 0.0f;

    float4 ra[4];
    float4 rb[NBL];

    auto loadA = [&](int kt) {
        if (a_cs == 1) {
            #pragma unroll
            for (int i = 0; i < 4; i++) {
                int idx = tid + i * 128;
                int m = idx >> 2;
                int kc = (idx & 3) * 4;
                ra[i] = *(const float4*)(A + aoff + (long)(row0 + m) * a_rs + kt + kc);
            }
        } else {
            #pragma unroll
            for (int i = 0; i < 4; i++) {
                int idx = tid + i * 128;
                int m4 = (idx & 31) * 4;
                int kk = idx >> 5;
                ra[i] = *(const float4*)(A + aoff + (long)(kt + kk) * a_cs + row0 + m4);
            }
        }
    };
    auto storeA = [&](int bf) {
        if (a_cs == 1) {
            #pragma unroll
            for (int i = 0; i < 4; i++) {
                int idx = tid + i * 128;
                int m = idx >> 2;
                int kc = (idx & 3) * 4;
                float v[4] = {ra[i].x, ra[i].y, ra[i].z, ra[i].w};
                #pragma unroll
                for (int j0 = 0; j0 < 4; j0++) {
                    int j = (j0 + lane) & 3;
                    As[bf][kc + j][m] = cvt_tf32(v[j]);
                }
            }
        } else {
            #pragma unroll
            for (int i = 0; i < 4; i++) {
                int idx = tid + i * 128;
                int m4 = (idx & 31) * 4;
                int kk = idx >> 5;
                float4 t;
                t.x = cvt_tf32(ra[i].x); t.y = cvt_tf32(ra[i].y);
                t.z = cvt_tf32(ra[i].z); t.w = cvt_tf32(ra[i].w);
                *(float4*)&As[bf][kk][m4] = t;
            }
        }
    };
    auto loadB = [&](int kt) {
        #pragma unroll
        for (int i = 0; i < NBL; i++) {
            int idx = tid + i * 128;
            int n4 = (idx & (BN / 4 - 1)) * 4;
            int kk = idx / (BN / 4);
            rb[i] = *(const float4*)(B + boff + (long)(kt + kk) * b_ks + col0 + n4);
        }
    };
    auto storeB = [&](int bf) {
        #pragma unroll
        for (int i = 0; i < NBL; i++) {
            int idx = tid + i * 128;
            int n4 = (idx & (BN / 4 - 1)) * 4;
            int kk = idx / (BN / 4);
            float4 t;
            t.x = cvt_tf32(rb[i].x); t.y = cvt_tf32(rb[i].y);
            t.z = cvt_tf32(rb[i].z); t.w = cvt_tf32(rb[i].w);
            *(float4*)&Bs[bf][kk][n4] = t;
        }
    };
    auto compute = [&](int bf) {
        #pragma unroll
        for (int s = 0; s < 2; s++) {
            int k8 = s * 8;
            uint32_t af[4][4];
            #pragma unroll
            for (int mi = 0; mi < 4; mi++) {
                int mr = m_warp + mi * 16 + (lane >> 2);
                af[mi][0] = __float_as_uint(As[bf][k8 + (lane & 3)][mr]);
                af[mi][1] = __float_as_uint(As[bf][k8 + (lane & 3)][mr + 8]);
                af[mi][2] = __float_as_uint(As[bf][k8 + 4 + (lane & 3)][mr]);
                af[mi][3] = __float_as_uint(As[bf][k8 + 4 + (lane & 3)][mr + 8]);
            }
            #pragma unroll
            for (int ni = 0; ni < NI; ni++) {
                int nc = n_warp + ni * 8 + (lane >> 2);
                uint32_t b0 = __float_as_uint(Bs[bf][k8 + (lane & 3)][nc]);
                uint32_t b1 = __float_as_uint(Bs[bf][k8 + 4 + (lane & 3)][nc]);
                #pragma unroll
                for (int mi = 0; mi < 4; mi++)
                    mma_tf32(c[mi][ni], af[mi], b0, b1);
            }
        }
    };

    loadA(kbeg); loadB(kbeg);
    storeA(0);   storeB(0);
    __syncthreads();
    int buf = 0;
    for (int kt = kbeg; kt < kend; kt += BK) {
        bool has_next = (kt + BK) < kend;
        if (has_next) { loadA(kt + BK); loadB(kt + BK); }
        compute(buf);
        if (has_next) {
            storeA(buf ^ 1); storeB(buf ^ 1);
            __syncthreads();
            buf ^= 1;
        }
    }

    #pragma unroll
    for (int mi = 0; mi < 4; mi++) {
        int r = row0 + m_warp + mi * 16 + (lane >> 2);
        long crow0 = coff + (long)r * c_rs;
        long crow1 = coff + (long)(r + 8) * c_rs;
        float rdv0 = 1.0f, rdv1 = 1.0f;
        if (epi == 3) {
            long dof = (long)(batch >> 3) * d_so + (long)(batch & 7) * d_si;
            rdv0 = 1.0f / denom[dof + r];
            rdv1 = 1.0f / denom[dof + r + 8];
        }
        #pragma unroll
        for (int ni = 0; ni < NI; ni++) {
            int cc = col0 + n_warp + ni * 8 + 2 * (lane & 3);
            float v0 = alpha * c[mi][ni][0];
            float v1 = alpha * c[mi][ni][1];
            float v2 = alpha * c[mi][ni][2];
            float v3 = alpha * c[mi][ni][3];
            if (nsplit > 1) {
                atomicAdd(C + crow0 + cc,     v0);
                atomicAdd(C + crow0 + cc + 1, v1);
                atomicAdd(C + crow1 + cc,     v2);
                atomicAdd(C + crow1 + cc + 1, v3);
            } else {
                if (bias) {
                    float2 bb = *(const float2*)(bias + cc);
                    v0 += bb.x; v1 += bb.y; v2 += bb.x; v3 += bb.y;
                }
                if (epi == 1) {
                    v0 = fmaxf(v0, 0.f); v1 = fmaxf(v1, 0.f);
                    v2 = fmaxf(v2, 0.f); v3 = fmaxf(v3, 0.f);
                } else if (epi == 2) {
                    v0 = gelu_f(v0); v1 = gelu_f(v1);
                    v2 = gelu_f(v2); v3 = gelu_f(v3);
                } else if (epi == 3) {
                    v0 *= rdv0; v1 *= rdv0; v2 *= rdv1; v3 *= rdv1;
                }
                if (beta) {
                    float2 c0 = *(const float2*)(C + crow0 + cc);
                    float2 c1 = *(const float2*)(C + crow1 + cc);
                    v0 += c0.x; v1 += c0.y; v2 += c1.x; v3 += c1.y;
                }
                *(float2*)(C + crow0 + cc) = make_float2(v0, v1);
                *(float2*)(C + crow1 + cc) = make_float2(v2, v3);
            }
        }
    }
}

// =====================================================================
// Fused FAVOR feature kernel (tf32x3). qk rows have stride QKVN.
// MODE 0 (Q): qf = ratio*(exp(dd-diag-rowmax)+keps), denom = qf.ksum.
// MODE 1 (K): raw dd -> outf, kdiag, block-max -> atomicMax(stab key).
// =====================================================================
template<int MODE>
__global__ __launch_bounds__(256, 2)
void favor_gemm_kernel(const float* __restrict__ qk,
                       const float* __restrict__ pT_hi,
                       const float* __restrict__ pT_lo,
                       float* __restrict__ outf,
                       const float* __restrict__ ksum,
                       float* __restrict__ denom,
                       unsigned* __restrict__ stab_u,
                       float* __restrict__ kdiag)
{
    constexpr int BK = 16;
    __shared__ float As_hi[BK][72], As_lo[BK][72];
    __shared__ float Bs_hi[BK][NBF + 8], Bs_lo[BK][NBF + 8];
    __shared__ float diag_s[64];
    __shared__ float red[4][64];
    __shared__ float rmax_s[64];
    __shared__ float ksum_s[NBF];

    int bh = blockIdx.y;
    int b = bh >> 3, h = bh & 7;
    int row0 = blockIdx.x * 64;
    const float* aptr = qk + ((long)(b * NN) + row0) * QKVN + h * DH;

    int tid = threadIdx.x;
    int lane = tid & 31, w = tid >> 5;
    int m_warp = (w >> 2) * 32;
    int n_warp = (w & 3) * 64;

    if (MODE == 0) ksum_s[tid] = ksum[bh * NBF + tid];

    float c[2][8][4];
    #pragma unroll
    for (int mi = 0; mi < 2; mi++)
        #pragma unroll
        for (int ni = 0; ni < 8; ni++)
            #pragma unroll
            for (int t = 0; t < 4; t++) c[mi][ni][t] = 0.0f;

    int am = tid >> 2;
    int akc = (tid & 3) * 4;
    float sq = 0.0f;

    for (int kt = 0; kt < DH; kt += BK) {
        float4 av = *(const float4*)(aptr + (long)am * QKVN + kt + akc);
        av.x *= DN; av.y *= DN; av.z *= DN; av.w *= DN;
        sq += av.x * av.x + av.y * av.y + av.z * av.z + av.w * av.w;
        float vv[4] = {av.x, av.y, av.z, av.w};
        #pragma unroll
        for (int j0 = 0; j0 < 4; j0++) {
            int j = (j0 + lane) & 3;
            float hi = cvt_tf32(vv[j]);
            As_hi[akc + j][am] = hi;
            As_lo[akc + j][am] = cvt_tf32(vv[j] - hi);
        }
        #pragma unroll
        for (int t = 0; t < 4; t++) {
            int idx = tid + t * 256;
            int n4 = (idx & 63) * 4;
            int kk = idx >> 6;
            *(float4*)&Bs_hi[kk][n4] = *(const float4*)(pT_hi + (long)(kt + kk) * NBF + n4);
            *(float4*)&Bs_lo[kk][n4] = *(const float4*)(pT_lo + (long)(kt + kk) * NBF + n4);
        }
        __syncthreads();
        #pragma unroll
        for (int s = 0; s < 2; s++) {
            int k8 = s * 8;
            uint32_t ah[2][4], al[2][4];
            #pragma unroll
            for (int mi = 0; mi < 2; mi++) {
                int mr = m_warp + mi * 16 + (lane >> 2);
                ah[mi][0] = __float_as_uint(As_hi[k8 + (lane & 3)][mr]);
                ah[mi][1] = __float_as_uint(As_hi[k8 + (lane & 3)][mr + 8]);
                ah[mi][2] = __float_as_uint(As_hi[k8 + 4 + (lane & 3)][mr]);
                ah[mi][3] = __float_as_uint(As_hi[k8 + 4 + (lane & 3)][mr + 8]);
                al[mi][0] = __float_as_uint(As_lo[k8 + (lane & 3)][mr]);
                al[mi][1] = __float_as_uint(As_lo[k8 + (lane & 3)][mr + 8]);
                al[mi][2] = __float_as_uint(As_lo[k8 + 4 + (lane & 3)][mr]);
                al[mi][3] = __float_as_uint(As_lo[k8 + 4 + (lane & 3)][mr + 8]);
            }
            #pragma unroll
            for (int ni = 0; ni < 8; ni++) {
                int nc = n_warp + ni * 8 + (lane >> 2);
                uint32_t bh0 = __float_as_uint(Bs_hi[k8 + (lane & 3)][nc]);
                uint32_t bh1 = __float_as_uint(Bs_hi[k8 + 4 + (lane & 3)][nc]);
                uint32_t bl0 = __float_as_uint(Bs_lo[k8 + (lane & 3)][nc]);
                uint32_t bl1 = __float_as_uint(Bs_lo[k8 + 4 + (lane & 3)][nc]);
                #pragma unroll
                for (int mi = 0; mi < 2; mi++) {
                    mma_tf32(c[mi][ni], ah[mi], bh0, bh1);
                    mma_tf32(c[mi][ni], ah[mi], bl0, bl1);
                    mma_tf32(c[mi][ni], al[mi], bh0, bh1);
                }
            }
        }
        __syncthreads();
    }

    sq += __shfl_xor_sync(0xffffffffu, sq, 1);
    sq += __shfl_xor_sync(0xffffffffu, sq, 2);
    if ((tid & 3) == 0) diag_s[am] = 0.5f * sq;

    float mx[2][2];
    #pragma unroll
    for (int mi = 0; mi < 2; mi++) {
        float mlo = -INFINITY, mhi = -INFINITY;
        #pragma unroll
        for (int ni = 0; ni < 8; ni++) {
            mlo = fmaxf(mlo, fmaxf(c[mi][ni][0], c[mi][ni][1]));
            mhi = fmaxf(mhi, fmaxf(c[mi][ni][2], c[mi][ni][3]));
        }
        #pragma unroll
        for (int o = 1; o <= 2; o <<= 1) {
            mlo = fmaxf(mlo, __shfl_xor_sync(0xffffffffu, mlo, o));
            mhi = fmaxf(mhi, __shfl_xor_sync(0xffffffffu, mhi, o));
        }
        mx[mi][0] = mlo; mx[mi][1] = mhi;
    }
    if ((lane & 3) == 0) {
        #pragma unroll
        for (int mi = 0; mi < 2; mi++) {
            int lr = m_warp + mi * 16 + (lane >> 2);
            red[w & 3][lr]     = mx[mi][0];
            red[w & 3][lr + 8] = mx[mi][1];
        }
    }
    __syncthreads();
    if (tid < 64)
        rmax_s[tid] = fmaxf(fmaxf(red[0][tid], red[1][tid]),
                            fmaxf(red[2][tid], red[3][tid]));
    __syncthreads();

    if (MODE == 1) {
        if (tid < 64)
            kdiag[(long)bh * NN + row0 + tid] = diag_s[tid];
        // block max of rmax_s -> atomicMax(stab key)
        if (tid < 32) {
            float m = fmaxf(rmax_s[tid], rmax_s[tid + 32]);
            #pragma unroll
            for (int o = 16; o; o >>= 1)
                m = fmaxf(m, __shfl_xor_sync(0xffffffffu, m, o));
            if (tid == 0) atomicMax(&stab_u[bh], fkey(m));
        }
        #pragma unroll
        for (int mi = 0; mi < 2; mi++) {
            int rl = m_warp + mi * 16 + (lane >> 2);
            long o0 = ((long)bh * NN + row0 + rl) * NBF;
            long o1 = ((long)bh * NN + row0 + rl + 8) * NBF;
            #pragma unroll
            for (int ni = 0; ni < 8; ni++) {
                int nc = n_warp + ni * 8 + 2 * (lane & 3);
                *(float2*)(outf + o0 + nc) = make_float2(c[mi][ni][0], c[mi][ni][1]);
                *(float2*)(outf + o1 + nc) = make_float2(c[mi][ni][2], c[mi][ni][3]);
            }
        }
        return;
    }

    float ds[2][2] = {{0.f, 0.f}, {0.f, 0.f}};
    #pragma unroll
    for (int mi = 0; mi < 2; mi++) {
        int rl = m_warp + mi * 16 + (lane >> 2);
        float sub0 = diag_s[rl]     + rmax_s[rl];
        float sub1 = diag_s[rl + 8] + rmax_s[rl + 8];
        long o0 = ((long)bh * NN + row0 + rl) * NBF;
        long o1 = ((long)bh * NN + row0 + rl + 8) * NBF;
        #pragma unroll
        for (int ni = 0; ni < 8; ni++) {
            int nc = n_warp + ni * 8 + 2 * (lane & 3);
            float v0 = RATIO * (expf(c[mi][ni][0] - sub0) + KEPS);
            float v1 = RATIO * (expf(c[mi][ni][1] - sub0) + KEPS);
            float v2 = RATIO * (expf(c[mi][ni][2] - sub1) + KEPS);
            float v3 = RATIO * (expf(c[mi][ni][3] - sub1) + KEPS);
            *(float2*)(outf + o0 + nc) = make_float2(v0, v1);
            *(float2*)(outf + o1 + nc) = make_float2(v2, v3);
            ds[mi][0] += v0 * ksum_s[nc] + v1 * ksum_s[nc + 1];
            ds[mi][1] += v2 * ksum_s[nc] + v3 * ksum_s[nc + 1];
        }
    }
    #pragma unroll
    for (int mi = 0; mi < 2; mi++) {
        #pragma unroll
        for (int o = 1; o <= 2; o <<= 1) {
            ds[mi][0] += __shfl_xor_sync(0xffffffffu, ds[mi][0], o);
            ds[mi][1] += __shfl_xor_sync(0xffffffffu, ds[mi][1], o);
        }
    }
    __syncthreads();
    if ((lane & 3) == 0) {
        #pragma unroll
        for (int mi = 0; mi < 2; mi++) {
            int lr = m_warp + mi * 16 + (lane >> 2);
            red[w & 3][lr]     = ds[mi][0];
            red[w & 3][lr + 8] = ds[mi][1];
        }
    }
    __syncthreads();
    if (tid < 64)
        denom[(long)bh * NN + row0 + tid] =
            red[0][tid] + red[1][tid] + red[2][tid] + red[3][tid];
}

__global__ void kexp_kernel(float* __restrict__ kf,
                            const float* __restrict__ kdiag,
                            const unsigned* __restrict__ stab_u,
                            float* __restrict__ ksum)
{
    long rbase = (long)blockIdx.x * 64;
    int bh = (int)(rbase >> 13);
    float st = fkey_inv(stab_u[bh]);
    int col = threadIdx.x;
    float s = 0.0f;
    #pragma unroll 4
    for (int i = 0; i < 64; i++) {
        long r = rbase + i;
        float dd = kf[r * NBF + col];
        float v = RATIO * (expf(dd - kdiag[r] - st) + KEPS);
        kf[r * NBF + col] = v;
        s += v;
    }
    atomicAdd(&ksum[bh * NBF + col], s);
}

// ---------------- elementwise / misc kernels ----------------
__global__ void zero_kernel(float* p, long n) {
    long i = (long)blockIdx.x * blockDim.x + threadIdx.x;
    long stride = (long)gridDim.x * blockDim.x;
    for (; i < n; i += stride) p[i] = 0.0f;
}

// zero ksum + init stab keys
__global__ void zks_kernel(float* __restrict__ ksum, unsigned* __restrict__ stab_u) {
    int i = blockIdx.x * 256 + threadIdx.x;
    ksum[i] = 0.0f;
    if (i < BH) stab_u[i] = 0u;
}

__global__ void concat_w_kernel(const float* __restrict__ wq,
                                const float* __restrict__ wk,
                                const float* __restrict__ wv,
                                float* __restrict__ wall)
{
    int c = blockIdx.x;
    int j = threadIdx.x;   // 512
    wall[(long)c * QKVN + j]        = wq[(long)c * INNER + j];
    wall[(long)c * QKVN + 512 + j]  = wk[(long)c * INNER + j];
    wall[(long)c * QKVN + 1024 + j] = wv[(long)c * INNER + j];
}

__global__ void embed_kernel(const float* __restrict__ x,
                             const float* __restrict__ w1,
                             const float* __restrict__ b1,
                             float* __restrict__ h)
{
    long i = blockIdx.x;
    int j = threadIdx.x;
    float v = x[i] * w1[j] + b1[j];
    h[i * DIM + j] = fmaxf(v, 0.0f);
}

__global__ void deg_kernel(const int* __restrict__ ei,
                           const float* __restrict__ ew,
                           float* __restrict__ deg)
{
    int e = blockIdx.x * blockDim.x + threadIdx.x;
    if (e < EEDG) atomicAdd(&deg[ei[EEDG + e]], ew[e]);
}

__global__ void dinv_kernel(const float* __restrict__ deg, float* __restrict__ dinv)
{
    int i = blockIdx.x * blockDim.x + threadIdx.x;
    if (i < NN) {
        float d = deg[i];
        dinv[i] = (d > 0.0f) ? rsqrtf(fmaxf(d, 1e-12f)) : 0.0f;
    }
}

__global__ void agg_kernel(const int* __restrict__ ei,
                           const float* __restrict__ ew,
                           const float* __restrict__ dinv,
                           const float* __restrict__ emb,
                           float* __restrict__ agg)
{
    int e = blockIdx.x;
    int j = threadIdx.x;
    int r = ei[e];
    int c = ei[EEDG + e];
    float w = dinv[r] * ew[e] * dinv[c];
    atomicAdd(&agg[(long)c * DIM + j], emb[(long)r * DIM + j] * w);
}

__global__ void zadd_kernel(float* __restrict__ z,
                            const float* __restrict__ pos,
                            const float* __restrict__ go)
{
    long i = blockIdx.x;
    int j = threadIdx.x;
    int n = (int)(i & (NN - 1));
    z[i * DIM + j] += pos[(long)n * DIM + j] + go[(long)n * DIM + j];
}

__global__ void ln_kernel(const float* __restrict__ x,
                          const float* __restrict__ g,
                          const float* __restrict__ b,
                          float* __restrict__ y)
{
    int warp = threadIdx.x >> 5, lane = threadIdx.x & 31;
    long row = (long)blockIdx.x * 8 + warp;
    const float4* xr = (const float4*)(x + row * DIM);
    float4 v0 = xr[lane];
    float4 v1 = xr[lane + 32];
    float s  = v0.x + v0.y + v0.z + v0.w + v1.x + v1.y + v1.z + v1.w;
    float s2 = v0.x*v0.x + v0.y*v0.y + v0.z*v0.z + v0.w*v0.w
             + v1.x*v1.x + v1.y*v1.y + v1.z*v1.z + v1.w*v1.w;
    #pragma unroll
    for (int o = 16; o; o >>= 1) {
        s  += __shfl_xor_sync(0xffffffffu, s,  o);
        s2 += __shfl_xor_sync(0xffffffffu, s2, o);
    }
    float mean = s * (1.0f / DIM);
    float var = s2 * (1.0f / DIM) - mean * mean;
    float rstd = rsqrtf(fmaxf(var, 0.0f) + LNEPS);
    const float4* g4 = (const float4*)g;
    const float4* b4 = (const float4*)b;
    float4* yr = (float4*)(y + row * DIM);
    float4 ga = g4[lane], bb = b4[lane];
    float4 o0;
    o0.x = (v0.x - mean) * rstd * ga.x + bb.x;
    o0.y = (v0.y - mean) * rstd * ga.y + bb.y;
    o0.z = (v0.z - mean) * rstd * ga.z + bb.z;
    o0.w = (v0.w - mean) * rstd * ga.w + bb.w;
    yr[lane] = o0;
    ga = g4[lane + 32]; bb = b4[lane + 32];
    float4 o1;
    o1.x = (v1.x - mean) * rstd * ga.x + bb.x;
    o1.y = (v1.y - mean) * rstd * ga.y + bb.y;
    o1.z = (v1.z - mean) * rstd * ga.z + bb.z;
    o1.w = (v1.w - mean) * rstd * ga.w + bb.w;
    yr[lane + 32] = o1;
}

__global__ void transpose_proj_kernel(const float* __restrict__ proj,
                                      float* __restrict__ pT_hi,
                                      float* __restrict__ pT_lo)
{
    int m = blockIdx.x;
    int d = threadIdx.x;
    float v = proj[(long)m * DH + d];
    float hi = cvt_tf32(v);
    pT_hi[(long)d * NBF + m] = hi;
    pT_lo[(long)d * NBF + m] = cvt_tf32(v - hi);
}

__global__ void head_kernel(const float* __restrict__ y,
                            const float* __restrict__ w,
                            const float* __restrict__ bb,
                            float* __restrict__ out)
{
    int warp = threadIdx.x >> 5, lane = threadIdx.x & 31;
    long row = (long)blockIdx.x * 8 + warp;
    const float* yr = y + row * DIM;
    float s = 0.0f;
    #pragma unroll
    for (int i = 0; i < 8; i++) s += yr[lane + i * 32] * w[lane + i * 32];
    #pragma unroll
    for (int o = 16; o; o >>= 1) s += __shfl_xor_sync(0xffffffffu, s, o);
    if (lane == 0) out[row] = s + bb[0];
}

// ---------------- host ----------------
template<int BN, int WN>
static inline void launch_tgemm(cudaStream_t st, int M, int N, int K,
    const float* A, int a_rs, int a_cs, long a_so, long a_si,
    const float* B, int b_ks, long b_so, long b_si,
    float* C, int c_rs, long c_so, long c_si,
    const float* bias, const float* denom, long d_so, long d_si,
    float alpha, int beta, int epi, int nbatch, int nsplit)
{
    dim3 grid(N / BN, M / 128, nbatch * nsplit);
    tgemm_kernel<BN, WN><<<grid, 128, 0, st>>>(M, N, K, A, a_rs, a_cs, a_so, a_si,
                                        B, b_ks, b_so, b_si, C, c_rs, c_so, c_si,
                                        bias, denom, d_so, d_si, alpha, beta, epi, nsplit);
}

extern "C" void kernel_launch(void* const* d_in, const int* in_sizes, int n_in,
                              void* d_out, int out_size)
{
    const float* x        = (const float*)d_in[0];
    const float* mlp_w1   = (const float*)d_in[1];
    const float* mlp_b1   = (const float*)d_in[2];
    const float* mlp_w2   = (const float*)d_in[3];
    const float* mlp_b2   = (const float*)d_in[4];
    const float* pos      = (const float*)d_in[5];
    const float* gnn_emb  = (const float*)d_in[6];
    const float* gnn_w    = (const float*)d_in[7];
    const float* gnn_b    = (const float*)d_in[8];
    const float* ew       = (const float*)d_in[9];
    const float* proj     = (const float*)d_in[10];
    const float* ln1_g    = (const float*)d_in[11];
    const float* ln1_b    = (const float*)d_in[12];
    const float* wq       = (const float*)d_in[13];
    const float* wk       = (const float*)d_in[14];
    const float* wv       = (const float*)d_in[15];
    const float* wo       = (const float*)d_in[16];
    const float* bo       = (const float*)d_in[17];
    const float* ln2_g    = (const float*)d_in[18];
    const float* ln2_b    = (const float*)d_in[19];
    const float* ffw1     = (const float*)d_in[20];
    const float* ffb1     = (const float*)d_in[21];
    const float* ffw2     = (const float*)d_in[22];
    const float* ffb2     = (const float*)d_in[23];
    const float* normf_g  = (const float*)d_in[24];
    const float* normf_b  = (const float*)d_in[25];
    const float* out_w    = (const float*)d_in[26];
    const float* out_b    = (const float*)d_in[27];
    const int*   ei       = (const int*)d_in[28];
    float* out            = (float*)d_out;

    float *z, *y, *qkv, *wqkv, *o, *ff, *qf, *kf, *agg, *go, *deg, *dinv;
    float *ksum, *ctx, *denom, *kdiag, *pT_hi, *pT_lo;
    unsigned* stab_u;
    cudaGetSymbolAddress((void**)&z, g_z);
    cudaGetSymbolAddress((void**)&y, g_y);
    cudaGetSymbolAddress((void**)&qkv, g_qkv);
    cudaGetSymbolAddress((void**)&wqkv, g_wqkv);
    cudaGetSymbolAddress((void**)&o, g_o);
    cudaGetSymbolAddress((void**)&ff, g_ff);
    cudaGetSymbolAddress((void**)&qf, g_qf);
    cudaGetSymbolAddress((void**)&kf, g_kf);
    cudaGetSymbolAddress((void**)&agg, g_agg);
    cudaGetSymbolAddress((void**)&go, g_go);
    cudaGetSymbolAddress((void**)&deg, g_deg);
    cudaGetSymbolAddress((void**)&dinv, g_dinv);
    cudaGetSymbolAddress((void**)&stab_u, g_stab_u);
    cudaGetSymbolAddress((void**)&ksum, g_ksum);
    cudaGetSymbolAddress((void**)&ctx, g_ctx);
    cudaGetSymbolAddress((void**)&denom, g_denom);
    cudaGetSymbolAddress((void**)&kdiag, g_kdiag);
    cudaGetSymbolAddress((void**)&pT_hi, g_pT_hi);
    cudaGetSymbolAddress((void**)&pT_lo, g_pT_lo);

    // streams & events: created once on first (correctness) call
    static cudaStream_t sA = nullptr, sB = nullptr;
    static cudaEvent_t evs[32];
    if (sA == nullptr) {
        cudaStreamCreateWithFlags(&sA, cudaStreamNonBlocking);
        cudaStreamCreateWithFlags(&sB, cudaStreamNonBlocking);
        for (int i = 0; i < 32; i++)
            cudaEventCreateWithFlags(&evs[i], cudaEventDisableTiming);
    }
    cudaStream_t s0 = cudaStreamPerThread;
    int ne = 0;
    auto fork_to = [&](cudaStream_t dst) {
        cudaEventRecord(evs[ne], s0);
        cudaStreamWaitEvent(dst, evs[ne], 0);
        ne++;
    };
    auto join_from = [&](cudaStream_t src) {
        cudaEventRecord(evs[ne], src);
        cudaStreamWaitEvent(s0, evs[ne], 0);
        ne++;
    };

    // ---- prologue (ordered so launch #6 = embed tgemm for ncu -s 5) ----
    zero_kernel<<<64, 256, 0, s0>>>(deg, NN);                       // 1
    zero_kernel<<<1024, 256, 0, s0>>>(agg, (long)NN * DIM);        // 2
    deg_kernel<<<EEDG / 256, 256, 0, s0>>>(ei, ew, deg);           // 3
    dinv_kernel<<<NN / 256, 256, 0, s0>>>(deg, dinv);              // 4
    fork_to(sB);
    embed_kernel<<<ROWS, DIM, 0, sB>>>(x, mlp_w1, mlp_b1, y);      // 5
    launch_tgemm<128, 64>(sB, ROWS, DIM, DIM, y, DIM, 1, 0, 0,    // 6 <- profiled
                          mlp_w2, DIM, 0, 0,
                          z, DIM, 0, 0, mlp_b2, nullptr, 0, 0, 1.0f, 0, 0, 1, 1);
    transpose_proj_kernel<<<NBF, DH, 0, s0>>>(proj, pT_hi, pT_lo);
    agg_kernel<<<EEDG, DIM, 0, s0>>>(ei, ew, dinv, gnn_emb, agg);
    launch_tgemm<128, 64>(s0, NN, DIM, DIM, agg, DIM, 1, 0, 0, gnn_w, DIM, 0, 0,
                          go, DIM, 0, 0, gnn_b, nullptr, 0, 0, 1.0f, 0, 0, 1, 1);
    join_from(sB);
    zadd_kernel<<<ROWS, DIM, 0, s0>>>(z, pos, go);

    // ---- transformer layers ----
    for (int l = 0; l < 2; l++) {
        const float* wq_l   = wq  + (long)l * DIM * INNER;
        const float* wk_l   = wk  + (long)l * DIM * INNER;
        const float* wv_l   = wv  + (long)l * DIM * INNER;
        const float* wo_l   = wo  + (long)l * INNER * DIM;
        const float* bo_l   = bo  + (long)l * DIM;
        const float* ffw1_l = ffw1 + (long)l * DIM * FFD;
        const float* ffb1_l = ffb1 + (long)l * FFD;
        const float* ffw2_l = ffw2 + (long)l * FFD * DIM;
        const float* ffb2_l = ffb2 + (long)l * DIM;

        // weight concat + ln can overlap
        fork_to(sA);
        concat_w_kernel<<<DIM, 512, 0, sA>>>(wq_l, wk_l, wv_l, wqkv);
        ln_kernel<<<ROWS / 8, 256, 0, s0>>>(z, ln1_g + l * DIM, ln1_b + l * DIM, y);
        join_from(sA);

        // fused QKV: one wide GEMM
        launch_tgemm<128, 64>(s0, ROWS, QKVN, DIM, y, DIM, 1, 0, 0, wqkv, QKVN, 0, 0,
                              qkv, QKVN, 0, 0, nullptr, nullptr, 0, 0, 1.0f, 0, 0, 1, 1);

        // ctx-zero off-path
        fork_to(sB);
        zero_kernel<<<256, 256, 0, sB>>>(ctx, (long)BH * NBF * DH);

        zks_kernel<<<16, 256, 0, s0>>>(ksum, stab_u);
        favor_gemm_kernel<1><<<dim3(NN / 64, BH), 256, 0, s0>>>(
            qkv + 512, pT_hi, pT_lo, kf, nullptr, nullptr, stab_u, kdiag);
        kexp_kernel<<<BH * NN / 64, 256, 0, s0>>>(kf, kdiag, stab_u, ksum);

        // favor_q overlaps ctx
        fork_to(sA);
        favor_gemm_kernel<0><<<dim3(NN / 64, BH), 256, 0, sA>>>(
            qkv, pT_hi, pT_lo, qf, ksum, denom, nullptr, nullptr);

        join_from(sB);
        launch_tgemm<64, 32>(s0, NBF, DH, NN,
                             kf, 1, NBF, 8LL * NN * NBF, (long)NN * NBF,
                             qkv + 1024, QKVN, (long)NN * QKVN, DH,
                             ctx, DH, 8LL * NBF * DH, (long)NBF * DH,
                             nullptr, nullptr, 0, 0, 1.0f, 0, 0, BH, 32);

        join_from(sA);
        launch_tgemm<64, 32>(s0, NN, DH, NBF,
                             qf, NBF, 1, 8LL * NN * NBF, (long)NN * NBF,
                             ctx, DH, 8LL * NBF * DH, (long)NBF * DH,
                             o, INNER, (long)NN * INNER, DH,
                             nullptr, denom, 8LL * NN, NN, 1.0f, 0, 3, BH, 1);

        launch_tgemm<128, 64>(s0, ROWS, DIM, INNER, o, INNER, 1, 0, 0, wo_l, DIM, 0, 0,
                              z, DIM, 0, 0, bo_l, nullptr, 0, 0, 1.0f, 1, 0, 1, 1);

        ln_kernel<<<ROWS / 8, 256, 0, s0>>>(z, ln2_g + l * DIM, ln2_b + l * DIM, y);
        launch_tgemm<128, 64>(s0, ROWS, FFD, DIM, y, DIM, 1, 0, 0, ffw1_l, FFD, 0, 0,
                              ff, FFD, 0, 0, ffb1_l, nullptr, 0, 0, 1.0f, 0, 2, 1, 1);
        launch_tgemm<128, 64>(s0, ROWS, DIM, FFD, ff, FFD, 1, 0, 0, ffw2_l, DIM, 0, 0,
                              z, DIM, 0, 0, ffb2_l, nullptr, 0, 0, 1.0f, 1, 0, 1, 1);
    }

    // ---- final LN + head ----
    ln_kernel<<<ROWS / 8, 256, 0, s0>>>(z, normf_g, normf_b, y);
    head_kernel<<<ROWS / 8, 256, 0, s0>>>(y, out_w, out_b, out);
}

// round 8
// speedup vs baseline: 30.0468x; 1.0455x over previous
#include <cuda_runtime.h>
#include <math.h>
#include <stdint.h>

// ---------------- problem constants ----------------
#define BSZ    2
#define NN     8192
#define DIM    256
#define HEADS  8
#define DH     64
#define INNER  512
#define QKVN   1536
#define NBF    256
#define FFD    1024
#define EEDG   131072
#define ROWS   (BSZ*NN)
#define BH     (BSZ*HEADS)
#define KEPS   1e-4f
#define LNEPS  1e-5f
#define DN     0.3535533905932738f   /* 64^-0.25 */
#define RATIO  0.0625f               /* 256^-0.5 */

// ---------------- scratch ----------------
__device__ float g_z[ROWS*DIM];
__device__ float g_y[ROWS*DIM];
__device__ float g_qkv[(size_t)ROWS*QKVN];
__device__ float g_wqkv[DIM*QKVN];
__device__ float g_o[ROWS*INNER];
__device__ float g_ff[(size_t)ROWS*FFD];
__device__ float g_qf[(size_t)BH*NN*NBF];
__device__ float g_kf[(size_t)BH*NN*NBF];     // raw dd for K
__device__ float g_agg[NN*DIM];
__device__ float g_go[NN*DIM];
__device__ float g_deg[NN];
__device__ float g_dinv[NN];
__device__ unsigned g_stab_u[BH];
__device__ float g_ksum[BH*NBF];
__device__ float g_ctx[BH*NBF*DH];
__device__ float g_kdiag[BH*NN];
__device__ float g_pT_hi[DH*NBF];
__device__ float g_pT_lo[DH*NBF];

__device__ __forceinline__ float gelu_f(float v) {
    const float c = 0.7978845608028654f;
    float t = tanhf(c * (v + 0.044715f * v * v * v));
    return 0.5f * v * (1.0f + t);
}

__device__ __forceinline__ float cvt_tf32(float x) {
    uint32_t u;
    asm("cvt.rna.tf32.f32 %0, %1;" : "=r"(u) : "f"(x));
    return __uint_as_float(u);
}

__device__ __forceinline__ unsigned fkey(float f) {
    unsigned b = __float_as_uint(f);
    return (b & 0x80000000u) ? ~b : (b | 0x80000000u);
}
__device__ __forceinline__ float fkey_inv(unsigned u) {
    unsigned b = (u & 0x80000000u) ? (u ^ 0x80000000u) : ~u;
    return __uint_as_float(b);
}

__device__ __forceinline__ void mma_tf32(float* c, const uint32_t* a,
                                         uint32_t b0, uint32_t b1) {
    asm volatile(
        "mma.sync.aligned.m16n8k8.row.col.f32.tf32.tf32.f32 "
        "{%0,%1,%2,%3}, {%4,%5,%6,%7}, {%8,%9}, {%0,%1,%2,%3};\n"
        : "+f"(c[0]), "+f"(c[1]), "+f"(c[2]), "+f"(c[3])
        : "r"(a[0]), "r"(a[1]), "r"(a[2]), "r"(a[3]), "r"(b0), "r"(b1));
}

// =====================================================================
// tf32 tensor-core GEMM (residual-stream GEMMs). Block 128 x BN, 4 warps.
// =====================================================================
template<int BN, int WN>
__global__ __launch_bounds__(128)
void tgemm_kernel(int M, int N, int K,
                  const float* __restrict__ A, int a_rs, int a_cs, long a_so, long a_si,
                  const float* __restrict__ B, int b_ks, long b_so, long b_si,
                  float* __restrict__ C, int c_rs, long c_so, long c_si,
                  const float* __restrict__ bias,
                  float alpha, int beta, int epi, int nsplit)
{
    constexpr int BK = 16;
    constexpr int SA = 136;
    constexpr int SB = BN + 8;
    constexpr int NI = WN / 8;
    constexpr int NBL = BN / 32;
    __shared__ float As[2][BK][SA];
    __shared__ float Bs[2][BK][SB];

    int zz = blockIdx.z;
    int batch = zz / nsplit;
    int split = zz - batch * nsplit;
    long aoff = (long)(batch >> 3) * a_so + (long)(batch & 7) * a_si;
    long boff = (long)(batch >> 3) * b_so + (long)(batch & 7) * b_si;
    long coff = (long)(batch >> 3) * c_so + (long)(batch & 7) * c_si;
    int row0 = blockIdx.y * 128;
    int col0 = blockIdx.x * BN;
    int kchunk = K / nsplit;
    int kbeg = split * kchunk;
    int kend = kbeg + kchunk;

    int tid = threadIdx.x;
    int lane = tid & 31;
    int warp = tid >> 5;
    int m_warp = (warp >> 1) * 64;
    int n_warp = (warp & 1) * WN;

    float c[4][NI][4];
    #pragma unroll
    for (int i = 0; i < 4; i++)
        #pragma unroll
        for (int j = 0; j < NI; j++)
            #pragma unroll
            for (int t = 0; t < 4; t++) c[i][j][t] = 0.0f;

    float4 ra[4];
    float4 rb[NBL];

    auto loadA = [&](int kt) {
        if (a_cs == 1) {
            #pragma unroll
            for (int i = 0; i < 4; i++) {
                int idx = tid + i * 128;
                int m = idx >> 2;
                int kc = (idx & 3) * 4;
                ra[i] = *(const float4*)(A + aoff + (long)(row0 + m) * a_rs + kt + kc);
            }
        } else {
            #pragma unroll
            for (int i = 0; i < 4; i++) {
                int idx = tid + i * 128;
                int m4 = (idx & 31) * 4;
                int kk = idx >> 5;
                ra[i] = *(const float4*)(A + aoff + (long)(kt + kk) * a_cs + row0 + m4);
            }
        }
    };
    auto storeA = [&](int bf) {
        if (a_cs == 1) {
            #pragma unroll
            for (int i = 0; i < 4; i++) {
                int idx = tid + i * 128;
                int m = idx >> 2;
                int kc = (idx & 3) * 4;
                float v[4] = {ra[i].x, ra[i].y, ra[i].z, ra[i].w};
                #pragma unroll
                for (int j0 = 0; j0 < 4; j0++) {
                    int j = (j0 + lane) & 3;
                    As[bf][kc + j][m] = cvt_tf32(v[j]);
                }
            }
        } else {
            #pragma unroll
            for (int i = 0; i < 4; i++) {
                int idx = tid + i * 128;
                int m4 = (idx & 31) * 4;
                int kk = idx >> 5;
                float4 t;
                t.x = cvt_tf32(ra[i].x); t.y = cvt_tf32(ra[i].y);
                t.z = cvt_tf32(ra[i].z); t.w = cvt_tf32(ra[i].w);
                *(float4*)&As[bf][kk][m4] = t;
            }
        }
    };
    auto loadB = [&](int kt) {
        #pragma unroll
        for (int i = 0; i < NBL; i++) {
            int idx = tid + i * 128;
            int n4 = (idx & (BN / 4 - 1)) * 4;
            int kk = idx / (BN / 4);
            rb[i] = *(const float4*)(B + boff + (long)(kt + kk) * b_ks + col0 + n4);
        }
    };
    auto storeB = [&](int bf) {
        #pragma unroll
        for (int i = 0; i < NBL; i++) {
            int idx = tid + i * 128;
            int n4 = (idx & (BN / 4 - 1)) * 4;
            int kk = idx / (BN / 4);
            float4 t;
            t.x = cvt_tf32(rb[i].x); t.y = cvt_tf32(rb[i].y);
            t.z = cvt_tf32(rb[i].z); t.w = cvt_tf32(rb[i].w);
            *(float4*)&Bs[bf][kk][n4] = t;
        }
    };
    auto compute = [&](int bf) {
        #pragma unroll
        for (int s = 0; s < 2; s++) {
            int k8 = s * 8;
            uint32_t af[4][4];
            #pragma unroll
            for (int mi = 0; mi < 4; mi++) {
                int mr = m_warp + mi * 16 + (lane >> 2);
                af[mi][0] = __float_as_uint(As[bf][k8 + (lane & 3)][mr]);
                af[mi][1] = __float_as_uint(As[bf][k8 + (lane & 3)][mr + 8]);
                af[mi][2] = __float_as_uint(As[bf][k8 + 4 + (lane & 3)][mr]);
                af[mi][3] = __float_as_uint(As[bf][k8 + 4 + (lane & 3)][mr + 8]);
            }
            #pragma unroll
            for (int ni = 0; ni < NI; ni++) {
                int nc = n_warp + ni * 8 + (lane >> 2);
                uint32_t b0 = __float_as_uint(Bs[bf][k8 + (lane & 3)][nc]);
                uint32_t b1 = __float_as_uint(Bs[bf][k8 + 4 + (lane & 3)][nc]);
                #pragma unroll
                for (int mi = 0; mi < 4; mi++)
                    mma_tf32(c[mi][ni], af[mi], b0, b1);
            }
        }
    };

    loadA(kbeg); loadB(kbeg);
    storeA(0);   storeB(0);
    __syncthreads();
    int buf = 0;
    for (int kt = kbeg; kt < kend; kt += BK) {
        bool has_next = (kt + BK) < kend;
        if (has_next) { loadA(kt + BK); loadB(kt + BK); }
        compute(buf);
        if (has_next) {
            storeA(buf ^ 1); storeB(buf ^ 1);
            __syncthreads();
            buf ^= 1;
        }
    }

    #pragma unroll
    for (int mi = 0; mi < 4; mi++) {
        int r = row0 + m_warp + mi * 16 + (lane >> 2);
        long crow0 = coff + (long)r * c_rs;
        long crow1 = coff + (long)(r + 8) * c_rs;
        #pragma unroll
        for (int ni = 0; ni < NI; ni++) {
            int cc = col0 + n_warp + ni * 8 + 2 * (lane & 3);
            float v0 = alpha * c[mi][ni][0];
            float v1 = alpha * c[mi][ni][1];
            float v2 = alpha * c[mi][ni][2];
            float v3 = alpha * c[mi][ni][3];
            if (nsplit > 1) {
                atomicAdd(C + crow0 + cc,     v0);
                atomicAdd(C + crow0 + cc + 1, v1);
                atomicAdd(C + crow1 + cc,     v2);
                atomicAdd(C + crow1 + cc + 1, v3);
            } else {
                if (bias) {
                    float2 bb = *(const float2*)(bias + cc);
                    v0 += bb.x; v1 += bb.y; v2 += bb.x; v3 += bb.y;
                }
                if (epi == 1) {
                    v0 = fmaxf(v0, 0.f); v1 = fmaxf(v1, 0.f);
                    v2 = fmaxf(v2, 0.f); v3 = fmaxf(v3, 0.f);
                } else if (epi == 2) {
                    v0 = gelu_f(v0); v1 = gelu_f(v1);
                    v2 = gelu_f(v2); v3 = gelu_f(v3);
                }
                if (beta) {
                    float2 c0 = *(const float2*)(C + crow0 + cc);
                    float2 c1 = *(const float2*)(C + crow1 + cc);
                    v0 += c0.x; v1 += c0.y; v2 += c1.x; v3 += c1.y;
                }
                *(float2*)(C + crow0 + cc) = make_float2(v0, v1);
                *(float2*)(C + crow1 + cc) = make_float2(v2, v3);
            }
        }
    }
}

// =====================================================================
// ctxk: ctx[bh] += kf^T @ v with kf computed inline from raw dd:
//   kf = RATIO*(exp(dd - kdiag[n] - stab[bh]) + KEPS)
// Also accumulates ksum[bh][m] (each element staged exactly once).
// M=NBF(256), N=DH(64), K=NN, split-K atomics. grid(1, 2, BH*NSPLIT).
// =====================================================================
#define CTX_NSPLIT 32
__global__ __launch_bounds__(128)
void ctxk_kernel(const float* __restrict__ dd,
                 const float* __restrict__ vsrc,    // qkv + 1024
                 const float* __restrict__ kdiag,
                 const unsigned* __restrict__ stab_u,
                 float* __restrict__ ctx,
                 float* __restrict__ ksum)
{
    constexpr int BK = 16;
    __shared__ float As[2][BK][136];
    __shared__ float Bs[2][BK][72];

    int zz = blockIdx.z;
    int batch = zz / CTX_NSPLIT;
    int split = zz - batch * CTX_NSPLIT;
    long aoff = (long)batch * NN * NBF;
    long boff = (long)(batch >> 3) * NN * QKVN + (long)(batch & 7) * DH;
    long coff = (long)batch * NBF * DH;
    const float* kdg = kdiag + (long)batch * NN;
    float stab = fkey_inv(stab_u[batch]);

    int row0 = blockIdx.y * 128;
    int kbeg = split * (NN / CTX_NSPLIT);
    int kend = kbeg + NN / CTX_NSPLIT;

    int tid = threadIdx.x;
    int lane = tid & 31;
    int warp = tid >> 5;
    int m_warp = (warp >> 1) * 64;
    int n_warp = (warp & 1) * 32;

    float c[4][4][4];
    #pragma unroll
    for (int i = 0; i < 4; i++)
        #pragma unroll
        for (int j = 0; j < 4; j++)
            #pragma unroll
            for (int t = 0; t < 4; t++) c[i][j][t] = 0.0f;

    float ks_acc[4] = {0.f, 0.f, 0.f, 0.f};
    float4 ra[4];
    float4 rb[2];

    auto loadA = [&](int kt) {
        #pragma unroll
        for (int i = 0; i < 4; i++) {
            int idx = tid + i * 128;
            int m4 = (idx & 31) * 4;
            int kk = idx >> 5;
            ra[i] = *(const float4*)(dd + aoff + (long)(kt + kk) * NBF + row0 + m4);
        }
    };
    auto storeA = [&](int bf, int kt) {
        #pragma unroll
        for (int i = 0; i < 4; i++) {
            int idx = tid + i * 128;
            int m4 = (idx & 31) * 4;
            int kk = idx >> 5;
            float sub = kdg[kt + kk] + stab;
            float k0 = RATIO * (expf(ra[i].x - sub) + KEPS);
            float k1 = RATIO * (expf(ra[i].y - sub) + KEPS);
            float k2 = RATIO * (expf(ra[i].z - sub) + KEPS);
            float k3 = RATIO * (expf(ra[i].w - sub) + KEPS);
            ks_acc[0] += k0; ks_acc[1] += k1; ks_acc[2] += k2; ks_acc[3] += k3;
            float4 t;
            t.x = cvt_tf32(k0); t.y = cvt_tf32(k1);
            t.z = cvt_tf32(k2); t.w = cvt_tf32(k3);
            *(float4*)&As[bf][kk][m4] = t;
        }
    };
    auto loadB = [&](int kt) {
        #pragma unroll
        for (int i = 0; i < 2; i++) {
            int idx = tid + i * 128;
            int n4 = (idx & 15) * 4;
            int kk = idx >> 4;
            rb[i] = *(const float4*)(vsrc + boff + (long)(kt + kk) * QKVN + n4);
        }
    };
    auto storeB = [&](int bf) {
        #pragma unroll
        for (int i = 0; i < 2; i++) {
            int idx = tid + i * 128;
            int n4 = (idx & 15) * 4;
            int kk = idx >> 4;
            float4 t;
            t.x = cvt_tf32(rb[i].x); t.y = cvt_tf32(rb[i].y);
            t.z = cvt_tf32(rb[i].z); t.w = cvt_tf32(rb[i].w);
            *(float4*)&Bs[bf][kk][n4] = t;
        }
    };
    auto compute = [&](int bf) {
        #pragma unroll
        for (int s = 0; s < 2; s++) {
            int k8 = s * 8;
            uint32_t af[4][4];
            #pragma unroll
            for (int mi = 0; mi < 4; mi++) {
                int mr = m_warp + mi * 16 + (lane >> 2);
                af[mi][0] = __float_as_uint(As[bf][k8 + (lane & 3)][mr]);
                af[mi][1] = __float_as_uint(As[bf][k8 + (lane & 3)][mr + 8]);
                af[mi][2] = __float_as_uint(As[bf][k8 + 4 + (lane & 3)][mr]);
                af[mi][3] = __float_as_uint(As[bf][k8 + 4 + (lane & 3)][mr + 8]);
            }
            #pragma unroll
            for (int ni = 0; ni < 4; ni++) {
                int nc = n_warp + ni * 8 + (lane >> 2);
                uint32_t b0 = __float_as_uint(Bs[bf][k8 + (lane & 3)][nc]);
                uint32_t b1 = __float_as_uint(Bs[bf][k8 + 4 + (lane & 3)][nc]);
                #pragma unroll
                for (int mi = 0; mi < 4; mi++)
                    mma_tf32(c[mi][ni], af[mi], b0, b1);
            }
        }
    };

    loadA(kbeg); loadB(kbeg);
    storeA(0, kbeg); storeB(0);
    __syncthreads();
    int buf = 0;
    for (int kt = kbeg; kt < kend; kt += BK) {
        bool has_next = (kt + BK) < kend;
        if (has_next) { loadA(kt + BK); loadB(kt + BK); }
        compute(buf);
        if (has_next) {
            storeA(buf ^ 1, kt + BK); storeB(buf ^ 1);
            __syncthreads();
            buf ^= 1;
        }
    }

    // ksum partials (feature index = row0 + m4 + j)
    {
        int m4 = (tid & 31) * 4;
        #pragma unroll
        for (int j = 0; j < 4; j++)
            atomicAdd(&ksum[(long)batch * NBF + row0 + m4 + j], ks_acc[j]);
    }

    // ctx atomics
    #pragma unroll
    for (int mi = 0; mi < 4; mi++) {
        int r = row0 + m_warp + mi * 16 + (lane >> 2);
        long crow0 = coff + (long)r * DH;
        long crow1 = coff + (long)(r + 8) * DH;
        #pragma unroll
        for (int ni = 0; ni < 4; ni++) {
            int cc = n_warp + ni * 8 + 2 * (lane & 3);
            atomicAdd(ctx + crow0 + cc,     c[mi][ni][0]);
            atomicAdd(ctx + crow0 + cc + 1, c[mi][ni][1]);
            atomicAdd(ctx + crow1 + cc,     c[mi][ni][2]);
            atomicAdd(ctx + crow1 + cc + 1, c[mi][ni][3]);
        }
    }
}

// =====================================================================
// attn: o = (qf @ ctx) / (qf . ksum), denom computed inline.
// M=NN per bh, N=DH(64), K=NBF(256) full. grid(1, NN/128, BH).
// =====================================================================
__global__ __launch_bounds__(128)
void attn_kernel(const float* __restrict__ qf,
                 const float* __restrict__ ctx,
                 const float* __restrict__ ksum,
                 float* __restrict__ o)
{
    constexpr int BK = 16;
    __shared__ float As[2][BK][136];
    __shared__ float Bs[2][BK][72];
    __shared__ float ksum_s[NBF];
    __shared__ float denom_s[128];

    int batch = blockIdx.z;
    long aoff = (long)batch * NN * NBF;
    long boff = (long)batch * NBF * DH;
    long coff = (long)(batch >> 3) * NN * INNER + (long)(batch & 7) * DH;
    int row0 = blockIdx.y * 128;

    int tid = threadIdx.x;
    int lane = tid & 31;
    int warp = tid >> 5;
    int m_warp = (warp >> 1) * 64;
    int n_warp = (warp & 1) * 32;

    ksum_s[tid] = ksum[(long)batch * NBF + tid];
    ksum_s[tid + 128] = ksum[(long)batch * NBF + tid + 128];
    denom_s[tid] = 0.0f;
    __syncthreads();

    float c[4][4][4];
    #pragma unroll
    for (int i = 0; i < 4; i++)
        #pragma unroll
        for (int j = 0; j < 4; j++)
            #pragma unroll
            for (int t = 0; t < 4; t++) c[i][j][t] = 0.0f;

    float dacc[4] = {0.f, 0.f, 0.f, 0.f};
    float4 ra[4];
    float4 rb[2];

    auto loadA = [&](int kt) {
        #pragma unroll
        for (int i = 0; i < 4; i++) {
            int idx = tid + i * 128;
            int m = idx >> 2;
            int kc = (idx & 3) * 4;
            ra[i] = *(const float4*)(qf + aoff + (long)(row0 + m) * NBF + kt + kc);
        }
    };
    auto storeA = [&](int bf, int kt) {
        #pragma unroll
        for (int i = 0; i < 4; i++) {
            int idx = tid + i * 128;
            int m = idx >> 2;
            int kc = (idx & 3) * 4;
            float v[4] = {ra[i].x, ra[i].y, ra[i].z, ra[i].w};
            dacc[i] += v[0] * ksum_s[kt + kc] + v[1] * ksum_s[kt + kc + 1]
                     + v[2] * ksum_s[kt + kc + 2] + v[3] * ksum_s[kt + kc + 3];
            #pragma unroll
            for (int j0 = 0; j0 < 4; j0++) {
                int j = (j0 + lane) & 3;
                As[bf][kc + j][m] = cvt_tf32(v[j]);
            }
        }
    };
    auto loadB = [&](int kt) {
        #pragma unroll
        for (int i = 0; i < 2; i++) {
            int idx = tid + i * 128;
            int n4 = (idx & 15) * 4;
            int kk = idx >> 4;
            rb[i] = *(const float4*)(ctx + boff + (long)(kt + kk) * DH + n4);
        }
    };
    auto storeB = [&](int bf) {
        #pragma unroll
        for (int i = 0; i < 2; i++) {
            int idx = tid + i * 128;
            int n4 = (idx & 15) * 4;
            int kk = idx >> 4;
            float4 t;
            t.x = cvt_tf32(rb[i].x); t.y = cvt_tf32(rb[i].y);
            t.z = cvt_tf32(rb[i].z); t.w = cvt_tf32(rb[i].w);
            *(float4*)&Bs[bf][kk][n4] = t;
        }
    };
    auto compute = [&](int bf) {
        #pragma unroll
        for (int s = 0; s < 2; s++) {
            int k8 = s * 8;
            uint32_t af[4][4];
            #pragma unroll
            for (int mi = 0; mi < 4; mi++) {
                int mr = m_warp + mi * 16 + (lane >> 2);
                af[mi][0] = __float_as_uint(As[bf][k8 + (lane & 3)][mr]);
                af[mi][1] = __float_as_uint(As[bf][k8 + (lane & 3)][mr + 8]);
                af[mi][2] = __float_as_uint(As[bf][k8 + 4 + (lane & 3)][mr]);
                af[mi][3] = __float_as_uint(As[bf][k8 + 4 + (lane & 3)][mr + 8]);
            }
            #pragma unroll
            for (int ni = 0; ni < 4; ni++) {
                int nc = n_warp + ni * 8 + (lane >> 2);
                uint32_t b0 = __float_as_uint(Bs[bf][k8 + (lane & 3)][nc]);
                uint32_t b1 = __float_as_uint(Bs[bf][k8 + 4 + (lane & 3)][nc]);
                #pragma unroll
                for (int mi = 0; mi < 4; mi++)
                    mma_tf32(c[mi][ni], af[mi], b0, b1);
            }
        }
    };

    loadA(0); loadB(0);
    storeA(0, 0); storeB(0);
    __syncthreads();
    int buf = 0;
    for (int kt = 0; kt < NBF; kt += BK) {
        bool has_next = (kt + BK) < NBF;
        if (has_next) { loadA(kt + BK); loadB(kt + BK); }
        compute(buf);
        if (has_next) {
            storeA(buf ^ 1, kt + BK); storeB(buf ^ 1);
            __syncthreads();
            buf ^= 1;
        }
    }

    // finalize denom
    #pragma unroll
    for (int i = 0; i < 4; i++) {
        int m = (tid + i * 128) >> 2;
        atomicAdd(&denom_s[m], dacc[i]);
    }
    __syncthreads();

    // epilogue: divide, write
    #pragma unroll
    for (int mi = 0; mi < 4; mi++) {
        int lr = m_warp + mi * 16 + (lane >> 2);
        float rdv0 = 1.0f / denom_s[lr];
        float rdv1 = 1.0f / denom_s[lr + 8];
        long crow0 = coff + (long)(row0 + lr) * INNER;
        long crow1 = coff + (long)(row0 + lr + 8) * INNER;
        #pragma unroll
        for (int ni = 0; ni < 4; ni++) {
            int cc = n_warp + ni * 8 + 2 * (lane & 3);
            *(float2*)(o + crow0 + cc) = make_float2(c[mi][ni][0] * rdv0, c[mi][ni][1] * rdv0);
            *(float2*)(o + crow1 + cc) = make_float2(c[mi][ni][2] * rdv1, c[mi][ni][3] * rdv1);
        }
    }
}

// =====================================================================
// Fused FAVOR feature kernel (tf32x3). qk rows have stride QKVN.
// MODE 0 (Q): qf = ratio*(exp(dd-diag-rowmax)+keps). No ksum needed.
// MODE 1 (K): raw dd -> outf, kdiag, block-max -> atomicMax(stab key).
// =====================================================================
template<int MODE>
__global__ __launch_bounds__(256, 2)
void favor_gemm_kernel(const float* __restrict__ qk,
                       const float* __restrict__ pT_hi,
                       const float* __restrict__ pT_lo,
                       float* __restrict__ outf,
                       unsigned* __restrict__ stab_u,
                       float* __restrict__ kdiag)
{
    constexpr int BK = 16;
    __shared__ float As_hi[BK][72], As_lo[BK][72];
    __shared__ float Bs_hi[BK][NBF + 8], Bs_lo[BK][NBF + 8];
    __shared__ float diag_s[64];
    __shared__ float red[4][64];
    __shared__ float rmax_s[64];

    int bh = blockIdx.y;
    int b = bh >> 3, h = bh & 7;
    int row0 = blockIdx.x * 64;
    const float* aptr = qk + ((long)(b * NN) + row0) * QKVN + h * DH;

    int tid = threadIdx.x;
    int lane = tid & 31, w = tid >> 5;
    int m_warp = (w >> 2) * 32;
    int n_warp = (w & 3) * 64;

    float c[2][8][4];
    #pragma unroll
    for (int mi = 0; mi < 2; mi++)
        #pragma unroll
        for (int ni = 0; ni < 8; ni++)
            #pragma unroll
            for (int t = 0; t < 4; t++) c[mi][ni][t] = 0.0f;

    int am = tid >> 2;
    int akc = (tid & 3) * 4;
    float sq = 0.0f;

    for (int kt = 0; kt < DH; kt += BK) {
        float4 av = *(const float4*)(aptr + (long)am * QKVN + kt + akc);
        av.x *= DN; av.y *= DN; av.z *= DN; av.w *= DN;
        sq += av.x * av.x + av.y * av.y + av.z * av.z + av.w * av.w;
        float vv[4] = {av.x, av.y, av.z, av.w};
        #pragma unroll
        for (int j0 = 0; j0 < 4; j0++) {
            int j = (j0 + lane) & 3;
            float hi = cvt_tf32(vv[j]);
            As_hi[akc + j][am] = hi;
            As_lo[akc + j][am] = cvt_tf32(vv[j] - hi);
        }
        #pragma unroll
        for (int t = 0; t < 4; t++) {
            int idx = tid + t * 256;
            int n4 = (idx & 63) * 4;
            int kk = idx >> 6;
            *(float4*)&Bs_hi[kk][n4] = *(const float4*)(pT_hi + (long)(kt + kk) * NBF + n4);
            *(float4*)&Bs_lo[kk][n4] = *(const float4*)(pT_lo + (long)(kt + kk) * NBF + n4);
        }
        __syncthreads();
        #pragma unroll
        for (int s = 0; s < 2; s++) {
            int k8 = s * 8;
            uint32_t ah[2][4], al[2][4];
            #pragma unroll
            for (int mi = 0; mi < 2; mi++) {
                int mr = m_warp + mi * 16 + (lane >> 2);
                ah[mi][0] = __float_as_uint(As_hi[k8 + (lane & 3)][mr]);
                ah[mi][1] = __float_as_uint(As_hi[k8 + (lane & 3)][mr + 8]);
                ah[mi][2] = __float_as_uint(As_hi[k8 + 4 + (lane & 3)][mr]);
                ah[mi][3] = __float_as_uint(As_hi[k8 + 4 + (lane & 3)][mr + 8]);
                al[mi][0] = __float_as_uint(As_lo[k8 + (lane & 3)][mr]);
                al[mi][1] = __float_as_uint(As_lo[k8 + (lane & 3)][mr + 8]);
                al[mi][2] = __float_as_uint(As_lo[k8 + 4 + (lane & 3)][mr]);
                al[mi][3] = __float_as_uint(As_lo[k8 + 4 + (lane & 3)][mr + 8]);
            }
            #pragma unroll
            for (int ni = 0; ni < 8; ni++) {
                int nc = n_warp + ni * 8 + (lane >> 2);
                uint32_t bh0 = __float_as_uint(Bs_hi[k8 + (lane & 3)][nc]);
                uint32_t bh1 = __float_as_uint(Bs_hi[k8 + 4 + (lane & 3)][nc]);
                uint32_t bl0 = __float_as_uint(Bs_lo[k8 + (lane & 3)][nc]);
                uint32_t bl1 = __float_as_uint(Bs_lo[k8 + 4 + (lane & 3)][nc]);
                #pragma unroll
                for (int mi = 0; mi < 2; mi++) {
                    mma_tf32(c[mi][ni], ah[mi], bh0, bh1);
                    mma_tf32(c[mi][ni], ah[mi], bl0, bl1);
                    mma_tf32(c[mi][ni], al[mi], bh0, bh1);
                }
            }
        }
        __syncthreads();
    }

    sq += __shfl_xor_sync(0xffffffffu, sq, 1);
    sq += __shfl_xor_sync(0xffffffffu, sq, 2);
    if ((tid & 3) == 0) diag_s[am] = 0.5f * sq;

    float mx[2][2];
    #pragma unroll
    for (int mi = 0; mi < 2; mi++) {
        float mlo = -INFINITY, mhi = -INFINITY;
        #pragma unroll
        for (int ni = 0; ni < 8; ni++) {
            mlo = fmaxf(mlo, fmaxf(c[mi][ni][0], c[mi][ni][1]));
            mhi = fmaxf(mhi, fmaxf(c[mi][ni][2], c[mi][ni][3]));
        }
        #pragma unroll
        for (int o = 1; o <= 2; o <<= 1) {
            mlo = fmaxf(mlo, __shfl_xor_sync(0xffffffffu, mlo, o));
            mhi = fmaxf(mhi, __shfl_xor_sync(0xffffffffu, mhi, o));
        }
        mx[mi][0] = mlo; mx[mi][1] = mhi;
    }
    if ((lane & 3) == 0) {
        #pragma unroll
        for (int mi = 0; mi < 2; mi++) {
            int lr = m_warp + mi * 16 + (lane >> 2);
            red[w & 3][lr]     = mx[mi][0];
            red[w & 3][lr + 8] = mx[mi][1];
        }
    }
    __syncthreads();
    if (tid < 64)
        rmax_s[tid] = fmaxf(fmaxf(red[0][tid], red[1][tid]),
                            fmaxf(red[2][tid], red[3][tid]));
    __syncthreads();

    if (MODE == 1) {
        if (tid < 64)
            kdiag[(long)bh * NN + row0 + tid] = diag_s[tid];
        if (tid < 32) {
            float m = fmaxf(rmax_s[tid], rmax_s[tid + 32]);
            #pragma unroll
            for (int o = 16; o; o >>= 1)
                m = fmaxf(m, __shfl_xor_sync(0xffffffffu, m, o));
            if (tid == 0) atomicMax(&stab_u[bh], fkey(m));
        }
        #pragma unroll
        for (int mi = 0; mi < 2; mi++) {
            int rl = m_warp + mi * 16 + (lane >> 2);
            long o0 = ((long)bh * NN + row0 + rl) * NBF;
            long o1 = ((long)bh * NN + row0 + rl + 8) * NBF;
            #pragma unroll
            for (int ni = 0; ni < 8; ni++) {
                int nc = n_warp + ni * 8 + 2 * (lane & 3);
                *(float2*)(outf + o0 + nc) = make_float2(c[mi][ni][0], c[mi][ni][1]);
                *(float2*)(outf + o1 + nc) = make_float2(c[mi][ni][2], c[mi][ni][3]);
            }
        }
        return;
    }

    // Q mode: exp + write qf
    #pragma unroll
    for (int mi = 0; mi < 2; mi++) {
        int rl = m_warp + mi * 16 + (lane >> 2);
        float sub0 = diag_s[rl]     + rmax_s[rl];
        float sub1 = diag_s[rl + 8] + rmax_s[rl + 8];
        long o0 = ((long)bh * NN + row0 + rl) * NBF;
        long o1 = ((long)bh * NN + row0 + rl + 8) * NBF;
        #pragma unroll
        for (int ni = 0; ni < 8; ni++) {
            int nc = n_warp + ni * 8 + 2 * (lane & 3);
            float v0 = RATIO * (expf(c[mi][ni][0] - sub0) + KEPS);
            float v1 = RATIO * (expf(c[mi][ni][1] - sub0) + KEPS);
            float v2 = RATIO * (expf(c[mi][ni][2] - sub1) + KEPS);
            float v3 = RATIO * (expf(c[mi][ni][3] - sub1) + KEPS);
            *(float2*)(outf + o0 + nc) = make_float2(v0, v1);
            *(float2*)(outf + o1 + nc) = make_float2(v2, v3);
        }
    }
}

// ---------------- elementwise / misc kernels ----------------
__global__ void zero_kernel(float* p, long n) {
    long i = (long)blockIdx.x * blockDim.x + threadIdx.x;
    long stride = (long)gridDim.x * blockDim.x;
    for (; i < n; i += stride) p[i] = 0.0f;
}

__global__ void zks_kernel(float* __restrict__ ksum, unsigned* __restrict__ stab_u) {
    int i = blockIdx.x * 256 + threadIdx.x;
    ksum[i] = 0.0f;
    if (i < BH) stab_u[i] = 0u;
}

__global__ void concat_w_kernel(const float* __restrict__ wq,
                                const float* __restrict__ wk,
                                const float* __restrict__ wv,
                                float* __restrict__ wall)
{
    int c = blockIdx.x;
    int j = threadIdx.x;
    wall[(long)c * QKVN + j]        = wq[(long)c * INNER + j];
    wall[(long)c * QKVN + 512 + j]  = wk[(long)c * INNER + j];
    wall[(long)c * QKVN + 1024 + j] = wv[(long)c * INNER + j];
}

__global__ void embed_kernel(const float* __restrict__ x,
                             const float* __restrict__ w1,
                             const float* __restrict__ b1,
                             float* __restrict__ h)
{
    long i = blockIdx.x;
    int j = threadIdx.x;
    float v = x[i] * w1[j] + b1[j];
    h[i * DIM + j] = fmaxf(v, 0.0f);
}

__global__ void deg_kernel(const int* __restrict__ ei,
                           const float* __restrict__ ew,
                           float* __restrict__ deg)
{
    int e = blockIdx.x * blockDim.x + threadIdx.x;
    if (e < EEDG) atomicAdd(&deg[ei[EEDG + e]], ew[e]);
}

__global__ void dinv_kernel(const float* __restrict__ deg, float* __restrict__ dinv)
{
    int i = blockIdx.x * blockDim.x + threadIdx.x;
    if (i < NN) {
        float d = deg[i];
        dinv[i] = (d > 0.0f) ? rsqrtf(fmaxf(d, 1e-12f)) : 0.0f;
    }
}

__global__ void agg_kernel(const int* __restrict__ ei,
                           const float* __restrict__ ew,
                           const float* __restrict__ dinv,
                           const float* __restrict__ emb,
                           float* __restrict__ agg)
{
    int e = blockIdx.x;
    int j = threadIdx.x;
    int r = ei[e];
    int c = ei[EEDG + e];
    float w = dinv[r] * ew[e] * dinv[c];
    atomicAdd(&agg[(long)c * DIM + j], emb[(long)r * DIM + j] * w);
}

__global__ void zadd_kernel(float* __restrict__ z,
                            const float* __restrict__ pos,
                            const float* __restrict__ go)
{
    long i = blockIdx.x;
    int j = threadIdx.x;
    int n = (int)(i & (NN - 1));
    z[i * DIM + j] += pos[(long)n * DIM + j] + go[(long)n * DIM + j];
}

__global__ void ln_kernel(const float* __restrict__ x,
                          const float* __restrict__ g,
                          const float* __restrict__ b,
                          float* __restrict__ y)
{
    int warp = threadIdx.x >> 5, lane = threadIdx.x & 31;
    long row = (long)blockIdx.x * 8 + warp;
    const float4* xr = (const float4*)(x + row * DIM);
    float4 v0 = xr[lane];
    float4 v1 = xr[lane + 32];
    float s  = v0.x + v0.y + v0.z + v0.w + v1.x + v1.y + v1.z + v1.w;
    float s2 = v0.x*v0.x + v0.y*v0.y + v0.z*v0.z + v0.w*v0.w
             + v1.x*v1.x + v1.y*v1.y + v1.z*v1.z + v1.w*v1.w;
    #pragma unroll
    for (int o = 16; o; o >>= 1) {
        s  += __shfl_xor_sync(0xffffffffu, s,  o);
        s2 += __shfl_xor_sync(0xffffffffu, s2, o);
    }
    float mean = s * (1.0f / DIM);
    float var = s2 * (1.0f / DIM) - mean * mean;
    float rstd = rsqrtf(fmaxf(var, 0.0f) + LNEPS);
    const float4* g4 = (const float4*)g;
    const float4* b4 = (const float4*)b;
    float4* yr = (float4*)(y + row * DIM);
    float4 ga = g4[lane], bb = b4[lane];
    float4 o0;
    o0.x = (v0.x - mean) * rstd * ga.x + bb.x;
    o0.y = (v0.y - mean) * rstd * ga.y + bb.y;
    o0.z = (v0.z - mean) * rstd * ga.z + bb.z;
    o0.w = (v0.w - mean) * rstd * ga.w + bb.w;
    yr[lane] = o0;
    ga = g4[lane + 32]; bb = b4[lane + 32];
    float4 o1;
    o1.x = (v1.x - mean) * rstd * ga.x + bb.x;
    o1.y = (v1.y - mean) * rstd * ga.y + bb.y;
    o1.z = (v1.z - mean) * rstd * ga.z + bb.z;
    o1.w = (v1.w - mean) * rstd * ga.w + bb.w;
    yr[lane + 32] = o1;
}

__global__ void transpose_proj_kernel(const float* __restrict__ proj,
                                      float* __restrict__ pT_hi,
                                      float* __restrict__ pT_lo)
{
    int m = blockIdx.x;
    int d = threadIdx.x;
    float v = proj[(long)m * DH + d];
    float hi = cvt_tf32(v);
    pT_hi[(long)d * NBF + m] = hi;
    pT_lo[(long)d * NBF + m] = cvt_tf32(v - hi);
}

__global__ void head_kernel(const float* __restrict__ y,
                            const float* __restrict__ w,
                            const float* __restrict__ bb,
                            float* __restrict__ out)
{
    int warp = threadIdx.x >> 5, lane = threadIdx.x & 31;
    long row = (long)blockIdx.x * 8 + warp;
    const float* yr = y + row * DIM;
    float s = 0.0f;
    #pragma unroll
    for (int i = 0; i < 8; i++) s += yr[lane + i * 32] * w[lane + i * 32];
    #pragma unroll
    for (int o = 16; o; o >>= 1) s += __shfl_xor_sync(0xffffffffu, s, o);
    if (lane == 0) out[row] = s + bb[0];
}

// ---------------- host ----------------
template<int BN, int WN>
static inline void launch_tgemm(cudaStream_t st, int M, int N, int K,
    const float* A, int a_rs, int a_cs, long a_so, long a_si,
    const float* B, int b_ks, long b_so, long b_si,
    float* C, int c_rs, long c_so, long c_si,
    const float* bias, float alpha, int beta, int epi, int nbatch, int nsplit)
{
    dim3 grid(N / BN, M / 128, nbatch * nsplit);
    tgemm_kernel<BN, WN><<<grid, 128, 0, st>>>(M, N, K, A, a_rs, a_cs, a_so, a_si,
                                        B, b_ks, b_so, b_si, C, c_rs, c_so, c_si,
                                        bias, alpha, beta, epi, nsplit);
}

extern "C" void kernel_launch(void* const* d_in, const int* in_sizes, int n_in,
                              void* d_out, int out_size)
{
    const float* x        = (const float*)d_in[0];
    const float* mlp_w1   = (const float*)d_in[1];
    const float* mlp_b1   = (const float*)d_in[2];
    const float* mlp_w2   = (const float*)d_in[3];
    const float* mlp_b2   = (const float*)d_in[4];
    const float* pos      = (const float*)d_in[5];
    const float* gnn_emb  = (const float*)d_in[6];
    const float* gnn_w    = (const float*)d_in[7];
    const float* gnn_b    = (const float*)d_in[8];
    const float* ew       = (const float*)d_in[9];
    const float* proj     = (const float*)d_in[10];
    const float* ln1_g    = (const float*)d_in[11];
    const float* ln1_b    = (const float*)d_in[12];
    const float* wq       = (const float*)d_in[13];
    const float* wk       = (const float*)d_in[14];
    const float* wv       = (const float*)d_in[15];
    const float* wo       = (const float*)d_in[16];
    const float* bo       = (const float*)d_in[17];
    const float* ln2_g    = (const float*)d_in[18];
    const float* ln2_b    = (const float*)d_in[19];
    const float* ffw1     = (const float*)d_in[20];
    const float* ffb1     = (const float*)d_in[21];
    const float* ffw2     = (const float*)d_in[22];
    const float* ffb2     = (const float*)d_in[23];
    const float* normf_g  = (const float*)d_in[24];
    const float* normf_b  = (const float*)d_in[25];
    const float* out_w    = (const float*)d_in[26];
    const float* out_b    = (const float*)d_in[27];
    const int*   ei       = (const int*)d_in[28];
    float* out            = (float*)d_out;

    float *z, *y, *qkv, *wqkv, *o, *ff, *qf, *kf, *agg, *go, *deg, *dinv;
    float *ksum, *ctx, *kdiag, *pT_hi, *pT_lo;
    unsigned* stab_u;
    cudaGetSymbolAddress((void**)&z, g_z);
    cudaGetSymbolAddress((void**)&y, g_y);
    cudaGetSymbolAddress((void**)&qkv, g_qkv);
    cudaGetSymbolAddress((void**)&wqkv, g_wqkv);
    cudaGetSymbolAddress((void**)&o, g_o);
    cudaGetSymbolAddress((void**)&ff, g_ff);
    cudaGetSymbolAddress((void**)&qf, g_qf);
    cudaGetSymbolAddress((void**)&kf, g_kf);
    cudaGetSymbolAddress((void**)&agg, g_agg);
    cudaGetSymbolAddress((void**)&go, g_go);
    cudaGetSymbolAddress((void**)&deg, g_deg);
    cudaGetSymbolAddress((void**)&dinv, g_dinv);
    cudaGetSymbolAddress((void**)&stab_u, g_stab_u);
    cudaGetSymbolAddress((void**)&ksum, g_ksum);
    cudaGetSymbolAddress((void**)&ctx, g_ctx);
    cudaGetSymbolAddress((void**)&kdiag, g_kdiag);
    cudaGetSymbolAddress((void**)&pT_hi, g_pT_hi);
    cudaGetSymbolAddress((void**)&pT_lo, g_pT_lo);

    static cudaStream_t sA = nullptr, sB = nullptr;
    static cudaEvent_t evs[32];
    if (sA == nullptr) {
        cudaStreamCreateWithFlags(&sA, cudaStreamNonBlocking);
        cudaStreamCreateWithFlags(&sB, cudaStreamNonBlocking);
        for (int i = 0; i < 32; i++)
            cudaEventCreateWithFlags(&evs[i], cudaEventDisableTiming);
    }
    cudaStream_t s0 = cudaStreamPerThread;
    int ne = 0;
    auto fork_to = [&](cudaStream_t dst) {
        cudaEventRecord(evs[ne], s0);
        cudaStreamWaitEvent(dst, evs[ne], 0);
        ne++;
    };
    auto join_from = [&](cudaStream_t src) {
        cudaEventRecord(evs[ne], src);
        cudaStreamWaitEvent(s0, evs[ne], 0);
        ne++;
    };

    // ---- prologue ----
    zero_kernel<<<64, 256, 0, s0>>>(deg, NN);
    zero_kernel<<<1024, 256, 0, s0>>>(agg, (long)NN * DIM);
    deg_kernel<<<EEDG / 256, 256, 0, s0>>>(ei, ew, deg);
    dinv_kernel<<<NN / 256, 256, 0, s0>>>(deg, dinv);
    fork_to(sB);
    embed_kernel<<<ROWS, DIM, 0, sB>>>(x, mlp_w1, mlp_b1, y);
    launch_tgemm<128, 64>(sB, ROWS, DIM, DIM, y, DIM, 1, 0, 0, mlp_w2, DIM, 0, 0,
                          z, DIM, 0, 0, mlp_b2, 1.0f, 0, 0, 1, 1);
    transpose_proj_kernel<<<NBF, DH, 0, s0>>>(proj, pT_hi, pT_lo);
    agg_kernel<<<EEDG, DIM, 0, s0>>>(ei, ew, dinv, gnn_emb, agg);
    launch_tgemm<128, 64>(s0, NN, DIM, DIM, agg, DIM, 1, 0, 0, gnn_w, DIM, 0, 0,
                          go, DIM, 0, 0, gnn_b, 1.0f, 0, 0, 1, 1);
    join_from(sB);
    zadd_kernel<<<ROWS, DIM, 0, s0>>>(z, pos, go);

    // ---- transformer layers ----
    for (int l = 0; l < 2; l++) {
        const float* wq_l   = wq  + (long)l * DIM * INNER;
        const float* wk_l   = wk  + (long)l * DIM * INNER;
        const float* wv_l   = wv  + (long)l * DIM * INNER;
        const float* wo_l   = wo  + (long)l * INNER * DIM;
        const float* bo_l   = bo  + (long)l * DIM;
        const float* ffw1_l = ffw1 + (long)l * DIM * FFD;
        const float* ffb1_l = ffb1 + (long)l * FFD;
        const float* ffw2_l = ffw2 + (long)l * FFD * DIM;
        const float* ffb2_l = ffb2 + (long)l * DIM;

        fork_to(sA);
        concat_w_kernel<<<DIM, 512, 0, sA>>>(wq_l, wk_l, wv_l, wqkv);
        ln_kernel<<<ROWS / 8, 256, 0, s0>>>(z, ln1_g + l * DIM, ln1_b + l * DIM, y);
        join_from(sA);

        launch_tgemm<128, 64>(s0, ROWS, QKVN, DIM, y, DIM, 1, 0, 0, wqkv, QKVN, 0, 0,
                              qkv, QKVN, 0, 0, nullptr, 1.0f, 0, 0, 1, 1);

        // favor_q fully parallel on sA (only needs qkv + proj)
        fork_to(sA);
        favor_gemm_kernel<0><<<dim3(NN / 64, BH), 256, 0, sA>>>(
            qkv, pT_hi, pT_lo, qf, nullptr, nullptr);

        // ctx-zero off-path
        fork_to(sB);
        zero_kernel<<<256, 256, 0, sB>>>(ctx, (long)BH * NBF * DH);

        // K path on s0
        zks_kernel<<<16, 256, 0, s0>>>(ksum, stab_u);
        favor_gemm_kernel<1><<<dim3(NN / 64, BH), 256, 0, s0>>>(
            qkv + 512, pT_hi, pT_lo, kf, stab_u, kdiag);

        join_from(sB);
        ctxk_kernel<<<dim3(1, 2, BH * CTX_NSPLIT), 128, 0, s0>>>(
            kf, qkv + 1024, kdiag, stab_u, ctx, ksum);

        join_from(sA);
        attn_kernel<<<dim3(1, NN / 128, BH), 128, 0, s0>>>(qf, ctx, ksum, o);

        launch_tgemm<128, 64>(s0, ROWS, DIM, INNER, o, INNER, 1, 0, 0, wo_l, DIM, 0, 0,
                              z, DIM, 0, 0, bo_l, 1.0f, 1, 0, 1, 1);

        ln_kernel<<<ROWS / 8, 256, 0, s0>>>(z, ln2_g + l * DIM, ln2_b + l * DIM, y);
        launch_tgemm<128, 64>(s0, ROWS, FFD, DIM, y, DIM, 1, 0, 0, ffw1_l, FFD, 0, 0,
                              ff, FFD, 0, 0, ffb1_l, 1.0f, 0, 2, 1, 1);
        launch_tgemm<128, 64>(s0, ROWS, DIM, FFD, ff, FFD, 1, 0, 0, ffw2_l, DIM, 0, 0,
                              z, DIM, 0, 0, ffb2_l, 1.0f, 1, 0, 1, 1);
    }

    // ---- final LN + head ----
    ln_kernel<<<ROWS / 8, 256, 0, s0>>>(z, normf_g, normf_b, y);
    head_kernel<<<ROWS / 8, 256, 0, s0>>>(y, out_w, out_b, out);
}

// round 9
// speedup vs baseline: 32.3205x; 1.0757x over previous
#include <cuda_runtime.h>
#include <cuda_bf16.h>
#include <math.h>
#include <stdint.h>

// ---------------- problem constants ----------------
#define BSZ    2
#define NN     8192
#define DIM    256
#define HEADS  8
#define DH     64
#define INNER  512
#define QKVN   1536
#define NBF    256
#define FFD    1024
#define EEDG   131072
#define ROWS   (BSZ*NN)
#define BH     (BSZ*HEADS)
#define KEPS   1e-4f
#define LNEPS  1e-5f
#define DN     0.3535533905932738f
#define RATIO  0.0625f

// ---------------- scratch ----------------
__device__ float g_z[ROWS*DIM];
__device__ float g_y[ROWS*DIM];
__device__ float g_qkv[(size_t)ROWS*QKVN];
__device__ float g_wqkv[DIM*QKVN];
__device__ float g_o[ROWS*INNER];
__device__ float g_ff[(size_t)ROWS*FFD];
__device__ float g_qf[(size_t)BH*NN*NBF];
__device__ float g_kf[(size_t)BH*NN*NBF];     // raw dd for K
__device__ float g_agg[NN*DIM];
__device__ float g_go[NN*DIM];
__device__ float g_deg[NN];
__device__ float g_dinv[NN];
__device__ unsigned g_stab_u[BH];
__device__ float g_ksum[BH*NBF];
__device__ float g_ctx[BH*NBF*DH];
__device__ float g_kdiag[BH*NN];
__device__ __nv_bfloat16 g_pb_hi[NBF*DH];
__device__ __nv_bfloat16 g_pb_lo[NBF*DH];

__device__ __forceinline__ float gelu_f(float v) {
    const float c = 0.7978845608028654f;
    float t = tanhf(c * (v + 0.044715f * v * v * v));
    return 0.5f * v * (1.0f + t);
}

__device__ __forceinline__ float cvt_tf32(float x) {
    uint32_t u;
    asm("cvt.rna.tf32.f32 %0, %1;" : "=r"(u) : "f"(x));
    return __uint_as_float(u);
}

__device__ __forceinline__ unsigned fkey(float f) {
    unsigned b = __float_as_uint(f);
    return (b & 0x80000000u) ? ~b : (b | 0x80000000u);
}
__device__ __forceinline__ float fkey_inv(unsigned u) {
    unsigned b = (u & 0x80000000u) ? (u ^ 0x80000000u) : ~u;
    return __uint_as_float(b);
}

__device__ __forceinline__ void mma_tf32(float* c, const uint32_t* a,
                                         uint32_t b0, uint32_t b1) {
    asm volatile(
        "mma.sync.aligned.m16n8k8.row.col.f32.tf32.tf32.f32 "
        "{%0,%1,%2,%3}, {%4,%5,%6,%7}, {%8,%9}, {%0,%1,%2,%3};\n"
        : "+f"(c[0]), "+f"(c[1]), "+f"(c[2]), "+f"(c[3])
        : "r"(a[0]), "r"(a[1]), "r"(a[2]), "r"(a[3]), "r"(b0), "r"(b1));
}

__device__ __forceinline__ void mma_bf16(float* c, const uint32_t* a,
                                         uint32_t b0, uint32_t b1) {
    asm volatile(
        "mma.sync.aligned.m16n8k16.row.col.f32.bf16.bf16.f32 "
        "{%0,%1,%2,%3}, {%4,%5,%6,%7}, {%8,%9}, {%0,%1,%2,%3};\n"
        : "+f"(c[0]), "+f"(c[1]), "+f"(c[2]), "+f"(c[3])
        : "r"(a[0]), "r"(a[1]), "r"(a[2]), "r"(a[3]), "r"(b0), "r"(b1));
}

// =====================================================================
// tf32 tensor-core GEMM (residual-stream GEMMs). Block 128 x BN, 4 warps.
// =====================================================================
template<int BN, int WN>
__global__ __launch_bounds__(128)
void tgemm_kernel(int M, int N, int K,
                  const float* __restrict__ A, int a_rs, int a_cs, long a_so, long a_si,
                  const float* __restrict__ B, int b_ks, long b_so, long b_si,
                  float* __restrict__ C, int c_rs, long c_so, long c_si,
                  const float* __restrict__ bias,
                  float alpha, int beta, int epi, int nsplit)
{
    constexpr int BK = 16;
    constexpr int SA = 136;
    constexpr int SB = BN + 8;
    constexpr int NI = WN / 8;
    constexpr int NBL = BN / 32;
    __shared__ float As[2][BK][SA];
    __shared__ float Bs[2][BK][SB];

    int zz = blockIdx.z;
    int batch = zz / nsplit;
    int split = zz - batch * nsplit;
    long aoff = (long)(batch >> 3) * a_so + (long)(batch & 7) * a_si;
    long boff = (long)(batch >> 3) * b_so + (long)(batch & 7) * b_si;
    long coff = (long)(batch >> 3) * c_so + (long)(batch & 7) * c_si;
    int row0 = blockIdx.y * 128;
    int col0 = blockIdx.x * BN;
    int kchunk = K / nsplit;
    int kbeg = split * kchunk;
    int kend = kbeg + kchunk;

    int tid = threadIdx.x;
    int lane = tid & 31;
    int warp = tid >> 5;
    int m_warp = (warp >> 1) * 64;
    int n_warp = (warp & 1) * WN;

    float c[4][NI][4];
    #pragma unroll
    for (int i = 0; i < 4; i++)
        #pragma unroll
        for (int j = 0; j < NI; j++)
            #pragma unroll
            for (int t = 0; t < 4; t++) c[i][j][t] = 0.0f;

    float4 ra[4];
    float4 rb[NBL];

    auto loadA = [&](int kt) {
        if (a_cs == 1) {
            #pragma unroll
            for (int i = 0; i < 4; i++) {
                int idx = tid + i * 128;
                int m = idx >> 2;
                int kc = (idx & 3) * 4;
                ra[i] = *(const float4*)(A + aoff + (long)(row0 + m) * a_rs + kt + kc);
            }
        } else {
            #pragma unroll
            for (int i = 0; i < 4; i++) {
                int idx = tid + i * 128;
                int m4 = (idx & 31) * 4;
                int kk = idx >> 5;
                ra[i] = *(const float4*)(A + aoff + (long)(kt + kk) * a_cs + row0 + m4);
            }
        }
    };
    auto storeA = [&](int bf) {
        if (a_cs == 1) {
            #pragma unroll
            for (int i = 0; i < 4; i++) {
                int idx = tid + i * 128;
                int m = idx >> 2;
                int kc = (idx & 3) * 4;
                float v[4] = {ra[i].x, ra[i].y, ra[i].z, ra[i].w};
                #pragma unroll
                for (int j0 = 0; j0 < 4; j0++) {
                    int j = (j0 + lane) & 3;
                    As[bf][kc + j][m] = cvt_tf32(v[j]);
                }
            }
        } else {
            #pragma unroll
            for (int i = 0; i < 4; i++) {
                int idx = tid + i * 128;
                int m4 = (idx & 31) * 4;
                int kk = idx >> 5;
                float4 t;
                t.x = cvt_tf32(ra[i].x); t.y = cvt_tf32(ra[i].y);
                t.z = cvt_tf32(ra[i].z); t.w = cvt_tf32(ra[i].w);
                *(float4*)&As[bf][kk][m4] = t;
            }
        }
    };
    auto loadB = [&](int kt) {
        #pragma unroll
        for (int i = 0; i < NBL; i++) {
            int idx = tid + i * 128;
            int n4 = (idx & (BN / 4 - 1)) * 4;
            int kk = idx / (BN / 4);
            rb[i] = *(const float4*)(B + boff + (long)(kt + kk) * b_ks + col0 + n4);
        }
    };
    auto storeB = [&](int bf) {
        #pragma unroll
        for (int i = 0; i < NBL; i++) {
            int idx = tid + i * 128;
            int n4 = (idx & (BN / 4 - 1)) * 4;
            int kk = idx / (BN / 4);
            float4 t;
            t.x = cvt_tf32(rb[i].x); t.y = cvt_tf32(rb[i].y);
            t.z = cvt_tf32(rb[i].z); t.w = cvt_tf32(rb[i].w);
            *(float4*)&Bs[bf][kk][n4] = t;
        }
    };
    auto compute = [&](int bf) {
        #pragma unroll
        for (int s = 0; s < 2; s++) {
            int k8 = s * 8;
            uint32_t af[4][4];
            #pragma unroll
            for (int mi = 0; mi < 4; mi++) {
                int mr = m_warp + mi * 16 + (lane >> 2);
                af[mi][0] = __float_as_uint(As[bf][k8 + (lane & 3)][mr]);
                af[mi][1] = __float_as_uint(As[bf][k8 + (lane & 3)][mr + 8]);
                af[mi][2] = __float_as_uint(As[bf][k8 + 4 + (lane & 3)][mr]);
                af[mi][3] = __float_as_uint(As[bf][k8 + 4 + (lane & 3)][mr + 8]);
            }
            #pragma unroll
            for (int ni = 0; ni < NI; ni++) {
                int nc = n_warp + ni * 8 + (lane >> 2);
                uint32_t b0 = __float_as_uint(Bs[bf][k8 + (lane & 3)][nc]);
                uint32_t b1 = __float_as_uint(Bs[bf][k8 + 4 + (lane & 3)][nc]);
                #pragma unroll
                for (int mi = 0; mi < 4; mi++)
                    mma_tf32(c[mi][ni], af[mi], b0, b1);
            }
        }
    };

    loadA(kbeg); loadB(kbeg);
    storeA(0);   storeB(0);
    __syncthreads();
    int buf = 0;
    for (int kt = kbeg; kt < kend; kt += BK) {
        bool has_next = (kt + BK) < kend;
        if (has_next) { loadA(kt + BK); loadB(kt + BK); }
        compute(buf);
        if (has_next) {
            storeA(buf ^ 1); storeB(buf ^ 1);
            __syncthreads();
            buf ^= 1;
        }
    }

    #pragma unroll
    for (int mi = 0; mi < 4; mi++) {
        int r = row0 + m_warp + mi * 16 + (lane >> 2);
        long crow0 = coff + (long)r * c_rs;
        long crow1 = coff + (long)(r + 8) * c_rs;
        #pragma unroll
        for (int ni = 0; ni < NI; ni++) {
            int cc = col0 + n_warp + ni * 8 + 2 * (lane & 3);
            float v0 = alpha * c[mi][ni][0];
            float v1 = alpha * c[mi][ni][1];
            float v2 = alpha * c[mi][ni][2];
            float v3 = alpha * c[mi][ni][3];
            if (nsplit > 1) {
                atomicAdd(C + crow0 + cc,     v0);
                atomicAdd(C + crow0 + cc + 1, v1);
                atomicAdd(C + crow1 + cc,     v2);
                atomicAdd(C + crow1 + cc + 1, v3);
            } else {
                if (bias) {
                    float2 bb = *(const float2*)(bias + cc);
                    v0 += bb.x; v1 += bb.y; v2 += bb.x; v3 += bb.y;
                }
                if (epi == 1) {
                    v0 = fmaxf(v0, 0.f); v1 = fmaxf(v1, 0.f);
                    v2 = fmaxf(v2, 0.f); v3 = fmaxf(v3, 0.f);
                } else if (epi == 2) {
                    v0 = gelu_f(v0); v1 = gelu_f(v1);
                    v2 = gelu_f(v2); v3 = gelu_f(v3);
                }
                if (beta) {
                    float2 c0 = *(const float2*)(C + crow0 + cc);
                    float2 c1 = *(const float2*)(C + crow1 + cc);
                    v0 += c0.x; v1 += c0.y; v2 += c1.x; v3 += c1.y;
                }
                *(float2*)(C + crow0 + cc) = make_float2(v0, v1);
                *(float2*)(C + crow1 + cc) = make_float2(v2, v3);
            }
        }
    }
}

// =====================================================================
// ctxk: ctx[bh] += kf^T @ v with kf computed inline from raw dd.
// =====================================================================
#define CTX_NSPLIT 32
__global__ __launch_bounds__(128)
void ctxk_kernel(const float* __restrict__ dd,
                 const float* __restrict__ vsrc,
                 const float* __restrict__ kdiag,
                 const unsigned* __restrict__ stab_u,
                 float* __restrict__ ctx,
                 float* __restrict__ ksum)
{
    constexpr int BK = 16;
    __shared__ float As[2][BK][136];
    __shared__ float Bs[2][BK][72];

    int zz = blockIdx.z;
    int batch = zz / CTX_NSPLIT;
    int split = zz - batch * CTX_NSPLIT;
    long aoff = (long)batch * NN * NBF;
    long boff = (long)(batch >> 3) * NN * QKVN + (long)(batch & 7) * DH;
    long coff = (long)batch * NBF * DH;
    const float* kdg = kdiag + (long)batch * NN;
    float stab = fkey_inv(stab_u[batch]);

    int row0 = blockIdx.y * 128;
    int kbeg = split * (NN / CTX_NSPLIT);
    int kend = kbeg + NN / CTX_NSPLIT;

    int tid = threadIdx.x;
    int lane = tid & 31;
    int warp = tid >> 5;
    int m_warp = (warp >> 1) * 64;
    int n_warp = (warp & 1) * 32;

    float c[4][4][4];
    #pragma unroll
    for (int i = 0; i < 4; i++)
        #pragma unroll
        for (int j = 0; j < 4; j++)
            #pragma unroll
            for (int t = 0; t < 4; t++) c[i][j][t] = 0.0f;

    float ks_acc[4] = {0.f, 0.f, 0.f, 0.f};
    float4 ra[4];
    float4 rb[2];

    auto loadA = [&](int kt) {
        #pragma unroll
        for (int i = 0; i < 4; i++) {
            int idx = tid + i * 128;
            int m4 = (idx & 31) * 4;
            int kk = idx >> 5;
            ra[i] = *(const float4*)(dd + aoff + (long)(kt + kk) * NBF + row0 + m4);
        }
    };
    auto storeA = [&](int bf, int kt) {
        #pragma unroll
        for (int i = 0; i < 4; i++) {
            int idx = tid + i * 128;
            int m4 = (idx & 31) * 4;
            int kk = idx >> 5;
            float sub = kdg[kt + kk] + stab;
            float k0 = RATIO * (expf(ra[i].x - sub) + KEPS);
            float k1 = RATIO * (expf(ra[i].y - sub) + KEPS);
            float k2 = RATIO * (expf(ra[i].z - sub) + KEPS);
            float k3 = RATIO * (expf(ra[i].w - sub) + KEPS);
            ks_acc[0] += k0; ks_acc[1] += k1; ks_acc[2] += k2; ks_acc[3] += k3;
            float4 t;
            t.x = cvt_tf32(k0); t.y = cvt_tf32(k1);
            t.z = cvt_tf32(k2); t.w = cvt_tf32(k3);
            *(float4*)&As[bf][kk][m4] = t;
        }
    };
    auto loadB = [&](int kt) {
        #pragma unroll
        for (int i = 0; i < 2; i++) {
            int idx = tid + i * 128;
            int n4 = (idx & 15) * 4;
            int kk = idx >> 4;
            rb[i] = *(const float4*)(vsrc + boff + (long)(kt + kk) * QKVN + n4);
        }
    };
    auto storeB = [&](int bf) {
        #pragma unroll
        for (int i = 0; i < 2; i++) {
            int idx = tid + i * 128;
            int n4 = (idx & 15) * 4;
            int kk = idx >> 4;
            float4 t;
            t.x = cvt_tf32(rb[i].x); t.y = cvt_tf32(rb[i].y);
            t.z = cvt_tf32(rb[i].z); t.w = cvt_tf32(rb[i].w);
            *(float4*)&Bs[bf][kk][n4] = t;
        }
    };
    auto compute = [&](int bf) {
        #pragma unroll
        for (int s = 0; s < 2; s++) {
            int k8 = s * 8;
            uint32_t af[4][4];
            #pragma unroll
            for (int mi = 0; mi < 4; mi++) {
                int mr = m_warp + mi * 16 + (lane >> 2);
                af[mi][0] = __float_as_uint(As[bf][k8 + (lane & 3)][mr]);
                af[mi][1] = __float_as_uint(As[bf][k8 + (lane & 3)][mr + 8]);
                af[mi][2] = __float_as_uint(As[bf][k8 + 4 + (lane & 3)][mr]);
                af[mi][3] = __float_as_uint(As[bf][k8 + 4 + (lane & 3)][mr + 8]);
            }
            #pragma unroll
            for (int ni = 0; ni < 4; ni++) {
                int nc = n_warp + ni * 8 + (lane >> 2);
                uint32_t b0 = __float_as_uint(Bs[bf][k8 + (lane & 3)][nc]);
                uint32_t b1 = __float_as_uint(Bs[bf][k8 + 4 + (lane & 3)][nc]);
                #pragma unroll
                for (int mi = 0; mi < 4; mi++)
                    mma_tf32(c[mi][ni], af[mi], b0, b1);
            }
        }
    };

    loadA(kbeg); loadB(kbeg);
    storeA(0, kbeg); storeB(0);
    __syncthreads();
    int buf = 0;
    for (int kt = kbeg; kt < kend; kt += BK) {
        bool has_next = (kt + BK) < kend;
        if (has_next) { loadA(kt + BK); loadB(kt + BK); }
        compute(buf);
        if (has_next) {
            storeA(buf ^ 1, kt + BK); storeB(buf ^ 1);
            __syncthreads();
            buf ^= 1;
        }
    }

    {
        int m4 = (tid & 31) * 4;
        #pragma unroll
        for (int j = 0; j < 4; j++)
            atomicAdd(&ksum[(long)batch * NBF + row0 + m4 + j], ks_acc[j]);
    }

    #pragma unroll
    for (int mi = 0; mi < 4; mi++) {
        int r = row0 + m_warp + mi * 16 + (lane >> 2);
        long crow0 = coff + (long)r * DH;
        long crow1 = coff + (long)(r + 8) * DH;
        #pragma unroll
        for (int ni = 0; ni < 4; ni++) {
            int cc = n_warp + ni * 8 + 2 * (lane & 3);
            atomicAdd(ctx + crow0 + cc,     c[mi][ni][0]);
            atomicAdd(ctx + crow0 + cc + 1, c[mi][ni][1]);
            atomicAdd(ctx + crow1 + cc,     c[mi][ni][2]);
            atomicAdd(ctx + crow1 + cc + 1, c[mi][ni][3]);
        }
    }
}

// =====================================================================
// attn: o = (qf @ ctx) / (qf . ksum), denom computed inline.
// =====================================================================
__global__ __launch_bounds__(128)
void attn_kernel(const float* __restrict__ qf,
                 const float* __restrict__ ctx,
                 const float* __restrict__ ksum,
                 float* __restrict__ o)
{
    constexpr int BK = 16;
    __shared__ float As[2][BK][136];
    __shared__ float Bs[2][BK][72];
    __shared__ float ksum_s[NBF];
    __shared__ float denom_s[128];

    int batch = blockIdx.z;
    long aoff = (long)batch * NN * NBF;
    long boff = (long)batch * NBF * DH;
    long coff = (long)(batch >> 3) * NN * INNER + (long)(batch & 7) * DH;
    int row0 = blockIdx.y * 128;

    int tid = threadIdx.x;
    int lane = tid & 31;
    int warp = tid >> 5;
    int m_warp = (warp >> 1) * 64;
    int n_warp = (warp & 1) * 32;

    ksum_s[tid] = ksum[(long)batch * NBF + tid];
    ksum_s[tid + 128] = ksum[(long)batch * NBF + tid + 128];
    denom_s[tid] = 0.0f;
    __syncthreads();

    float c[4][4][4];
    #pragma unroll
    for (int i = 0; i < 4; i++)
        #pragma unroll
        for (int j = 0; j < 4; j++)
            #pragma unroll
            for (int t = 0; t < 4; t++) c[i][j][t] = 0.0f;

    float dacc[4] = {0.f, 0.f, 0.f, 0.f};
    float4 ra[4];
    float4 rb[2];

    auto loadA = [&](int kt) {
        #pragma unroll
        for (int i = 0; i < 4; i++) {
            int idx = tid + i * 128;
            int m = idx >> 2;
            int kc = (idx & 3) * 4;
            ra[i] = *(const float4*)(qf + aoff + (long)(row0 + m) * NBF + kt + kc);
        }
    };
    auto storeA = [&](int bf, int kt) {
        #pragma unroll
        for (int i = 0; i < 4; i++) {
            int idx = tid + i * 128;
            int m = idx >> 2;
            int kc = (idx & 3) * 4;
            float v[4] = {ra[i].x, ra[i].y, ra[i].z, ra[i].w};
            dacc[i] += v[0] * ksum_s[kt + kc] + v[1] * ksum_s[kt + kc + 1]
                     + v[2] * ksum_s[kt + kc + 2] + v[3] * ksum_s[kt + kc + 3];
            #pragma unroll
            for (int j0 = 0; j0 < 4; j0++) {
                int j = (j0 + lane) & 3;
                As[bf][kc + j][m] = cvt_tf32(v[j]);
            }
        }
    };
    auto loadB = [&](int kt) {
        #pragma unroll
        for (int i = 0; i < 2; i++) {
            int idx = tid + i * 128;
            int n4 = (idx & 15) * 4;
            int kk = idx >> 4;
            rb[i] = *(const float4*)(ctx + boff + (long)(kt + kk) * DH + n4);
        }
    };
    auto storeB = [&](int bf) {
        #pragma unroll
        for (int i = 0; i < 2; i++) {
            int idx = tid + i * 128;
            int n4 = (idx & 15) * 4;
            int kk = idx >> 4;
            float4 t;
            t.x = cvt_tf32(rb[i].x); t.y = cvt_tf32(rb[i].y);
            t.z = cvt_tf32(rb[i].z); t.w = cvt_tf32(rb[i].w);
            *(float4*)&Bs[bf][kk][n4] = t;
        }
    };
    auto compute = [&](int bf) {
        #pragma unroll
        for (int s = 0; s < 2; s++) {
            int k8 = s * 8;
            uint32_t af[4][4];
            #pragma unroll
            for (int mi = 0; mi < 4; mi++) {
                int mr = m_warp + mi * 16 + (lane >> 2);
                af[mi][0] = __float_as_uint(As[bf][k8 + (lane & 3)][mr]);
                af[mi][1] = __float_as_uint(As[bf][k8 + (lane & 3)][mr + 8]);
                af[mi][2] = __float_as_uint(As[bf][k8 + 4 + (lane & 3)][mr]);
                af[mi][3] = __float_as_uint(As[bf][k8 + 4 + (lane & 3)][mr + 8]);
            }
            #pragma unroll
            for (int ni = 0; ni < 4; ni++) {
                int nc = n_warp + ni * 8 + (lane >> 2);
                uint32_t b0 = __float_as_uint(Bs[bf][k8 + (lane & 3)][nc]);
                uint32_t b1 = __float_as_uint(Bs[bf][k8 + 4 + (lane & 3)][nc]);
                #pragma unroll
                for (int mi = 0; mi < 4; mi++)
                    mma_tf32(c[mi][ni], af[mi], b0, b1);
            }
        }
    };

    loadA(0); loadB(0);
    storeA(0, 0); storeB(0);
    __syncthreads();
    int buf = 0;
    for (int kt = 0; kt < NBF; kt += BK) {
        bool has_next = (kt + BK) < NBF;
        if (has_next) { loadA(kt + BK); loadB(kt + BK); }
        compute(buf);
        if (has_next) {
            storeA(buf ^ 1, kt + BK); storeB(buf ^ 1);
            __syncthreads();
            buf ^= 1;
        }
    }

    #pragma unroll
    for (int i = 0; i < 4; i++) {
        int m = (tid + i * 128) >> 2;
        atomicAdd(&denom_s[m], dacc[i]);
    }
    __syncthreads();

    #pragma unroll
    for (int mi = 0; mi < 4; mi++) {
        int lr = m_warp + mi * 16 + (lane >> 2);
        float rdv0 = 1.0f / denom_s[lr];
        float rdv1 = 1.0f / denom_s[lr + 8];
        long crow0 = coff + (long)(row0 + lr) * INNER;
        long crow1 = coff + (long)(row0 + lr + 8) * INNER;
        #pragma unroll
        for (int ni = 0; ni < 4; ni++) {
            int cc = n_warp + ni * 8 + 2 * (lane & 3);
            *(float2*)(o + crow0 + cc) = make_float2(c[mi][ni][0] * rdv0, c[mi][ni][1] * rdv0);
            *(float2*)(o + crow1 + cc) = make_float2(c[mi][ni][2] * rdv1, c[mi][ni][3] * rdv1);
        }
    }
}

// =====================================================================
// FAVOR feature kernel, bf16x3 (m16n8k16): block 256 thr, 64 rows x 256 feats.
// A(64x64) and B(256x64) hi/lo staged once in dynamic smem; 4 pure MMA steps.
// MODE 0 (Q): qf = ratio*(exp(dd-diag-rowmax)+keps).
// MODE 1 (K): raw dd -> outf, kdiag, block-max -> atomicMax(stab key).
// =====================================================================
#define FAVOR_SMEM 93696

template<int MODE>
__global__ __launch_bounds__(256, 2)
void favor_gemm_kernel(const float* __restrict__ qk,
                       const __nv_bfloat16* __restrict__ pb_hi,
                       const __nv_bfloat16* __restrict__ pb_lo,
                       float* __restrict__ outf,
                       unsigned* __restrict__ stab_u,
                       float* __restrict__ kdiag)
{
    extern __shared__ __align__(16) char smraw[];
    __nv_bfloat16* As_hi = (__nv_bfloat16*)(smraw);            // [64][72]
    __nv_bfloat16* As_lo = (__nv_bfloat16*)(smraw + 9216);
    __nv_bfloat16* Bs_hi = (__nv_bfloat16*)(smraw + 18432);    // [256][72]
    __nv_bfloat16* Bs_lo = (__nv_bfloat16*)(smraw + 55296);
    float* diag_s = (float*)(smraw + 92160);                   // [64]
    float* rmax_s = (float*)(smraw + 92416);                   // [64]
    float (*red)[64] = (float(*)[64])(smraw + 92672);          // [4][64]

    int bh = blockIdx.y;
    int b = bh >> 3, h = bh & 7;
    int row0 = blockIdx.x * 64;
    const float* aptr = qk + ((long)(b * NN) + row0) * QKVN + h * DH;

    int tid = threadIdx.x;
    int lane = tid & 31, w = tid >> 5;
    int m_warp = (w >> 2) * 32;
    int n_warp = (w & 3) * 64;

    // ---- stage A (64 rows x 64 k), compute diag ----
    float sq[4];
    #pragma unroll
    for (int i = 0; i < 4; i++) {
        int f4 = tid + i * 256;
        int row = f4 >> 4;              // 0..63
        int kc = (f4 & 15) * 4;
        float4 v = *(const float4*)(aptr + (long)row * QKVN + kc);
        v.x *= DN; v.y *= DN; v.z *= DN; v.w *= DN;
        sq[i] = v.x * v.x + v.y * v.y + v.z * v.z + v.w * v.w;
        __nv_bfloat162 h0 = __floats2bfloat162_rn(v.x, v.y);
        __nv_bfloat162 h1 = __floats2bfloat162_rn(v.z, v.w);
        __nv_bfloat162 l0 = __floats2bfloat162_rn(v.x - __bfloat162float(h0.x),
                                                  v.y - __bfloat162float(h0.y));
        __nv_bfloat162 l1 = __floats2bfloat162_rn(v.z - __bfloat162float(h1.x),
                                                  v.w - __bfloat162float(h1.y));
        *(__nv_bfloat162*)&As_hi[row * 72 + kc]     = h0;
        *(__nv_bfloat162*)&As_hi[row * 72 + kc + 2] = h1;
        *(__nv_bfloat162*)&As_lo[row * 72 + kc]     = l0;
        *(__nv_bfloat162*)&As_lo[row * 72 + kc + 2] = l1;
    }
    // rows for thread: (w*2 + (lane>>4)) + i*16 ; reduce over 16 lanes
    #pragma unroll
    for (int i = 0; i < 4; i++) {
        #pragma unroll
        for (int o = 1; o < 16; o <<= 1)
            sq[i] += __shfl_xor_sync(0xffffffffu, sq[i], o);
    }
    if ((lane & 15) == 0) {
        int r0 = w * 2 + (lane >> 4);
        #pragma unroll
        for (int i = 0; i < 4; i++)
            diag_s[r0 + i * 16] = 0.5f * sq[i];
    }

    // ---- stage B (256 x 64 hi+lo) ----
    #pragma unroll
    for (int j = 0; j < 8; j++) {
        int u4 = tid + j * 256;
        int row = u4 >> 3;              // 0..255
        int c8 = (u4 & 7) * 8;
        *(uint4*)&Bs_hi[row * 72 + c8] = *(const uint4*)&pb_hi[(long)row * DH + c8];
        *(uint4*)&Bs_lo[row * 72 + c8] = *(const uint4*)&pb_lo[(long)row * DH + c8];
    }
    __syncthreads();

    float c[2][8][4];
    #pragma unroll
    for (int mi = 0; mi < 2; mi++)
        #pragma unroll
        for (int ni = 0; ni < 8; ni++)
            #pragma unroll
            for (int t = 0; t < 4; t++) c[mi][ni][t] = 0.0f;

    #pragma unroll
    for (int kt = 0; kt < 4; kt++) {
        int kb = kt * 16 + (lane & 3) * 2;
        uint32_t ah[2][4], al[2][4];
        #pragma unroll
        for (int mi = 0; mi < 2; mi++) {
            int mr = m_warp + mi * 16 + (lane >> 2);
            ah[mi][0] = *(const uint32_t*)&As_hi[mr * 72 + kb];
            ah[mi][1] = *(const uint32_t*)&As_hi[(mr + 8) * 72 + kb];
            ah[mi][2] = *(const uint32_t*)&As_hi[mr * 72 + kb + 8];
            ah[mi][3] = *(const uint32_t*)&As_hi[(mr + 8) * 72 + kb + 8];
            al[mi][0] = *(const uint32_t*)&As_lo[mr * 72 + kb];
            al[mi][1] = *(const uint32_t*)&As_lo[(mr + 8) * 72 + kb];
            al[mi][2] = *(const uint32_t*)&As_lo[mr * 72 + kb + 8];
            al[mi][3] = *(const uint32_t*)&As_lo[(mr + 8) * 72 + kb + 8];
        }
        #pragma unroll
        for (int ni = 0; ni < 8; ni++) {
            int nc = n_warp + ni * 8 + (lane >> 2);
            uint32_t bh0 = *(const uint32_t*)&Bs_hi[nc * 72 + kb];
            uint32_t bh1 = *(const uint32_t*)&Bs_hi[nc * 72 + kb + 8];
            uint32_t bl0 = *(const uint32_t*)&Bs_lo[nc * 72 + kb];
            uint32_t bl1 = *(const uint32_t*)&Bs_lo[nc * 72 + kb + 8];
            #pragma unroll
            for (int mi = 0; mi < 2; mi++) {
                mma_bf16(c[mi][ni], ah[mi], bh0, bh1);
                mma_bf16(c[mi][ni], ah[mi], bl0, bl1);
                mma_bf16(c[mi][ni], al[mi], bh0, bh1);
            }
        }
    }
    __syncthreads();   // diag_s written above; ensure visible (cheap)

    // per-row max over this warp's 64 cols
    float mx[2][2];
    #pragma unroll
    for (int mi = 0; mi < 2; mi++) {
        float mlo = -INFINITY, mhi = -INFINITY;
        #pragma unroll
        for (int ni = 0; ni < 8; ni++) {
            mlo = fmaxf(mlo, fmaxf(c[mi][ni][0], c[mi][ni][1]));
            mhi = fmaxf(mhi, fmaxf(c[mi][ni][2], c[mi][ni][3]));
        }
        #pragma unroll
        for (int o = 1; o <= 2; o <<= 1) {
            mlo = fmaxf(mlo, __shfl_xor_sync(0xffffffffu, mlo, o));
            mhi = fmaxf(mhi, __shfl_xor_sync(0xffffffffu, mhi, o));
        }
        mx[mi][0] = mlo; mx[mi][1] = mhi;
    }
    if ((lane & 3) == 0) {
        #pragma unroll
        for (int mi = 0; mi < 2; mi++) {
            int lr = m_warp + mi * 16 + (lane >> 2);
            red[w & 3][lr]     = mx[mi][0];
            red[w & 3][lr + 8] = mx[mi][1];
        }
    }
    __syncthreads();
    if (tid < 64)
        rmax_s[tid] = fmaxf(fmaxf(red[0][tid], red[1][tid]),
                            fmaxf(red[2][tid], red[3][tid]));
    __syncthreads();

    if (MODE == 1) {
        if (tid < 64)
            kdiag[(long)bh * NN + row0 + tid] = diag_s[tid];
        if (tid < 32) {
            float m = fmaxf(rmax_s[tid], rmax_s[tid + 32]);
            #pragma unroll
            for (int o = 16; o; o >>= 1)
                m = fmaxf(m, __shfl_xor_sync(0xffffffffu, m, o));
            if (tid == 0) atomicMax(&stab_u[bh], fkey(m));
        }
        #pragma unroll
        for (int mi = 0; mi < 2; mi++) {
            int rl = m_warp + mi * 16 + (lane >> 2);
            long o0 = ((long)bh * NN + row0 + rl) * NBF;
            long o1 = ((long)bh * NN + row0 + rl + 8) * NBF;
            #pragma unroll
            for (int ni = 0; ni < 8; ni++) {
                int nc = n_warp + ni * 8 + 2 * (lane & 3);
                *(float2*)(outf + o0 + nc) = make_float2(c[mi][ni][0], c[mi][ni][1]);
                *(float2*)(outf + o1 + nc) = make_float2(c[mi][ni][2], c[mi][ni][3]);
            }
        }
        return;
    }

    // Q mode: exp + write qf
    #pragma unroll
    for (int mi = 0; mi < 2; mi++) {
        int rl = m_warp + mi * 16 + (lane >> 2);
        float sub0 = diag_s[rl]     + rmax_s[rl];
        float sub1 = diag_s[rl + 8] + rmax_s[rl + 8];
        long o0 = ((long)bh * NN + row0 + rl) * NBF;
        long o1 = ((long)bh * NN + row0 + rl + 8) * NBF;
        #pragma unroll
        for (int ni = 0; ni < 8; ni++) {
            int nc = n_warp + ni * 8 + 2 * (lane & 3);
            float v0 = RATIO * (expf(c[mi][ni][0] - sub0) + KEPS);
            float v1 = RATIO * (expf(c[mi][ni][1] - sub0) + KEPS);
            float v2 = RATIO * (expf(c[mi][ni][2] - sub1) + KEPS);
            float v3 = RATIO * (expf(c[mi][ni][3] - sub1) + KEPS);
            *(float2*)(outf + o0 + nc) = make_float2(v0, v1);
            *(float2*)(outf + o1 + nc) = make_float2(v2, v3);
        }
    }
}

// ---------------- elementwise / misc kernels ----------------
__global__ void zero_kernel(float* p, long n) {
    long i = (long)blockIdx.x * blockDim.x + threadIdx.x;
    long stride = (long)gridDim.x * blockDim.x;
    for (; i < n; i += stride) p[i] = 0.0f;
}

__global__ void zks_kernel(float* __restrict__ ksum, unsigned* __restrict__ stab_u) {
    int i = blockIdx.x * 256 + threadIdx.x;
    ksum[i] = 0.0f;
    if (i < BH) stab_u[i] = 0u;
}

__global__ void concat_w_kernel(const float* __restrict__ wq,
                                const float* __restrict__ wk,
                                const float* __restrict__ wv,
                                float* __restrict__ wall)
{
    int c = blockIdx.x;
    int j = threadIdx.x;
    wall[(long)c * QKVN + j]        = wq[(long)c * INNER + j];
    wall[(long)c * QKVN + 512 + j]  = wk[(long)c * INNER + j];
    wall[(long)c * QKVN + 1024 + j] = wv[(long)c * INNER + j];
}

__global__ void embed_kernel(const float* __restrict__ x,
                             const float* __restrict__ w1,
                             const float* __restrict__ b1,
                             float* __restrict__ h)
{
    long i = blockIdx.x;
    int j = threadIdx.x;
    float v = x[i] * w1[j] + b1[j];
    h[i * DIM + j] = fmaxf(v, 0.0f);
}

__global__ void deg_kernel(const int* __restrict__ ei,
                           const float* __restrict__ ew,
                           float* __restrict__ deg)
{
    int e = blockIdx.x * blockDim.x + threadIdx.x;
    if (e < EEDG) atomicAdd(&deg[ei[EEDG + e]], ew[e]);
}

__global__ void dinv_kernel(const float* __restrict__ deg, float* __restrict__ dinv)
{
    int i = blockIdx.x * blockDim.x + threadIdx.x;
    if (i < NN) {
        float d = deg[i];
        dinv[i] = (d > 0.0f) ? rsqrtf(fmaxf(d, 1e-12f)) : 0.0f;
    }
}

__global__ void agg_kernel(const int* __restrict__ ei,
                           const float* __restrict__ ew,
                           const float* __restrict__ dinv,
                           const float* __restrict__ emb,
                           float* __restrict__ agg)
{
    int e = blockIdx.x;
    int j = threadIdx.x;
    int r = ei[e];
    int c = ei[EEDG + e];
    float w = dinv[r] * ew[e] * dinv[c];
    atomicAdd(&agg[(long)c * DIM + j], emb[(long)r * DIM + j] * w);
}

__global__ void zadd_kernel(float* __restrict__ z,
                            const float* __restrict__ pos,
                            const float* __restrict__ go)
{
    long i = blockIdx.x;
    int j = threadIdx.x;
    int n = (int)(i & (NN - 1));
    z[i * DIM + j] += pos[(long)n * DIM + j] + go[(long)n * DIM + j];
}

__global__ void ln_kernel(const float* __restrict__ x,
                          const float* __restrict__ g,
                          const float* __restrict__ b,
                          float* __restrict__ y)
{
    int warp = threadIdx.x >> 5, lane = threadIdx.x & 31;
    long row = (long)blockIdx.x * 8 + warp;
    const float4* xr = (const float4*)(x + row * DIM);
    float4 v0 = xr[lane];
    float4 v1 = xr[lane + 32];
    float s  = v0.x + v0.y + v0.z + v0.w + v1.x + v1.y + v1.z + v1.w;
    float s2 = v0.x*v0.x + v0.y*v0.y + v0.z*v0.z + v0.w*v0.w
             + v1.x*v1.x + v1.y*v1.y + v1.z*v1.z + v1.w*v1.w;
    #pragma unroll
    for (int o = 16; o; o >>= 1) {
        s  += __shfl_xor_sync(0xffffffffu, s,  o);
        s2 += __shfl_xor_sync(0xffffffffu, s2, o);
    }
    float mean = s * (1.0f / DIM);
    float var = s2 * (1.0f / DIM) - mean * mean;
    float rstd = rsqrtf(fmaxf(var, 0.0f) + LNEPS);
    const float4* g4 = (const float4*)g;
    const float4* b4 = (const float4*)b;
    float4* yr = (float4*)(y + row * DIM);
    float4 ga = g4[lane], bb = b4[lane];
    float4 o0;
    o0.x = (v0.x - mean) * rstd * ga.x + bb.x;
    o0.y = (v0.y - mean) * rstd * ga.y + bb.y;
    o0.z = (v0.z - mean) * rstd * ga.z + bb.z;
    o0.w = (v0.w - mean) * rstd * ga.w + bb.w;
    yr[lane] = o0;
    ga = g4[lane + 32]; bb = b4[lane + 32];
    float4 o1;
    o1.x = (v1.x - mean) * rstd * ga.x + bb.x;
    o1.y = (v1.y - mean) * rstd * ga.y + bb.y;
    o1.z = (v1.z - mean) * rstd * ga.z + bb.z;
    o1.w = (v1.w - mean) * rstd * ga.w + bb.w;
    yr[lane + 32] = o1;
}

// proj [NBF][DH] -> bf16 hi/lo (row-major, no transpose)
__global__ void proj_bf_kernel(const float* __restrict__ proj,
                               __nv_bfloat16* __restrict__ pb_hi,
                               __nv_bfloat16* __restrict__ pb_lo)
{
    int i = blockIdx.x * 256 + threadIdx.x;
    float v = proj[i];
    __nv_bfloat16 hi = __float2bfloat16(v);
    pb_hi[i] = hi;
    pb_lo[i] = __float2bfloat16(v - __bfloat162float(hi));
}

__global__ void head_kernel(const float* __restrict__ y,
                            const float* __restrict__ w,
                            const float* __restrict__ bb,
                            float* __restrict__ out)
{
    int warp = threadIdx.x >> 5, lane = threadIdx.x & 31;
    long row = (long)blockIdx.x * 8 + warp;
    const float* yr = y + row * DIM;
    float s = 0.0f;
    #pragma unroll
    for (int i = 0; i < 8; i++) s += yr[lane + i * 32] * w[lane + i * 32];
    #pragma unroll
    for (int o = 16; o; o >>= 1) s += __shfl_xor_sync(0xffffffffu, s, o);
    if (lane == 0) out[row] = s + bb[0];
}

// ---------------- host ----------------
template<int BN, int WN>
static inline void launch_tgemm(cudaStream_t st, int M, int N, int K,
    const float* A, int a_rs, int a_cs, long a_so, long a_si,
    const float* B, int b_ks, long b_so, long b_si,
    float* C, int c_rs, long c_so, long c_si,
    const float* bias, float alpha, int beta, int epi, int nbatch, int nsplit)
{
    dim3 grid(N / BN, M / 128, nbatch * nsplit);
    tgemm_kernel<BN, WN><<<grid, 128, 0, st>>>(M, N, K, A, a_rs, a_cs, a_so, a_si,
                                        B, b_ks, b_so, b_si, C, c_rs, c_so, c_si,
                                        bias, alpha, beta, epi, nsplit);
}

extern "C" void kernel_launch(void* const* d_in, const int* in_sizes, int n_in,
                              void* d_out, int out_size)
{
    const float* x        = (const float*)d_in[0];
    const float* mlp_w1   = (const float*)d_in[1];
    const float* mlp_b1   = (const float*)d_in[2];
    const float* mlp_w2   = (const float*)d_in[3];
    const float* mlp_b2   = (const float*)d_in[4];
    const float* pos      = (const float*)d_in[5];
    const float* gnn_emb  = (const float*)d_in[6];
    const float* gnn_w    = (const float*)d_in[7];
    const float* gnn_b    = (const float*)d_in[8];
    const float* ew       = (const float*)d_in[9];
    const float* proj     = (const float*)d_in[10];
    const float* ln1_g    = (const float*)d_in[11];
    const float* ln1_b    = (const float*)d_in[12];
    const float* wq       = (const float*)d_in[13];
    const float* wk       = (const float*)d_in[14];
    const float* wv       = (const float*)d_in[15];
    const float* wo       = (const float*)d_in[16];
    const float* bo       = (const float*)d_in[17];
    const float* ln2_g    = (const float*)d_in[18];
    const float* ln2_b    = (const float*)d_in[19];
    const float* ffw1     = (const float*)d_in[20];
    const float* ffb1     = (const float*)d_in[21];
    const float* ffw2     = (const float*)d_in[22];
    const float* ffb2     = (const float*)d_in[23];
    const float* normf_g  = (const float*)d_in[24];
    const float* normf_b  = (const float*)d_in[25];
    const float* out_w    = (const float*)d_in[26];
    const float* out_b    = (const float*)d_in[27];
    const int*   ei       = (const int*)d_in[28];
    float* out            = (float*)d_out;

    float *z, *y, *qkv, *wqkv, *o, *ff, *qf, *kf, *agg, *go, *deg, *dinv;
    float *ksum, *ctx, *kdiag;
    __nv_bfloat16 *pb_hi, *pb_lo;
    unsigned* stab_u;
    cudaGetSymbolAddress((void**)&z, g_z);
    cudaGetSymbolAddress((void**)&y, g_y);
    cudaGetSymbolAddress((void**)&qkv, g_qkv);
    cudaGetSymbolAddress((void**)&wqkv, g_wqkv);
    cudaGetSymbolAddress((void**)&o, g_o);
    cudaGetSymbolAddress((void**)&ff, g_ff);
    cudaGetSymbolAddress((void**)&qf, g_qf);
    cudaGetSymbolAddress((void**)&kf, g_kf);
    cudaGetSymbolAddress((void**)&agg, g_agg);
    cudaGetSymbolAddress((void**)&go, g_go);
    cudaGetSymbolAddress((void**)&deg, g_deg);
    cudaGetSymbolAddress((void**)&dinv, g_dinv);
    cudaGetSymbolAddress((void**)&stab_u, g_stab_u);
    cudaGetSymbolAddress((void**)&ksum, g_ksum);
    cudaGetSymbolAddress((void**)&ctx, g_ctx);
    cudaGetSymbolAddress((void**)&kdiag, g_kdiag);
    cudaGetSymbolAddress((void**)&pb_hi, g_pb_hi);
    cudaGetSymbolAddress((void**)&pb_lo, g_pb_lo);

    static cudaStream_t sA = nullptr, sB = nullptr;
    static cudaEvent_t evs[32];
    if (sA == nullptr) {
        cudaStreamCreateWithFlags(&sA, cudaStreamNonBlocking);
        cudaStreamCreateWithFlags(&sB, cudaStreamNonBlocking);
        for (int i = 0; i < 32; i++)
            cudaEventCreateWithFlags(&evs[i], cudaEventDisableTiming);
        cudaFuncSetAttribute(favor_gemm_kernel<0>,
                             cudaFuncAttributeMaxDynamicSharedMemorySize, FAVOR_SMEM);
        cudaFuncSetAttribute(favor_gemm_kernel<1>,
                             cudaFuncAttributeMaxDynamicSharedMemorySize, FAVOR_SMEM);
    }
    cudaStream_t s0 = cudaStreamPerThread;
    int ne = 0;
    auto fork_to = [&](cudaStream_t dst) {
        cudaEventRecord(evs[ne], s0);
        cudaStreamWaitEvent(dst, evs[ne], 0);
        ne++;
    };
    auto join_from = [&](cudaStream_t src) {
        cudaEventRecord(evs[ne], src);
        cudaStreamWaitEvent(s0, evs[ne], 0);
        ne++;
    };

    // ---- prologue ----
    zero_kernel<<<64, 256, 0, s0>>>(deg, NN);
    zero_kernel<<<1024, 256, 0, s0>>>(agg, (long)NN * DIM);
    deg_kernel<<<EEDG / 256, 256, 0, s0>>>(ei, ew, deg);
    dinv_kernel<<<NN / 256, 256, 0, s0>>>(deg, dinv);
    fork_to(sB);
    embed_kernel<<<ROWS, DIM, 0, sB>>>(x, mlp_w1, mlp_b1, y);
    launch_tgemm<128, 64>(sB, ROWS, DIM, DIM, y, DIM, 1, 0, 0, mlp_w2, DIM, 0, 0,
                          z, DIM, 0, 0, mlp_b2, 1.0f, 0, 0, 1, 1);
    proj_bf_kernel<<<NBF * DH / 256, 256, 0, s0>>>(proj, pb_hi, pb_lo);
    agg_kernel<<<EEDG, DIM, 0, s0>>>(ei, ew, dinv, gnn_emb, agg);
    launch_tgemm<128, 64>(s0, NN, DIM, DIM, agg, DIM, 1, 0, 0, gnn_w, DIM, 0, 0,
                          go, DIM, 0, 0, gnn_b, 1.0f, 0, 0, 1, 1);
    join_from(sB);
    zadd_kernel<<<ROWS, DIM, 0, s0>>>(z, pos, go);

    // ---- transformer layers ----
    for (int l = 0; l < 2; l++) {
        const float* wq_l   = wq  + (long)l * DIM * INNER;
        const float* wk_l   = wk  + (long)l * DIM * INNER;
        const float* wv_l   = wv  + (long)l * DIM * INNER;
        const float* wo_l   = wo  + (long)l * INNER * DIM;
        const float* bo_l   = bo  + (long)l * DIM;
        const float* ffw1_l = ffw1 + (long)l * DIM * FFD;
        const float* ffb1_l = ffb1 + (long)l * FFD;
        const float* ffw2_l = ffw2 + (long)l * FFD * DIM;
        const float* ffb2_l = ffb2 + (long)l * DIM;

        fork_to(sA);
        concat_w_kernel<<<DIM, 512, 0, sA>>>(wq_l, wk_l, wv_l, wqkv);
        ln_kernel<<<ROWS / 8, 256, 0, s0>>>(z, ln1_g + l * DIM, ln1_b + l * DIM, y);
        join_from(sA);

        launch_tgemm<128, 64>(s0, ROWS, QKVN, DIM, y, DIM, 1, 0, 0, wqkv, QKVN, 0, 0,
                              qkv, QKVN, 0, 0, nullptr, 1.0f, 0, 0, 1, 1);

        // favor_q fully parallel on sA
        fork_to(sA);
        favor_gemm_kernel<0><<<dim3(NN / 64, BH), 256, FAVOR_SMEM, sA>>>(
            qkv, pb_hi, pb_lo, qf, nullptr, nullptr);

        // ctx-zero off-path
        fork_to(sB);
        zero_kernel<<<256, 256, 0, sB>>>(ctx, (long)BH * NBF * DH);

        // K path on s0
        zks_kernel<<<16, 256, 0, s0>>>(ksum, stab_u);
        favor_gemm_kernel<1><<<dim3(NN / 64, BH), 256, FAVOR_SMEM, s0>>>(
            qkv + 512, pb_hi, pb_lo, kf, stab_u, kdiag);

        join_from(sB);
        ctxk_kernel<<<dim3(1, 2, BH * CTX_NSPLIT), 128, 0, s0>>>(
            kf, qkv + 1024, kdiag, stab_u, ctx, ksum);

        join_from(sA);
        attn_kernel<<<dim3(1, NN / 128, BH), 128, 0, s0>>>(qf, ctx, ksum, o);

        launch_tgemm<128, 64>(s0, ROWS, DIM, INNER, o, INNER, 1, 0, 0, wo_l, DIM, 0, 0,
                              z, DIM, 0, 0, bo_l, 1.0f, 1, 0, 1, 1);

        ln_kernel<<<ROWS / 8, 256, 0, s0>>>(z, ln2_g + l * DIM, ln2_b + l * DIM, y);
        launch_tgemm<128, 64>(s0, ROWS, FFD, DIM, y, DIM, 1, 0, 0, ffw1_l, FFD, 0, 0,
                              ff, FFD, 0, 0, ffb1_l, 1.0f, 0, 2, 1, 1);
        launch_tgemm<128, 64>(s0, ROWS, DIM, FFD, ff, FFD, 1, 0, 0, ffw2_l, DIM, 0, 0,
                              z, DIM, 0, 0, ffb2_l, 1.0f, 1, 0, 1, 1);
    }

    // ---- final LN + head ----
    ln_kernel<<<ROWS / 8, 256, 0, s0>>>(z, normf_g, normf_b, y);
    head_kernel<<<ROWS / 8, 256, 0, s0>>>(y, out_w, out_b, out);
}

// round 10
// speedup vs baseline: 34.0873x; 1.0547x over previous
#include <cuda_runtime.h>
#include <cuda_bf16.h>
#include <math.h>
#include <stdint.h>

// ---------------- problem constants ----------------
#define BSZ    2
#define NN     8192
#define DIM    256
#define HEADS  8
#define DH     64
#define INNER  512
#define QKVN   1536
#define NBF    256
#define FFD    1024
#define EEDG   131072
#define ROWS   (BSZ*NN)
#define BH     (BSZ*HEADS)
#define KEPS   1e-4f
#define LNEPS  1e-5f
#define DN     0.3535533905932738f
#define RATIO  0.0625f

// ---------------- scratch ----------------
__device__ float g_z[ROWS*DIM];
__device__ float g_y[ROWS*DIM];
__device__ float g_qkv[(size_t)ROWS*QKVN];
__device__ float g_wqkv[DIM*QKVN];
__device__ float g_wo_c[INNER*DIM];
__device__ float g_ff1_c[DIM*FFD];
__device__ float g_ff2_c[FFD*DIM];
__device__ float g_o[ROWS*INNER];
__device__ float g_ff[(size_t)ROWS*FFD];
__device__ float g_qf[(size_t)BH*NN*NBF];
__device__ float g_kf[(size_t)BH*NN*NBF];
__device__ float g_agg[NN*DIM];
__device__ float g_go[NN*DIM];
__device__ float g_deg[NN];
__device__ float g_dinv[NN];
__device__ unsigned g_stab_u[BH];
__device__ float g_ksum[BH*NBF];
__device__ float g_ctx[BH*NBF*DH];
__device__ float g_kdiag[BH*NN];
__device__ __nv_bfloat16 g_pb_hi[NBF*DH];
__device__ __nv_bfloat16 g_pb_lo[NBF*DH];

__device__ __forceinline__ float gelu_f(float v) {
    const float c = 0.7978845608028654f;
    float t = tanhf(c * (v + 0.044715f * v * v * v));
    return 0.5f * v * (1.0f + t);
}

__device__ __forceinline__ float cvt_tf32(float x) {
    uint32_t u;
    asm("cvt.rna.tf32.f32 %0, %1;" : "=r"(u) : "f"(x));
    return __uint_as_float(u);
}

__device__ __forceinline__ unsigned fkey(float f) {
    unsigned b = __float_as_uint(f);
    return (b & 0x80000000u) ? ~b : (b | 0x80000000u);
}
__device__ __forceinline__ float fkey_inv(unsigned u) {
    unsigned b = (u & 0x80000000u) ? (u ^ 0x80000000u) : ~u;
    return __uint_as_float(b);
}

__device__ __forceinline__ void mma_tf32(float* c, const uint32_t* a,
                                         uint32_t b0, uint32_t b1) {
    asm volatile(
        "mma.sync.aligned.m16n8k8.row.col.f32.tf32.tf32.f32 "
        "{%0,%1,%2,%3}, {%4,%5,%6,%7}, {%8,%9}, {%0,%1,%2,%3};\n"
        : "+f"(c[0]), "+f"(c[1]), "+f"(c[2]), "+f"(c[3])
        : "r"(a[0]), "r"(a[1]), "r"(a[2]), "r"(a[3]), "r"(b0), "r"(b1));
}

__device__ __forceinline__ void mma_bf16(float* c, const uint32_t* a,
                                         uint32_t b0, uint32_t b1) {
    asm volatile(
        "mma.sync.aligned.m16n8k16.row.col.f32.bf16.bf16.f32 "
        "{%0,%1,%2,%3}, {%4,%5,%6,%7}, {%8,%9}, {%0,%1,%2,%3};\n"
        : "+f"(c[0]), "+f"(c[1]), "+f"(c[2]), "+f"(c[3])
        : "r"(a[0]), "r"(a[1]), "r"(a[2]), "r"(a[3]), "r"(b0), "r"(b1));
}

// =====================================================================
// tf32 tensor-core GEMM. Block 128 x BN, 4 warps.
// cvtin: round A/B to tf32 at smem-store (use 1 only when operands are
// not pre-rounded). cvtout: round C to tf32 at write (when C feeds
// another tgemm as A).
// =====================================================================
template<int BN, int WN>
__global__ __launch_bounds__(128)
void tgemm_kernel(int M, int N, int K,
                  const float* __restrict__ A, int a_rs, int a_cs, long a_so, long a_si,
                  const float* __restrict__ B, int b_ks, long b_so, long b_si,
                  float* __restrict__ C, int c_rs, long c_so, long c_si,
                  const float* __restrict__ bias,
                  float alpha, int beta, int epi, int nsplit,
                  int cvtin, int cvtout)
{
    constexpr int BK = 16;
    constexpr int SA = 136;
    constexpr int SB = BN + 8;
    constexpr int NI = WN / 8;
    constexpr int NBL = BN / 32;
    __shared__ float As[2][BK][SA];
    __shared__ float Bs[2][BK][SB];

    int zz = blockIdx.z;
    int batch = zz / nsplit;
    int split = zz - batch * nsplit;
    long aoff = (long)(batch >> 3) * a_so + (long)(batch & 7) * a_si;
    long boff = (long)(batch >> 3) * b_so + (long)(batch & 7) * b_si;
    long coff = (long)(batch >> 3) * c_so + (long)(batch & 7) * c_si;
    int row0 = blockIdx.y * 128;
    int col0 = blockIdx.x * BN;
    int kchunk = K / nsplit;
    int kbeg = split * kchunk;
    int kend = kbeg + kchunk;

    int tid = threadIdx.x;
    int lane = tid & 31;
    int warp = tid >> 5;
    int m_warp = (warp >> 1) * 64;
    int n_warp = (warp & 1) * WN;

    float c[4][NI][4];
    #pragma unroll
    for (int i = 0; i < 4; i++)
        #pragma unroll
        for (int j = 0; j < NI; j++)
            #pragma unroll
            for (int t = 0; t < 4; t++) c[i][j][t] = 0.0f;

    float4 ra[4];
    float4 rb[NBL];

    auto loadA = [&](int kt) {
        if (a_cs == 1) {
            #pragma unroll
            for (int i = 0; i < 4; i++) {
                int idx = tid + i * 128;
                int m = idx >> 2;
                int kc = (idx & 3) * 4;
                ra[i] = *(const float4*)(A + aoff + (long)(row0 + m) * a_rs + kt + kc);
            }
        } else {
            #pragma unroll
            for (int i = 0; i < 4; i++) {
                int idx = tid + i * 128;
                int m4 = (idx & 31) * 4;
                int kk = idx >> 5;
                ra[i] = *(const float4*)(A + aoff + (long)(kt + kk) * a_cs + row0 + m4);
            }
        }
    };
    auto storeA = [&](int bf) {
        if (a_cs == 1) {
            #pragma unroll
            for (int i = 0; i < 4; i++) {
                int idx = tid + i * 128;
                int m = idx >> 2;
                int kc = (idx & 3) * 4;
                float v[4] = {ra[i].x, ra[i].y, ra[i].z, ra[i].w};
                if (cvtin) {
                    #pragma unroll
                    for (int j = 0; j < 4; j++) v[j] = cvt_tf32(v[j]);
                }
                #pragma unroll
                for (int j0 = 0; j0 < 4; j0++) {
                    int j = (j0 + lane) & 3;
                    As[bf][kc + j][m] = v[j];
                }
            }
        } else {
            #pragma unroll
            for (int i = 0; i < 4; i++) {
                int idx = tid + i * 128;
                int m4 = (idx & 31) * 4;
                int kk = idx >> 5;
                float4 t = ra[i];
                if (cvtin) {
                    t.x = cvt_tf32(t.x); t.y = cvt_tf32(t.y);
                    t.z = cvt_tf32(t.z); t.w = cvt_tf32(t.w);
                }
                *(float4*)&As[bf][kk][m4] = t;
            }
        }
    };
    auto loadB = [&](int kt) {
        #pragma unroll
        for (int i = 0; i < NBL; i++) {
            int idx = tid + i * 128;
            int n4 = (idx & (BN / 4 - 1)) * 4;
            int kk = idx / (BN / 4);
            rb[i] = *(const float4*)(B + boff + (long)(kt + kk) * b_ks + col0 + n4);
        }
    };
    auto storeB = [&](int bf) {
        #pragma unroll
        for (int i = 0; i < NBL; i++) {
            int idx = tid + i * 128;
            int n4 = (idx & (BN / 4 - 1)) * 4;
            int kk = idx / (BN / 4);
            float4 t = rb[i];
            if (cvtin) {
                t.x = cvt_tf32(t.x); t.y = cvt_tf32(t.y);
                t.z = cvt_tf32(t.z); t.w = cvt_tf32(t.w);
            }
            *(float4*)&Bs[bf][kk][n4] = t;
        }
    };
    auto compute = [&](int bf) {
        #pragma unroll
        for (int s = 0; s < 2; s++) {
            int k8 = s * 8;
            uint32_t af[4][4];
            #pragma unroll
            for (int mi = 0; mi < 4; mi++) {
                int mr = m_warp + mi * 16 + (lane >> 2);
                af[mi][0] = __float_as_uint(As[bf][k8 + (lane & 3)][mr]);
                af[mi][1] = __float_as_uint(As[bf][k8 + (lane & 3)][mr + 8]);
                af[mi][2] = __float_as_uint(As[bf][k8 + 4 + (lane & 3)][mr]);
                af[mi][3] = __float_as_uint(As[bf][k8 + 4 + (lane & 3)][mr + 8]);
            }
            #pragma unroll
            for (int ni = 0; ni < NI; ni++) {
                int nc = n_warp + ni * 8 + (lane >> 2);
                uint32_t b0 = __float_as_uint(Bs[bf][k8 + (lane & 3)][nc]);
                uint32_t b1 = __float_as_uint(Bs[bf][k8 + 4 + (lane & 3)][nc]);
                #pragma unroll
                for (int mi = 0; mi < 4; mi++)
                    mma_tf32(c[mi][ni], af[mi], b0, b1);
            }
        }
    };

    loadA(kbeg); loadB(kbeg);
    storeA(0);   storeB(0);
    __syncthreads();
    int buf = 0;
    for (int kt = kbeg; kt < kend; kt += BK) {
        bool has_next = (kt + BK) < kend;
        if (has_next) { loadA(kt + BK); loadB(kt + BK); }
        compute(buf);
        if (has_next) {
            storeA(buf ^ 1); storeB(buf ^ 1);
            __syncthreads();
            buf ^= 1;
        }
    }

    #pragma unroll
    for (int mi = 0; mi < 4; mi++) {
        int r = row0 + m_warp + mi * 16 + (lane >> 2);
        long crow0 = coff + (long)r * c_rs;
        long crow1 = coff + (long)(r + 8) * c_rs;
        #pragma unroll
        for (int ni = 0; ni < NI; ni++) {
            int cc = col0 + n_warp + ni * 8 + 2 * (lane & 3);
            float v0 = alpha * c[mi][ni][0];
            float v1 = alpha * c[mi][ni][1];
            float v2 = alpha * c[mi][ni][2];
            float v3 = alpha * c[mi][ni][3];
            if (nsplit > 1) {
                atomicAdd(C + crow0 + cc,     v0);
                atomicAdd(C + crow0 + cc + 1, v1);
                atomicAdd(C + crow1 + cc,     v2);
                atomicAdd(C + crow1 + cc + 1, v3);
            } else {
                if (bias) {
                    float2 bb = *(const float2*)(bias + cc);
                    v0 += bb.x; v1 += bb.y; v2 += bb.x; v3 += bb.y;
                }
                if (epi == 1) {
                    v0 = fmaxf(v0, 0.f); v1 = fmaxf(v1, 0.f);
                    v2 = fmaxf(v2, 0.f); v3 = fmaxf(v3, 0.f);
                } else if (epi == 2) {
                    v0 = gelu_f(v0); v1 = gelu_f(v1);
                    v2 = gelu_f(v2); v3 = gelu_f(v3);
                }
                if (beta) {
                    float2 c0 = *(const float2*)(C + crow0 + cc);
                    float2 c1 = *(const float2*)(C + crow1 + cc);
                    v0 += c0.x; v1 += c0.y; v2 += c1.x; v3 += c1.y;
                }
                if (cvtout) {
                    v0 = cvt_tf32(v0); v1 = cvt_tf32(v1);
                    v2 = cvt_tf32(v2); v3 = cvt_tf32(v3);
                }
                *(float2*)(C + crow0 + cc) = make_float2(v0, v1);
                *(float2*)(C + crow1 + cc) = make_float2(v2, v3);
            }
        }
    }
}

// =====================================================================
// ctxk: ctx[bh] += kf^T @ v with kf computed inline from raw dd.
// =====================================================================
#define CTX_NSPLIT 32
__global__ __launch_bounds__(128)
void ctxk_kernel(const float* __restrict__ dd,
                 const float* __restrict__ vsrc,
                 const float* __restrict__ kdiag,
                 const unsigned* __restrict__ stab_u,
                 float* __restrict__ ctx,
                 float* __restrict__ ksum)
{
    constexpr int BK = 16;
    __shared__ float As[2][BK][136];
    __shared__ float Bs[2][BK][72];

    int zz = blockIdx.z;
    int batch = zz / CTX_NSPLIT;
    int split = zz - batch * CTX_NSPLIT;
    long aoff = (long)batch * NN * NBF;
    long boff = (long)(batch >> 3) * NN * QKVN + (long)(batch & 7) * DH;
    long coff = (long)batch * NBF * DH;
    const float* kdg = kdiag + (long)batch * NN;
    float stab = fkey_inv(stab_u[batch]);

    int row0 = blockIdx.y * 128;
    int kbeg = split * (NN / CTX_NSPLIT);
    int kend = kbeg + NN / CTX_NSPLIT;

    int tid = threadIdx.x;
    int lane = tid & 31;
    int warp = tid >> 5;
    int m_warp = (warp >> 1) * 64;
    int n_warp = (warp & 1) * 32;

    float c[4][4][4];
    #pragma unroll
    for (int i = 0; i < 4; i++)
        #pragma unroll
        for (int j = 0; j < 4; j++)
            #pragma unroll
            for (int t = 0; t < 4; t++) c[i][j][t] = 0.0f;

    float ks_acc[4] = {0.f, 0.f, 0.f, 0.f};
    float4 ra[4];
    float4 rb[2];

    auto loadA = [&](int kt) {
        #pragma unroll
        for (int i = 0; i < 4; i++) {
            int idx = tid + i * 128;
            int m4 = (idx & 31) * 4;
            int kk = idx >> 5;
            ra[i] = *(const float4*)(dd + aoff + (long)(kt + kk) * NBF + row0 + m4);
        }
    };
    auto storeA = [&](int bf, int kt) {
        #pragma unroll
        for (int i = 0; i < 4; i++) {
            int idx = tid + i * 128;
            int m4 = (idx & 31) * 4;
            int kk = idx >> 5;
            float sub = kdg[kt + kk] + stab;
            float k0 = RATIO * (expf(ra[i].x - sub) + KEPS);
            float k1 = RATIO * (expf(ra[i].y - sub) + KEPS);
            float k2 = RATIO * (expf(ra[i].z - sub) + KEPS);
            float k3 = RATIO * (expf(ra[i].w - sub) + KEPS);
            ks_acc[0] += k0; ks_acc[1] += k1; ks_acc[2] += k2; ks_acc[3] += k3;
            float4 t;
            t.x = cvt_tf32(k0); t.y = cvt_tf32(k1);
            t.z = cvt_tf32(k2); t.w = cvt_tf32(k3);
            *(float4*)&As[bf][kk][m4] = t;
        }
    };
    auto loadB = [&](int kt) {
        #pragma unroll
        for (int i = 0; i < 2; i++) {
            int idx = tid + i * 128;
            int n4 = (idx & 15) * 4;
            int kk = idx >> 4;
            rb[i] = *(const float4*)(vsrc + boff + (long)(kt + kk) * QKVN + n4);
        }
    };
    auto storeB = [&](int bf) {
        #pragma unroll
        for (int i = 0; i < 2; i++) {
            int idx = tid + i * 128;
            int n4 = (idx & 15) * 4;
            int kk = idx >> 4;
            float4 t;
            t.x = cvt_tf32(rb[i].x); t.y = cvt_tf32(rb[i].y);
            t.z = cvt_tf32(rb[i].z); t.w = cvt_tf32(rb[i].w);
            *(float4*)&Bs[bf][kk][n4] = t;
        }
    };
    auto compute = [&](int bf) {
        #pragma unroll
        for (int s = 0; s < 2; s++) {
            int k8 = s * 8;
            uint32_t af[4][4];
            #pragma unroll
            for (int mi = 0; mi < 4; mi++) {
                int mr = m_warp + mi * 16 + (lane >> 2);
                af[mi][0] = __float_as_uint(As[bf][k8 + (lane & 3)][mr]);
                af[mi][1] = __float_as_uint(As[bf][k8 + (lane & 3)][mr + 8]);
                af[mi][2] = __float_as_uint(As[bf][k8 + 4 + (lane & 3)][mr]);
                af[mi][3] = __float_as_uint(As[bf][k8 + 4 + (lane & 3)][mr + 8]);
            }
            #pragma unroll
            for (int ni = 0; ni < 4; ni++) {
                int nc = n_warp + ni * 8 + (lane >> 2);
                uint32_t b0 = __float_as_uint(Bs[bf][k8 + (lane & 3)][nc]);
                uint32_t b1 = __float_as_uint(Bs[bf][k8 + 4 + (lane & 3)][nc]);
                #pragma unroll
                for (int mi = 0; mi < 4; mi++)
                    mma_tf32(c[mi][ni], af[mi], b0, b1);
            }
        }
    };

    loadA(kbeg); loadB(kbeg);
    storeA(0, kbeg); storeB(0);
    __syncthreads();
    int buf = 0;
    for (int kt = kbeg; kt < kend; kt += BK) {
        bool has_next = (kt + BK) < kend;
        if (has_next) { loadA(kt + BK); loadB(kt + BK); }
        compute(buf);
        if (has_next) {
            storeA(buf ^ 1, kt + BK); storeB(buf ^ 1);
            __syncthreads();
            buf ^= 1;
        }
    }

    {
        int m4 = (tid & 31) * 4;
        #pragma unroll
        for (int j = 0; j < 4; j++)
            atomicAdd(&ksum[(long)batch * NBF + row0 + m4 + j], ks_acc[j]);
    }

    #pragma unroll
    for (int mi = 0; mi < 4; mi++) {
        int r = row0 + m_warp + mi * 16 + (lane >> 2);
        long crow0 = coff + (long)r * DH;
        long crow1 = coff + (long)(r + 8) * DH;
        #pragma unroll
        for (int ni = 0; ni < 4; ni++) {
            int cc = n_warp + ni * 8 + 2 * (lane & 3);
            atomicAdd(ctx + crow0 + cc,     c[mi][ni][0]);
            atomicAdd(ctx + crow0 + cc + 1, c[mi][ni][1]);
            atomicAdd(ctx + crow1 + cc,     c[mi][ni][2]);
            atomicAdd(ctx + crow1 + cc + 1, c[mi][ni][3]);
        }
    }
}

// =====================================================================
// attn: o = (qf @ ctx) / (qf . ksum); o rounded to tf32 (feeds wo GEMM).
// =====================================================================
__global__ __launch_bounds__(128)
void attn_kernel(const float* __restrict__ qf,
                 const float* __restrict__ ctx,
                 const float* __restrict__ ksum,
                 float* __restrict__ o)
{
    constexpr int BK = 16;
    __shared__ float As[2][BK][136];
    __shared__ float Bs[2][BK][72];
    __shared__ float ksum_s[NBF];
    __shared__ float denom_s[128];

    int batch = blockIdx.z;
    long aoff = (long)batch * NN * NBF;
    long boff = (long)batch * NBF * DH;
    long coff = (long)(batch >> 3) * NN * INNER + (long)(batch & 7) * DH;
    int row0 = blockIdx.y * 128;

    int tid = threadIdx.x;
    int lane = tid & 31;
    int warp = tid >> 5;
    int m_warp = (warp >> 1) * 64;
    int n_warp = (warp & 1) * 32;

    ksum_s[tid] = ksum[(long)batch * NBF + tid];
    ksum_s[tid + 128] = ksum[(long)batch * NBF + tid + 128];
    denom_s[tid] = 0.0f;
    __syncthreads();

    float c[4][4][4];
    #pragma unroll
    for (int i = 0; i < 4; i++)
        #pragma unroll
        for (int j = 0; j < 4; j++)
            #pragma unroll
            for (int t = 0; t < 4; t++) c[i][j][t] = 0.0f;

    float dacc[4] = {0.f, 0.f, 0.f, 0.f};
    float4 ra[4];
    float4 rb[2];

    auto loadA = [&](int kt) {
        #pragma unroll
        for (int i = 0; i < 4; i++) {
            int idx = tid + i * 128;
            int m = idx >> 2;
            int kc = (idx & 3) * 4;
            ra[i] = *(const float4*)(qf + aoff + (long)(row0 + m) * NBF + kt + kc);
        }
    };
    auto storeA = [&](int bf, int kt) {
        #pragma unroll
        for (int i = 0; i < 4; i++) {
            int idx = tid + i * 128;
            int m = idx >> 2;
            int kc = (idx & 3) * 4;
            float v[4] = {ra[i].x, ra[i].y, ra[i].z, ra[i].w};
            dacc[i] += v[0] * ksum_s[kt + kc] + v[1] * ksum_s[kt + kc + 1]
                     + v[2] * ksum_s[kt + kc + 2] + v[3] * ksum_s[kt + kc + 3];
            #pragma unroll
            for (int j0 = 0; j0 < 4; j0++) {
                int j = (j0 + lane) & 3;
                As[bf][kc + j][m] = cvt_tf32(v[j]);
            }
        }
    };
    auto loadB = [&](int kt) {
        #pragma unroll
        for (int i = 0; i < 2; i++) {
            int idx = tid + i * 128;
            int n4 = (idx & 15) * 4;
            int kk = idx >> 4;
            rb[i] = *(const float4*)(ctx + boff + (long)(kt + kk) * DH + n4);
        }
    };
    auto storeB = [&](int bf) {
        #pragma unroll
        for (int i = 0; i < 2; i++) {
            int idx = tid + i * 128;
            int n4 = (idx & 15) * 4;
            int kk = idx >> 4;
            float4 t;
            t.x = cvt_tf32(rb[i].x); t.y = cvt_tf32(rb[i].y);
            t.z = cvt_tf32(rb[i].z); t.w = cvt_tf32(rb[i].w);
            *(float4*)&Bs[bf][kk][n4] = t;
        }
    };
    auto compute = [&](int bf) {
        #pragma unroll
        for (int s = 0; s < 2; s++) {
            int k8 = s * 8;
            uint32_t af[4][4];
            #pragma unroll
            for (int mi = 0; mi < 4; mi++) {
                int mr = m_warp + mi * 16 + (lane >> 2);
                af[mi][0] = __float_as_uint(As[bf][k8 + (lane & 3)][mr]);
                af[mi][1] = __float_as_uint(As[bf][k8 + (lane & 3)][mr + 8]);
                af[mi][2] = __float_as_uint(As[bf][k8 + 4 + (lane & 3)][mr]);
                af[mi][3] = __float_as_uint(As[bf][k8 + 4 + (lane & 3)][mr + 8]);
            }
            #pragma unroll
            for (int ni = 0; ni < 4; ni++) {
                int nc = n_warp + ni * 8 + (lane >> 2);
                uint32_t b0 = __float_as_uint(Bs[bf][k8 + (lane & 3)][nc]);
                uint32_t b1 = __float_as_uint(Bs[bf][k8 + 4 + (lane & 3)][nc]);
                #pragma unroll
                for (int mi = 0; mi < 4; mi++)
                    mma_tf32(c[mi][ni], af[mi], b0, b1);
            }
        }
    };

    loadA(0); loadB(0);
    storeA(0, 0); storeB(0);
    __syncthreads();
    int buf = 0;
    for (int kt = 0; kt < NBF; kt += BK) {
        bool has_next = (kt + BK) < NBF;
        if (has_next) { loadA(kt + BK); loadB(kt + BK); }
        compute(buf);
        if (has_next) {
            storeA(buf ^ 1, kt + BK); storeB(buf ^ 1);
            __syncthreads();
            buf ^= 1;
        }
    }

    #pragma unroll
    for (int i = 0; i < 4; i++) {
        int m = (tid + i * 128) >> 2;
        atomicAdd(&denom_s[m], dacc[i]);
    }
    __syncthreads();

    #pragma unroll
    for (int mi = 0; mi < 4; mi++) {
        int lr = m_warp + mi * 16 + (lane >> 2);
        float rdv0 = 1.0f / denom_s[lr];
        float rdv1 = 1.0f / denom_s[lr + 8];
        long crow0 = coff + (long)(row0 + lr) * INNER;
        long crow1 = coff + (long)(row0 + lr + 8) * INNER;
        #pragma unroll
        for (int ni = 0; ni < 4; ni++) {
            int cc = n_warp + ni * 8 + 2 * (lane & 3);
            *(float2*)(o + crow0 + cc) = make_float2(cvt_tf32(c[mi][ni][0] * rdv0),
                                                     cvt_tf32(c[mi][ni][1] * rdv0));
            *(float2*)(o + crow1 + cc) = make_float2(cvt_tf32(c[mi][ni][2] * rdv1),
                                                     cvt_tf32(c[mi][ni][3] * rdv1));
        }
    }
}

// =====================================================================
// FAVOR feature kernel, bf16x3 (m16n8k16). See R9.
// =====================================================================
#define FAVOR_SMEM 93696

template<int MODE>
__global__ __launch_bounds__(256, 2)
void favor_gemm_kernel(const float* __restrict__ qk,
                       const __nv_bfloat16* __restrict__ pb_hi,
                       const __nv_bfloat16* __restrict__ pb_lo,
                       float* __restrict__ outf,
                       unsigned* __restrict__ stab_u,
                       float* __restrict__ kdiag)
{
    extern __shared__ __align__(16) char smraw[];
    __nv_bfloat16* As_hi = (__nv_bfloat16*)(smraw);
    __nv_bfloat16* As_lo = (__nv_bfloat16*)(smraw + 9216);
    __nv_bfloat16* Bs_hi = (__nv_bfloat16*)(smraw + 18432);
    __nv_bfloat16* Bs_lo = (__nv_bfloat16*)(smraw + 55296);
    float* diag_s = (float*)(smraw + 92160);
    float* rmax_s = (float*)(smraw + 92416);
    float (*red)[64] = (float(*)[64])(smraw + 92672);

    int bh = blockIdx.y;
    int b = bh >> 3, h = bh & 7;
    int row0 = blockIdx.x * 64;
    const float* aptr = qk + ((long)(b * NN) + row0) * QKVN + h * DH;

    int tid = threadIdx.x;
    int lane = tid & 31, w = tid >> 5;
    int m_warp = (w >> 2) * 32;
    int n_warp = (w & 3) * 64;

    float sq[4];
    #pragma unroll
    for (int i = 0; i < 4; i++) {
        int f4 = tid + i * 256;
        int row = f4 >> 4;
        int kc = (f4 & 15) * 4;
        float4 v = *(const float4*)(aptr + (long)row * QKVN + kc);
        v.x *= DN; v.y *= DN; v.z *= DN; v.w *= DN;
        sq[i] = v.x * v.x + v.y * v.y + v.z * v.z + v.w * v.w;
        __nv_bfloat162 h0 = __floats2bfloat162_rn(v.x, v.y);
        __nv_bfloat162 h1 = __floats2bfloat162_rn(v.z, v.w);
        __nv_bfloat162 l0 = __floats2bfloat162_rn(v.x - __bfloat162float(h0.x),
                                                  v.y - __bfloat162float(h0.y));
        __nv_bfloat162 l1 = __floats2bfloat162_rn(v.z - __bfloat162float(h1.x),
                                                  v.w - __bfloat162float(h1.y));
        *(__nv_bfloat162*)&As_hi[row * 72 + kc]     = h0;
        *(__nv_bfloat162*)&As_hi[row * 72 + kc + 2] = h1;
        *(__nv_bfloat162*)&As_lo[row * 72 + kc]     = l0;
        *(__nv_bfloat162*)&As_lo[row * 72 + kc + 2] = l1;
    }
    #pragma unroll
    for (int i = 0; i < 4; i++) {
        #pragma unroll
        for (int o = 1; o < 16; o <<= 1)
            sq[i] += __shfl_xor_sync(0xffffffffu, sq[i], o);
    }
    if ((lane & 15) == 0) {
        int r0 = w * 2 + (lane >> 4);
        #pragma unroll
        for (int i = 0; i < 4; i++)
            diag_s[r0 + i * 16] = 0.5f * sq[i];
    }

    #pragma unroll
    for (int j = 0; j < 8; j++) {
        int u4 = tid + j * 256;
        int row = u4 >> 3;
        int c8 = (u4 & 7) * 8;
        *(uint4*)&Bs_hi[row * 72 + c8] = *(const uint4*)&pb_hi[(long)row * DH + c8];
        *(uint4*)&Bs_lo[row * 72 + c8] = *(const uint4*)&pb_lo[(long)row * DH + c8];
    }
    __syncthreads();

    float c[2][8][4];
    #pragma unroll
    for (int mi = 0; mi < 2; mi++)
        #pragma unroll
        for (int ni = 0; ni < 8; ni++)
            #pragma unroll
            for (int t = 0; t < 4; t++) c[mi][ni][t] = 0.0f;

    #pragma unroll
    for (int kt = 0; kt < 4; kt++) {
        int kb = kt * 16 + (lane & 3) * 2;
        uint32_t ah[2][4], al[2][4];
        #pragma unroll
        for (int mi = 0; mi < 2; mi++) {
            int mr = m_warp + mi * 16 + (lane >> 2);
            ah[mi][0] = *(const uint32_t*)&As_hi[mr * 72 + kb];
            ah[mi][1] = *(const uint32_t*)&As_hi[(mr + 8) * 72 + kb];
            ah[mi][2] = *(const uint32_t*)&As_hi[mr * 72 + kb + 8];
            ah[mi][3] = *(const uint32_t*)&As_hi[(mr + 8) * 72 + kb + 8];
            al[mi][0] = *(const uint32_t*)&As_lo[mr * 72 + kb];
            al[mi][1] = *(const uint32_t*)&As_lo[(mr + 8) * 72 + kb];
            al[mi][2] = *(const uint32_t*)&As_lo[mr * 72 + kb + 8];
            al[mi][3] = *(const uint32_t*)&As_lo[(mr + 8) * 72 + kb + 8];
        }
        #pragma unroll
        for (int ni = 0; ni < 8; ni++) {
            int nc = n_warp + ni * 8 + (lane >> 2);
            uint32_t bh0 = *(const uint32_t*)&Bs_hi[nc * 72 + kb];
            uint32_t bh1 = *(const uint32_t*)&Bs_hi[nc * 72 + kb + 8];
            uint32_t bl0 = *(const uint32_t*)&Bs_lo[nc * 72 + kb];
            uint32_t bl1 = *(const uint32_t*)&Bs_lo[nc * 72 + kb + 8];
            #pragma unroll
            for (int mi = 0; mi < 2; mi++) {
                mma_bf16(c[mi][ni], ah[mi], bh0, bh1);
                mma_bf16(c[mi][ni], ah[mi], bl0, bl1);
                mma_bf16(c[mi][ni], al[mi], bh0, bh1);
            }
        }
    }
    __syncthreads();

    float mx[2][2];
    #pragma unroll
    for (int mi = 0; mi < 2; mi++) {
        float mlo = -INFINITY, mhi = -INFINITY;
        #pragma unroll
        for (int ni = 0; ni < 8; ni++) {
            mlo = fmaxf(mlo, fmaxf(c[mi][ni][0], c[mi][ni][1]));
            mhi = fmaxf(mhi, fmaxf(c[mi][ni][2], c[mi][ni][3]));
        }
        #pragma unroll
        for (int o = 1; o <= 2; o <<= 1) {
            mlo = fmaxf(mlo, __shfl_xor_sync(0xffffffffu, mlo, o));
            mhi = fmaxf(mhi, __shfl_xor_sync(0xffffffffu, mhi, o));
        }
        mx[mi][0] = mlo; mx[mi][1] = mhi;
    }
    if ((lane & 3) == 0) {
        #pragma unroll
        for (int mi = 0; mi < 2; mi++) {
            int lr = m_warp + mi * 16 + (lane >> 2);
            red[w & 3][lr]     = mx[mi][0];
            red[w & 3][lr + 8] = mx[mi][1];
        }
    }
    __syncthreads();
    if (tid < 64)
        rmax_s[tid] = fmaxf(fmaxf(red[0][tid], red[1][tid]),
                            fmaxf(red[2][tid], red[3][tid]));
    __syncthreads();

    if (MODE == 1) {
        if (tid < 64)
            kdiag[(long)bh * NN + row0 + tid] = diag_s[tid];
        if (tid < 32) {
            float m = fmaxf(rmax_s[tid], rmax_s[tid + 32]);
            #pragma unroll
            for (int o = 16; o; o >>= 1)
                m = fmaxf(m, __shfl_xor_sync(0xffffffffu, m, o));
            if (tid == 0) atomicMax(&stab_u[bh], fkey(m));
        }
        #pragma unroll
        for (int mi = 0; mi < 2; mi++) {
            int rl = m_warp + mi * 16 + (lane >> 2);
            long o0 = ((long)bh * NN + row0 + rl) * NBF;
            long o1 = ((long)bh * NN + row0 + rl + 8) * NBF;
            #pragma unroll
            for (int ni = 0; ni < 8; ni++) {
                int nc = n_warp + ni * 8 + 2 * (lane & 3);
                *(float2*)(outf + o0 + nc) = make_float2(c[mi][ni][0], c[mi][ni][1]);
                *(float2*)(outf + o1 + nc) = make_float2(c[mi][ni][2], c[mi][ni][3]);
            }
        }
        return;
    }

    #pragma unroll
    for (int mi = 0; mi < 2; mi++) {
        int rl = m_warp + mi * 16 + (lane >> 2);
        float sub0 = diag_s[rl]     + rmax_s[rl];
        float sub1 = diag_s[rl + 8] + rmax_s[rl + 8];
        long o0 = ((long)bh * NN + row0 + rl) * NBF;
        long o1 = ((long)bh * NN + row0 + rl + 8) * NBF;
        #pragma unroll
        for (int ni = 0; ni < 8; ni++) {
            int nc = n_warp + ni * 8 + 2 * (lane & 3);
            float v0 = RATIO * (expf(c[mi][ni][0] - sub0) + KEPS);
            float v1 = RATIO * (expf(c[mi][ni][1] - sub0) + KEPS);
            float v2 = RATIO * (expf(c[mi][ni][2] - sub1) + KEPS);
            float v3 = RATIO * (expf(c[mi][ni][3] - sub1) + KEPS);
            *(float2*)(outf + o0 + nc) = make_float2(v0, v1);
            *(float2*)(outf + o1 + nc) = make_float2(v2, v3);
        }
    }
}

// ---------------- elementwise / misc kernels ----------------
__global__ void zero_kernel(float* p, long n) {
    long i = (long)blockIdx.x * blockDim.x + threadIdx.x;
    long stride = (long)gridDim.x * blockDim.x;
    for (; i < n; i += stride) p[i] = 0.0f;
}

__global__ void zks_kernel(float* __restrict__ ksum, unsigned* __restrict__ stab_u) {
    int i = blockIdx.x * 256 + threadIdx.x;
    ksum[i] = 0.0f;
    if (i < BH) stab_u[i] = 0u;
}

// concat + tf32-round wqkv
__global__ void concat_w_kernel(const float* __restrict__ wq,
                                const float* __restrict__ wk,
                                const float* __restrict__ wv,
                                float* __restrict__ wall)
{
    int c = blockIdx.x;
    int j = threadIdx.x;
    wall[(long)c * QKVN + j]        = cvt_tf32(wq[(long)c * INNER + j]);
    wall[(long)c * QKVN + 512 + j]  = cvt_tf32(wk[(long)c * INNER + j]);
    wall[(long)c * QKVN + 1024 + j] = cvt_tf32(wv[(long)c * INNER + j]);
}

// tf32-round a weight matrix into scratch
__global__ void cvtw_kernel(const float* __restrict__ src, float* __restrict__ dst, int n) {
    int i = blockIdx.x * 256 + threadIdx.x;
    if (i < n) dst[i] = cvt_tf32(src[i]);
}

__global__ void embed_kernel(const float* __restrict__ x,
                             const float* __restrict__ w1,
                             const float* __restrict__ b1,
                             float* __restrict__ h)
{
    long i = blockIdx.x;
    int j = threadIdx.x;
    float v = x[i] * w1[j] + b1[j];
    h[i * DIM + j] = cvt_tf32(fmaxf(v, 0.0f));
}

__global__ void deg_kernel(const int* __restrict__ ei,
                           const float* __restrict__ ew,
                           float* __restrict__ deg)
{
    int e = blockIdx.x * blockDim.x + threadIdx.x;
    if (e < EEDG) atomicAdd(&deg[ei[EEDG + e]], ew[e]);
}

__global__ void dinv_kernel(const float* __restrict__ deg, float* __restrict__ dinv)
{
    int i = blockIdx.x * blockDim.x + threadIdx.x;
    if (i < NN) {
        float d = deg[i];
        dinv[i] = (d > 0.0f) ? rsqrtf(fmaxf(d, 1e-12f)) : 0.0f;
    }
}

__global__ void agg_kernel(const int* __restrict__ ei,
                           const float* __restrict__ ew,
                           const float* __restrict__ dinv,
                           const float* __restrict__ emb,
                           float* __restrict__ agg)
{
    int e = blockIdx.x;
    int j = threadIdx.x;
    int r = ei[e];
    int c = ei[EEDG + e];
    float w = dinv[r] * ew[e] * dinv[c];
    atomicAdd(&agg[(long)c * DIM + j], emb[(long)r * DIM + j] * w);
}

__global__ void zadd_kernel(float* __restrict__ z,
                            const float* __restrict__ pos,
                            const float* __restrict__ go)
{
    long i = blockIdx.x;
    int j = threadIdx.x;
    int n = (int)(i & (NN - 1));
    z[i * DIM + j] += pos[(long)n * DIM + j] + go[(long)n * DIM + j];
}

// LN writes tf32-rounded y (y only ever feeds GEMM-A / head dot)
__global__ void ln_kernel(const float* __restrict__ x,
                          const float* __restrict__ g,
                          const float* __restrict__ b,
                          float* __restrict__ y)
{
    int warp = threadIdx.x >> 5, lane = threadIdx.x & 31;
    long row = (long)blockIdx.x * 8 + warp;
    const float4* xr = (const float4*)(x + row * DIM);
    float4 v0 = xr[lane];
    float4 v1 = xr[lane + 32];
    float s  = v0.x + v0.y + v0.z + v0.w + v1.x + v1.y + v1.z + v1.w;
    float s2 = v0.x*v0.x + v0.y*v0.y + v0.z*v0.z + v0.w*v0.w
             + v1.x*v1.x + v1.y*v1.y + v1.z*v1.z + v1.w*v1.w;
    #pragma unroll
    for (int o = 16; o; o >>= 1) {
        s  += __shfl_xor_sync(0xffffffffu, s,  o);
        s2 += __shfl_xor_sync(0xffffffffu, s2, o);
    }
    float mean = s * (1.0f / DIM);
    float var = s2 * (1.0f / DIM) - mean * mean;
    float rstd = rsqrtf(fmaxf(var, 0.0f) + LNEPS);
    const float4* g4 = (const float4*)g;
    const float4* b4 = (const float4*)b;
    float4* yr = (float4*)(y + row * DIM);
    float4 ga = g4[lane], bb = b4[lane];
    float4 o0;
    o0.x = cvt_tf32((v0.x - mean) * rstd * ga.x + bb.x);
    o0.y = cvt_tf32((v0.y - mean) * rstd * ga.y + bb.y);
    o0.z = cvt_tf32((v0.z - mean) * rstd * ga.z + bb.z);
    o0.w = cvt_tf32((v0.w - mean) * rstd * ga.w + bb.w);
    yr[lane] = o0;
    ga = g4[lane + 32]; bb = b4[lane + 32];
    float4 o1;
    o1.x = cvt_tf32((v1.x - mean) * rstd * ga.x + bb.x);
    o1.y = cvt_tf32((v1.y - mean) * rstd * ga.y + bb.y);
    o1.z = cvt_tf32((v1.z - mean) * rstd * ga.z + bb.z);
    o1.w = cvt_tf32((v1.w - mean) * rstd * ga.w + bb.w);
    yr[lane + 32] = o1;
}

__global__ void proj_bf_kernel(const float* __restrict__ proj,
                               __nv_bfloat16* __restrict__ pb_hi,
                               __nv_bfloat16* __restrict__ pb_lo)
{
    int i = blockIdx.x * 256 + threadIdx.x;
    float v = proj[i];
    __nv_bfloat16 hi = __float2bfloat16(v);
    pb_hi[i] = hi;
    pb_lo[i] = __float2bfloat16(v - __bfloat162float(hi));
}

__global__ void head_kernel(const float* __restrict__ y,
                            const float* __restrict__ w,
                            const float* __restrict__ bb,
                            float* __restrict__ out)
{
    int warp = threadIdx.x >> 5, lane = threadIdx.x & 31;
    long row = (long)blockIdx.x * 8 + warp;
    const float* yr = y + row * DIM;
    float s = 0.0f;
    #pragma unroll
    for (int i = 0; i < 8; i++) s += yr[lane + i * 32] * w[lane + i * 32];
    #pragma unroll
    for (int o = 16; o; o >>= 1) s += __shfl_xor_sync(0xffffffffu, s, o);
    if (lane == 0) out[row] = s + bb[0];
}

// ---------------- host ----------------
template<int BN, int WN>
static inline void launch_tgemm(cudaStream_t st, int M, int N, int K,
    const float* A, int a_rs, int a_cs, long a_so, long a_si,
    const float* B, int b_ks, long b_so, long b_si,
    float* C, int c_rs, long c_so, long c_si,
    const float* bias, float alpha, int beta, int epi, int nbatch, int nsplit,
    int cvtin, int cvtout)
{
    dim3 grid(N / BN, M / 128, nbatch * nsplit);
    tgemm_kernel<BN, WN><<<grid, 128, 0, st>>>(M, N, K, A, a_rs, a_cs, a_so, a_si,
                                        B, b_ks, b_so, b_si, C, c_rs, c_so, c_si,
                                        bias, alpha, beta, epi, nsplit, cvtin, cvtout);
}

extern "C" void kernel_launch(void* const* d_in, const int* in_sizes, int n_in,
                              void* d_out, int out_size)
{
    const float* x        = (const float*)d_in[0];
    const float* mlp_w1   = (const float*)d_in[1];
    const float* mlp_b1   = (const float*)d_in[2];
    const float* mlp_w2   = (const float*)d_in[3];
    const float* mlp_b2   = (const float*)d_in[4];
    const float* pos      = (const float*)d_in[5];
    const float* gnn_emb  = (const float*)d_in[6];
    const float* gnn_w    = (const float*)d_in[7];
    const float* gnn_b    = (const float*)d_in[8];
    const float* ew       = (const float*)d_in[9];
    const float* proj     = (const float*)d_in[10];
    const float* ln1_g    = (const float*)d_in[11];
    const float* ln1_b    = (const float*)d_in[12];
    const float* wq       = (const float*)d_in[13];
    const float* wk       = (const float*)d_in[14];
    const float* wv       = (const float*)d_in[15];
    const float* wo       = (const float*)d_in[16];
    const float* bo       = (const float*)d_in[17];
    const float* ln2_g    = (const float*)d_in[18];
    const float* ln2_b    = (const float*)d_in[19];
    const float* ffw1     = (const float*)d_in[20];
    const float* ffb1     = (const float*)d_in[21];
    const float* ffw2     = (const float*)d_in[22];
    const float* ffb2     = (const float*)d_in[23];
    const float* normf_g  = (const float*)d_in[24];
    const float* normf_b  = (const float*)d_in[25];
    const float* out_w    = (const float*)d_in[26];
    const float* out_b    = (const float*)d_in[27];
    const int*   ei       = (const int*)d_in[28];
    float* out            = (float*)d_out;

    float *z, *y, *qkv, *wqkv, *wo_c, *ff1_c, *ff2_c, *o, *ff, *qf, *kf;
    float *agg, *go, *deg, *dinv, *ksum, *ctx, *kdiag;
    __nv_bfloat16 *pb_hi, *pb_lo;
    unsigned* stab_u;
    cudaGetSymbolAddress((void**)&z, g_z);
    cudaGetSymbolAddress((void**)&y, g_y);
    cudaGetSymbolAddress((void**)&qkv, g_qkv);
    cudaGetSymbolAddress((void**)&wqkv, g_wqkv);
    cudaGetSymbolAddress((void**)&wo_c, g_wo_c);
    cudaGetSymbolAddress((void**)&ff1_c, g_ff1_c);
    cudaGetSymbolAddress((void**)&ff2_c, g_ff2_c);
    cudaGetSymbolAddress((void**)&o, g_o);
    cudaGetSymbolAddress((void**)&ff, g_ff);
    cudaGetSymbolAddress((void**)&qf, g_qf);
    cudaGetSymbolAddress((void**)&kf, g_kf);
    cudaGetSymbolAddress((void**)&agg, g_agg);
    cudaGetSymbolAddress((void**)&go, g_go);
    cudaGetSymbolAddress((void**)&deg, g_deg);
    cudaGetSymbolAddress((void**)&dinv, g_dinv);
    cudaGetSymbolAddress((void**)&stab_u, g_stab_u);
    cudaGetSymbolAddress((void**)&ksum, g_ksum);
    cudaGetSymbolAddress((void**)&ctx, g_ctx);
    cudaGetSymbolAddress((void**)&kdiag, g_kdiag);
    cudaGetSymbolAddress((void**)&pb_hi, g_pb_hi);
    cudaGetSymbolAddress((void**)&pb_lo, g_pb_lo);

    static cudaStream_t sA = nullptr, sB = nullptr;
    static cudaEvent_t evs[32];
    if (sA == nullptr) {
        cudaStreamCreateWithFlags(&sA, cudaStreamNonBlocking);
        cudaStreamCreateWithFlags(&sB, cudaStreamNonBlocking);
        for (int i = 0; i < 32; i++)
            cudaEventCreateWithFlags(&evs[i], cudaEventDisableTiming);
        cudaFuncSetAttribute(favor_gemm_kernel<0>,
                             cudaFuncAttributeMaxDynamicSharedMemorySize, FAVOR_SMEM);
        cudaFuncSetAttribute(favor_gemm_kernel<1>,
                             cudaFuncAttributeMaxDynamicSharedMemorySize, FAVOR_SMEM);
    }
    cudaStream_t s0 = cudaStreamPerThread;
    int ne = 0;
    auto fork_to = [&](cudaStream_t dst) {
        cudaEventRecord(evs[ne], s0);
        cudaStreamWaitEvent(dst, evs[ne], 0);
        ne++;
    };
    auto join_from = [&](cudaStream_t src) {
        cudaEventRecord(evs[ne], src);
        cudaStreamWaitEvent(s0, evs[ne], 0);
        ne++;
    };

    // ---- prologue ----
    zero_kernel<<<64, 256, 0, s0>>>(deg, NN);
    zero_kernel<<<1024, 256, 0, s0>>>(agg, (long)NN * DIM);
    deg_kernel<<<EEDG / 256, 256, 0, s0>>>(ei, ew, deg);
    dinv_kernel<<<NN / 256, 256, 0, s0>>>(deg, dinv);
    fork_to(sB);
    embed_kernel<<<ROWS, DIM, 0, sB>>>(x, mlp_w1, mlp_b1, y);
    launch_tgemm<128, 64>(sB, ROWS, DIM, DIM, y, DIM, 1, 0, 0, mlp_w2, DIM, 0, 0,
                          z, DIM, 0, 0, mlp_b2, 1.0f, 0, 0, 1, 1, 1, 0);
    proj_bf_kernel<<<NBF * DH / 256, 256, 0, s0>>>(proj, pb_hi, pb_lo);
    agg_kernel<<<EEDG, DIM, 0, s0>>>(ei, ew, dinv, gnn_emb, agg);
    launch_tgemm<128, 64>(s0, NN, DIM, DIM, agg, DIM, 1, 0, 0, gnn_w, DIM, 0, 0,
                          go, DIM, 0, 0, gnn_b, 1.0f, 0, 0, 1, 1, 1, 0);
    join_from(sB);
    zadd_kernel<<<ROWS, DIM, 0, s0>>>(z, pos, go);

    // ---- transformer layers ----
    for (int l = 0; l < 2; l++) {
        const float* wq_l   = wq  + (long)l * DIM * INNER;
        const float* wk_l   = wk  + (long)l * DIM * INNER;
        const float* wv_l   = wv  + (long)l * DIM * INNER;
        const float* wo_l   = wo  + (long)l * INNER * DIM;
        const float* bo_l   = bo  + (long)l * DIM;
        const float* ffw1_l = ffw1 + (long)l * DIM * FFD;
        const float* ffb1_l = ffb1 + (long)l * FFD;
        const float* ffw2_l = ffw2 + (long)l * FFD * DIM;
        const float* ffb2_l = ffb2 + (long)l * DIM;

        // weight prep on sA (off-path): concat+round wqkv, round wo/ff1/ff2
        fork_to(sA);
        concat_w_kernel<<<DIM, 512, 0, sA>>>(wq_l, wk_l, wv_l, wqkv);
        cvtw_kernel<<<(INNER * DIM + 255) / 256, 256, 0, sA>>>(wo_l, wo_c, INNER * DIM);
        cvtw_kernel<<<(DIM * FFD + 255) / 256, 256, 0, sA>>>(ffw1_l, ff1_c, DIM * FFD);
        cvtw_kernel<<<(FFD * DIM + 255) / 256, 256, 0, sA>>>(ffw2_l, ff2_c, FFD * DIM);
        ln_kernel<<<ROWS / 8, 256, 0, s0>>>(z, ln1_g + l * DIM, ln1_b + l * DIM, y);
        join_from(sA);

        // fused QKV (cvt-free mainloop; output raw fp32 for FAVOR precision)
        launch_tgemm<128, 64>(s0, ROWS, QKVN, DIM, y, DIM, 1, 0, 0, wqkv, QKVN, 0, 0,
                              qkv, QKVN, 0, 0, nullptr, 1.0f, 0, 0, 1, 1, 0, 0);

        // favor_q fully parallel on sA
        fork_to(sA);
        favor_gemm_kernel<0><<<dim3(NN / 64, BH), 256, FAVOR_SMEM, sA>>>(
            qkv, pb_hi, pb_lo, qf, nullptr, nullptr);

        fork_to(sB);
        zero_kernel<<<256, 256, 0, sB>>>(ctx, (long)BH * NBF * DH);

        zks_kernel<<<16, 256, 0, s0>>>(ksum, stab_u);
        favor_gemm_kernel<1><<<dim3(NN / 64, BH), 256, FAVOR_SMEM, s0>>>(
            qkv + 512, pb_hi, pb_lo, kf, stab_u, kdiag);

        join_from(sB);
        ctxk_kernel<<<dim3(1, 2, BH * CTX_NSPLIT), 128, 0, s0>>>(
            kf, qkv + 1024, kdiag, stab_u, ctx, ksum);

        join_from(sA);
        attn_kernel<<<dim3(1, NN / 128, BH), 128, 0, s0>>>(qf, ctx, ksum, o);

        launch_tgemm<128, 64>(s0, ROWS, DIM, INNER, o, INNER, 1, 0, 0, wo_c, DIM, 0, 0,
                              z, DIM, 0, 0, bo_l, 1.0f, 1, 0, 1, 1, 0, 0);

        ln_kernel<<<ROWS / 8, 256, 0, s0>>>(z, ln2_g + l * DIM, ln2_b + l * DIM, y);
        launch_tgemm<128, 64>(s0, ROWS, FFD, DIM, y, DIM, 1, 0, 0, ff1_c, FFD, 0, 0,
                              ff, FFD, 0, 0, ffb1_l, 1.0f, 0, 2, 1, 1, 0, 1);
        launch_tgemm<128, 64>(s0, ROWS, DIM, FFD, ff, FFD, 1, 0, 0, ff2_c, DIM, 0, 0,
                              z, DIM, 0, 0, ffb2_l, 1.0f, 1, 0, 1, 1, 0, 0);
    }

    // ---- final LN + head ----
    ln_kernel<<<ROWS / 8, 256, 0, s0>>>(z, normf_g, normf_b, y);
    head_kernel<<<ROWS / 8, 256, 0, s0>>>(y, out_w, out_b, out);
}